// round 6
// baseline (speedup 1.0000x reference)
#include <cuda_runtime.h>

#define N_NODES 50000
#define E_EDGES 800000
#define DCH     128
#define EDIM    16

typedef unsigned long long ull;

// ---------------- packed f32x2 helpers (sm_103a FFMA2) ----------------
__device__ __forceinline__ void fma2(ull &d, ull a, ull b) {
    asm("fma.rn.f32x2 %0, %1, %2, %0;" : "+l"(d) : "l"(a), "l"(b));
}
__device__ __forceinline__ ull dup2(float a) {
    ull r; asm("mov.b64 %0, {%1, %1};" : "=l"(r) : "f"(a)); return r;
}
__device__ __forceinline__ ull pack2(float a, float b) {
    ull r; asm("mov.b64 %0, {%1, %2};" : "=l"(r) : "f"(a), "f"(b)); return r;
}
__device__ __forceinline__ float2 u2f(ull v) {
    float2 f; asm("mov.b64 {%0, %1}, %2;" : "=f"(f.x), "=f"(f.y) : "l"(v)); return f;
}

// ---------------- device scratch ----------------
__device__ float g_xl[N_NODES * DCH];
__device__ float g_xr[N_NODES * DCH];
__device__ float g_zpre[N_NODES * DCH];
__device__ float g_z2[N_NODES * DCH];
__device__ float g_wext[384 * DCH];
__device__ int   g_deg[N_NODES];
__device__ int   g_cur[N_NODES];
__device__ int   g_off[N_NODES + 1];
__device__ int   g_srcl[E_EDGES];
__device__ int   g_eidl[E_EDGES];
__device__ int   g_cnt;
__device__ float g_stats[512];
__device__ float g_scale1[DCH], g_shift1[DCH];
__device__ float g_scale2[DCH], g_shift2[DCH];

// ---------------- zero scratch ----------------
__global__ void zero_kernel() {
    int idx = blockIdx.x * blockDim.x + threadIdx.x;
    if (idx < N_NODES) { g_deg[idx] = 0; g_cur[idx] = 0; }
    if (idx < 512) g_stats[idx] = 0.f;
    if (idx == 0) g_cnt = 0;
}

// ---------------- 128x128-block GEMM, FFMA2, 8x8/thread ----------------
__global__ __launch_bounds__(256, 2) void gemm128(
    const float* __restrict__ A, const float* __restrict__ W,
    const float* __restrict__ bias, float* __restrict__ C, int nrows)
{
    __shared__ float as[16][128];   // [k][row]
    __shared__ float ws[16][128];   // [k][col]
    int tid = threadIdx.x;
    int row0 = blockIdx.x * 128;
    int tcol = tid & 15, trow = tid >> 4;
    int c0 = tcol * 8, r0 = trow * 8;

    ull acc[8][4];
#pragma unroll
    for (int r = 0; r < 8; r++)
#pragma unroll
        for (int q = 0; q < 4; q++) acc[r][q] = 0ull;

    for (int kb = 0; kb < 128; kb += 16) {
#pragma unroll
        for (int it = 0; it < 2; it++) {
            int idx = tid + it * 256;
            int r = idx & 127, kg = idx >> 7;        // kg 0..3
            float4 v = make_float4(0.f, 0.f, 0.f, 0.f);
            int grow = row0 + r;
            if (grow < nrows) v = *(const float4*)(A + (size_t)grow * 128 + kb + kg * 4);
            as[kg * 4 + 0][r] = v.x; as[kg * 4 + 1][r] = v.y;
            as[kg * 4 + 2][r] = v.z; as[kg * 4 + 3][r] = v.w;
        }
#pragma unroll
        for (int it = 0; it < 2; it++) {
            int idx = tid + it * 256;
            int k = idx >> 5, cg = idx & 31;
            *(float4*)&ws[k][cg * 4] = *(const float4*)(W + (size_t)(kb + k) * 128 + cg * 4);
        }
        __syncthreads();
#pragma unroll
        for (int k = 0; k < 16; k++) {
            float4 alo = *(const float4*)&as[k][r0];
            float4 ahi = *(const float4*)&as[k][r0 + 4];
            ulonglong2 wA = *(const ulonglong2*)&ws[k][c0];
            ulonglong2 wB = *(const ulonglong2*)&ws[k][c0 + 4];
            ull ad[8];
            ad[0] = dup2(alo.x); ad[1] = dup2(alo.y); ad[2] = dup2(alo.z); ad[3] = dup2(alo.w);
            ad[4] = dup2(ahi.x); ad[5] = dup2(ahi.y); ad[6] = dup2(ahi.z); ad[7] = dup2(ahi.w);
#pragma unroll
            for (int r = 0; r < 8; r++) {
                fma2(acc[r][0], ad[r], wA.x);
                fma2(acc[r][1], ad[r], wA.y);
                fma2(acc[r][2], ad[r], wB.x);
                fma2(acc[r][3], ad[r], wB.y);
            }
        }
        __syncthreads();
    }
    float4 b0 = *(const float4*)(bias + c0);
    float4 b1 = *(const float4*)(bias + c0 + 4);
#pragma unroll
    for (int r = 0; r < 8; r++) {
        int grow = row0 + r0 + r;
        if (grow < nrows) {
            float2 u0 = u2f(acc[r][0]), u1 = u2f(acc[r][1]);
            float2 u2 = u2f(acc[r][2]), u3 = u2f(acc[r][3]);
            float4 o0 = make_float4(u0.x + b0.x, u0.y + b0.y, u1.x + b0.z, u1.y + b0.w);
            float4 o1 = make_float4(u2.x + b1.x, u2.y + b1.y, u3.x + b1.z, u3.y + b1.w);
            *(float4*)(C + (size_t)grow * 128 + c0) = o0;
            *(float4*)(C + (size_t)grow * 128 + c0 + 4) = o1;
        }
    }
}

// ---------------- CSR build (no self loops; atomic segment bases) ----------------
__global__ void hist_kernel(const int* __restrict__ ei) {
    int t = blockIdx.x * blockDim.x + threadIdx.x;
    if (t >= E_EDGES) return;
    atomicAdd(&g_deg[ei[E_EDGES + t]], 1);
}

__global__ void base_kernel() {
    int idx = blockIdx.x * blockDim.x + threadIdx.x;
    if (idx < N_NODES) g_off[idx] = atomicAdd(&g_cnt, g_deg[idx]);
}

__global__ void scatter_kernel(const int* __restrict__ ei) {
    int t = blockIdx.x * blockDim.x + threadIdx.x;
    if (t >= E_EDGES) return;
    int dst = ei[E_EDGES + t];
    int pos = atomicAdd(&g_cur[dst], 1);
    int o = g_off[dst] + pos;
    g_srcl[o] = ei[t];
    g_eidl[o] = t;
}

// ---------------- conv weight transpose ----------------
__global__ void prep_wext(const float* __restrict__ conv_w) {
    int idx = blockIdx.x * blockDim.x + threadIdx.x;
    if (idx >= 384 * 128) return;
    int kext = idx >> 7, cout = idx & 127;
    int t = kext >> 7, cin = kext & 127;
    g_wext[idx] = conv_w[cout * 384 + cin * 3 + t];
}

// ---------------- fused attention: warp/node, online softmax, FFMA2 ----------------
__global__ __launch_bounds__(128) void attn_kernel(
    const float* __restrict__ x,
    const float* __restrict__ edge_attr, const float* __restrict__ W_e,
    const float* __restrict__ att, const float* __restrict__ bias_gat,
    const float* __restrict__ weight1)
{
    __shared__ float red_s[256];
    int tid = threadIdx.x;
    red_s[tid] = 0.f; red_s[tid + 128] = 0.f;
    __syncthreads();

    int warp = tid >> 5, lane = tid & 31, c0 = lane * 4;
    int i = blockIdx.x * 4 + warp;   // grid = 12500 -> exactly N

    // hoist W_e column-pairs into registers
    ull wreg[32];
#pragma unroll
    for (int k = 0; k < 16; k++) {
        float4 w = *(const float4*)(W_e + k * 128 + c0);
        wreg[2 * k]     = pack2(w.x, w.y);
        wreg[2 * k + 1] = pack2(w.z, w.w);
    }

    const float4 xr4 = *(const float4*)(g_xr + (size_t)i * 128 + c0);
    const float4 xli = *(const float4*)(g_xl + (size_t)i * 128 + c0);
    const float4 a4  = *(const float4*)(att + c0);

    // self loop: message = leaky(xl_i + xr_i), no edge term
    float sx = xli.x + xr4.x, sy = xli.y + xr4.y;
    float sz = xli.z + xr4.z, sw = xli.w + xr4.w;
    sx = (sx > 0.f) ? sx : 0.2f * sx; sy = (sy > 0.f) ? sy : 0.2f * sy;
    sz = (sz > 0.f) ? sz : 0.2f * sz; sw = (sw > 0.f) ? sw : 0.2f * sw;
    float part = sx * a4.x + sy * a4.y + sz * a4.z + sw * a4.w;
#pragma unroll
    for (int o = 16; o; o >>= 1) part += __shfl_xor_sync(0xffffffffu, part, o);
    float m = part, den = 1.f;
    float4 acc = xli;

    int base = g_off[i], deg = g_deg[i];
    int s1 = 0, e1 = 0;
    float4 xl0 = make_float4(0.f, 0.f, 0.f, 0.f);
    float4 eaA = xl0, eaB = xl0, eaC = xl0, eaD = xl0;
    if (deg > 0) {
        int s0 = g_srcl[base], e0 = g_eidl[base];
        xl0 = *(const float4*)(g_xl + (size_t)s0 * 128 + c0);
        const float4* eap = (const float4*)(edge_attr + (size_t)e0 * EDIM);
        eaA = eap[0]; eaB = eap[1]; eaC = eap[2]; eaD = eap[3];
    }
    if (deg > 1) { s1 = g_srcl[base + 1]; e1 = g_eidl[base + 1]; }

    for (int jj = 0; jj < deg; ++jj) {
        float4 xl4 = xl0;
        float ev[16] = {eaA.x, eaA.y, eaA.z, eaA.w, eaB.x, eaB.y, eaB.z, eaB.w,
                        eaC.x, eaC.y, eaC.z, eaC.w, eaD.x, eaD.y, eaD.z, eaD.w};
        if (jj + 1 < deg) {   // prefetch next edge's payload
            xl0 = *(const float4*)(g_xl + (size_t)s1 * 128 + c0);
            const float4* eap = (const float4*)(edge_attr + (size_t)e1 * EDIM);
            eaA = eap[0]; eaB = eap[1]; eaC = eap[2]; eaD = eap[3];
        }
        if (jj + 2 < deg) { s1 = g_srcl[base + jj + 2]; e1 = g_eidl[base + jj + 2]; }

        ull m01 = pack2(xl4.x + xr4.x, xl4.y + xr4.y);
        ull m23 = pack2(xl4.z + xr4.z, xl4.w + xr4.w);
#pragma unroll
        for (int k = 0; k < 16; k++) {
            ull ed = dup2(ev[k]);
            fma2(m01, ed, wreg[2 * k]);
            fma2(m23, ed, wreg[2 * k + 1]);
        }
        float2 p01 = u2f(m01), p23 = u2f(m23);
        float mx = p01.x, my = p01.y, mz = p23.x, mw = p23.y;
        mx = (mx > 0.f) ? mx : 0.2f * mx;
        my = (my > 0.f) ? my : 0.2f * my;
        mz = (mz > 0.f) ? mz : 0.2f * mz;
        mw = (mw > 0.f) ? mw : 0.2f * mw;
        float p = mx * a4.x + my * a4.y + mz * a4.z + mw * a4.w;
#pragma unroll
        for (int o = 16; o; o >>= 1) p += __shfl_xor_sync(0xffffffffu, p, o);
        float l = p;
        if (l > m) {
            float scl = __expf(m - l);
            den *= scl;
            acc.x *= scl; acc.y *= scl; acc.z *= scl; acc.w *= scl;
            m = l;
        }
        float pr = __expf(l - m);
        den += pr;
        acc.x += pr * xl4.x; acc.y += pr * xl4.y;
        acc.z += pr * xl4.z; acc.w += pr * xl4.w;
    }

    float inv = 1.f / den;
    float a0 = weight1[0], a1 = weight1[1];
    float wm = fmaxf(a0, a1);
    float e0f = __expf(a0 - wm), e1f = __expf(a1 - wm);
    float is = 1.f / (e0f + e1f);
    float w10 = e0f * is, w11 = e1f * is;

    const float4 xv = *(const float4*)(x + (size_t)i * 128 + c0);
    const float4 bg = *(const float4*)(bias_gat + c0);
    float4 o;
    o.x = w10 * xv.x + w11 * (acc.x * inv + bg.x);
    o.y = w10 * xv.y + w11 * (acc.y * inv + bg.y);
    o.z = w10 * xv.z + w11 * (acc.z * inv + bg.z);
    o.w = w10 * xv.w + w11 * (acc.w * inv + bg.w);
    *(float4*)(g_zpre + (size_t)i * 128 + c0) = o;

    // fused BN1 stats
    atomicAdd(&red_s[c0 + 0], o.x); atomicAdd(&red_s[128 + c0 + 0], o.x * o.x);
    atomicAdd(&red_s[c0 + 1], o.y); atomicAdd(&red_s[128 + c0 + 1], o.y * o.y);
    atomicAdd(&red_s[c0 + 2], o.z); atomicAdd(&red_s[128 + c0 + 2], o.z * o.z);
    atomicAdd(&red_s[c0 + 3], o.w); atomicAdd(&red_s[128 + c0 + 3], o.w * o.w);
    __syncthreads();
    atomicAdd(&g_stats[tid], red_s[tid]);
    atomicAdd(&g_stats[tid + 128], red_s[tid + 128]);
}

__global__ void bn_finalize(const float* __restrict__ stats,
                            const float* __restrict__ gamma, const float* __restrict__ beta,
                            float* __restrict__ scale, float* __restrict__ shift)
{
    int c = threadIdx.x;
    float mu = stats[c] * (1.f / N_NODES);
    float var = stats[128 + c] * (1.f / N_NODES) - mu * mu;
    float rstd = rsqrtf(var + 1e-5f);
    float s = rstd * gamma[c];
    scale[c] = s;
    shift[c] = beta[c] - mu * s;
}

// ---------------- conv1d(k=3) GEMM (FFMA2) + mix + fused BN2 stats ----------------
__global__ __launch_bounds__(128, 3) void conv_kernel(const float* __restrict__ conv_b,
                                                      const float* __restrict__ weight2)
{
    __shared__ float zs[66][128];
    __shared__ float wt[16][128];
    __shared__ float sc_s[128], sh_s[128];
    __shared__ float red2[256];
    int tid = threadIdx.x;
    int row0 = blockIdx.x * 64;
    sc_s[tid] = g_scale1[tid]; sh_s[tid] = g_shift1[tid];
    red2[tid] = 0.f; red2[tid + 128] = 0.f;
    __syncthreads();

    for (int idx = tid; idx < 66 * 32; idx += 128) {
        int rr = idx >> 5, cg = idx & 31;
        int grow = row0 - 1 + rr;
        float4 v = make_float4(0.f, 0.f, 0.f, 0.f);
        if (grow >= 0 && grow < N_NODES) {
            float4 z = *(const float4*)(g_zpre + (size_t)grow * 128 + cg * 4);
            int c = cg * 4;
            v.x = z.x * sc_s[c] + sh_s[c];
            v.y = z.y * sc_s[c + 1] + sh_s[c + 1];
            v.z = z.z * sc_s[c + 2] + sh_s[c + 2];
            v.w = z.w * sc_s[c + 3] + sh_s[c + 3];
        }
        *(float4*)&zs[rr][cg * 4] = v;
    }

    int tcol = tid & 15, trow = tid >> 4;
    int c0 = tcol * 8, r0 = trow * 8;
    ull acc[8][4];
#pragma unroll
    for (int r = 0; r < 8; r++)
#pragma unroll
        for (int q = 0; q < 4; q++) acc[r][q] = 0ull;

    for (int t = 0; t < 3; t++) {
        for (int kc = 0; kc < 8; kc++) {
            __syncthreads();
#pragma unroll
            for (int it = 0; it < 4; it++) {
                int idx = tid + it * 128;
                int k = idx >> 5, cg = idx & 31;
                *(float4*)&wt[k][cg * 4] =
                    *(const float4*)(g_wext + (size_t)(t * 128 + kc * 16 + k) * 128 + cg * 4);
            }
            __syncthreads();
#pragma unroll
            for (int k = 0; k < 16; k++) {
                ulonglong2 wA = *(const ulonglong2*)&wt[k][c0];
                ulonglong2 wB = *(const ulonglong2*)&wt[k][c0 + 4];
#pragma unroll
                for (int r = 0; r < 8; r++) {
                    ull ad = dup2(zs[r0 + r + t][kc * 16 + k]);
                    fma2(acc[r][0], ad, wA.x);
                    fma2(acc[r][1], ad, wA.y);
                    fma2(acc[r][2], ad, wB.x);
                    fma2(acc[r][3], ad, wB.y);
                }
            }
        }
    }

    float a0 = weight2[0], a1 = weight2[1];
    float wm = fmaxf(a0, a1);
    float e0 = __expf(a0 - wm), e1 = __expf(a1 - wm);
    float is = 1.f / (e0 + e1);
    float w20 = e0 * is, w21 = e1 * is;

    float4 b0 = *(const float4*)(conv_b + c0);
    float4 b1 = *(const float4*)(conv_b + c0 + 4);
    float sst[8], qst[8];
#pragma unroll
    for (int j = 0; j < 8; j++) { sst[j] = 0.f; qst[j] = 0.f; }

#pragma unroll
    for (int r = 0; r < 8; r++) {
        int grow = row0 + r0 + r;
        if (grow < N_NODES) {
            float2 u0 = u2f(acc[r][0]), u1 = u2f(acc[r][1]);
            float2 u2 = u2f(acc[r][2]), u3 = u2f(acc[r][3]);
            float z1v[8] = {u0.x + b0.x, u0.y + b0.y, u1.x + b0.z, u1.y + b0.w,
                            u2.x + b1.x, u2.y + b1.y, u3.x + b1.z, u3.y + b1.w};
            float4 znA = *(float4*)&zs[r0 + r + 1][c0];
            float4 znB = *(float4*)&zs[r0 + r + 1][c0 + 4];
            float zn[8] = {znA.x, znA.y, znA.z, znA.w, znB.x, znB.y, znB.z, znB.w};
            float ov[8];
#pragma unroll
            for (int j = 0; j < 8; j++) {
                float v = z1v[j];
                v = (v > 0.f) ? v : 0.01f * v;
                float oo = w20 * zn[j] + w21 * v;
                ov[j] = oo;
                sst[j] += oo; qst[j] += oo * oo;
            }
            *(float4*)(g_z2 + (size_t)grow * 128 + c0)     = make_float4(ov[0], ov[1], ov[2], ov[3]);
            *(float4*)(g_z2 + (size_t)grow * 128 + c0 + 4) = make_float4(ov[4], ov[5], ov[6], ov[7]);
        }
    }
#pragma unroll
    for (int j = 0; j < 8; j++) {
        atomicAdd(&red2[c0 + j], sst[j]);
        atomicAdd(&red2[128 + c0 + j], qst[j]);
    }
    __syncthreads();
    atomicAdd(&g_stats[256 + tid], red2[tid]);
    atomicAdd(&g_stats[256 + 128 + tid], red2[tid + 128]);
}

// ---------------- final BN2 apply ----------------
__global__ void final_apply(float* __restrict__ out) {
    int idx = blockIdx.x * blockDim.x + threadIdx.x;
    if (idx >= N_NODES * 32) return;
    int cg = idx & 31;
    int c = cg * 4;
    float4 z = *(const float4*)(g_z2 + (size_t)idx * 4);
    float4 o;
    o.x = z.x * g_scale2[c]     + g_shift2[c];
    o.y = z.y * g_scale2[c + 1] + g_shift2[c + 1];
    o.z = z.z * g_scale2[c + 2] + g_shift2[c + 2];
    o.w = z.w * g_scale2[c + 3] + g_shift2[c + 3];
    *(float4*)(out + (size_t)idx * 4) = o;
}

// ---------------- launch ----------------
extern "C" void kernel_launch(void* const* d_in, const int* in_sizes, int n_in,
                              void* d_out, int out_size)
{
    const float* x         = (const float*)d_in[0];
    const int*   ei        = (const int*)d_in[1];
    const float* edge_attr = (const float*)d_in[2];
    const float* W_l       = (const float*)d_in[3];
    const float* b_l       = (const float*)d_in[4];
    const float* W_r       = (const float*)d_in[5];
    const float* b_r       = (const float*)d_in[6];
    const float* W_e       = (const float*)d_in[7];
    const float* att       = (const float*)d_in[8];
    const float* bias_gat  = (const float*)d_in[9];
    const float* weight1   = (const float*)d_in[10];
    const float* bn1_gamma = (const float*)d_in[11];
    const float* bn1_beta  = (const float*)d_in[12];
    const float* conv_w    = (const float*)d_in[13];
    const float* conv_b    = (const float*)d_in[14];
    const float* weight2   = (const float*)d_in[15];
    const float* bn2_gamma = (const float*)d_in[16];
    const float* bn2_beta  = (const float*)d_in[17];
    float* out = (float*)d_out;

    float *p_xl, *p_xr, *p_stats, *p_sc1, *p_sh1, *p_sc2, *p_sh2;
    cudaGetSymbolAddress((void**)&p_xl, g_xl);
    cudaGetSymbolAddress((void**)&p_xr, g_xr);
    cudaGetSymbolAddress((void**)&p_stats, g_stats);
    cudaGetSymbolAddress((void**)&p_sc1, g_scale1);
    cudaGetSymbolAddress((void**)&p_sh1, g_shift1);
    cudaGetSymbolAddress((void**)&p_sc2, g_scale2);
    cudaGetSymbolAddress((void**)&p_sh2, g_shift2);

    zero_kernel<<<(N_NODES + 255) / 256, 256>>>();
    gemm128<<<(N_NODES + 127) / 128, 256>>>(x, W_l, b_l, p_xl, N_NODES);
    gemm128<<<(N_NODES + 127) / 128, 256>>>(x, W_r, b_r, p_xr, N_NODES);
    hist_kernel<<<(E_EDGES + 255) / 256, 256>>>(ei);
    base_kernel<<<(N_NODES + 255) / 256, 256>>>();
    scatter_kernel<<<(E_EDGES + 255) / 256, 256>>>(ei);
    prep_wext<<<(384 * 128 + 255) / 256, 256>>>(conv_w);
    attn_kernel<<<N_NODES / 4, 128>>>(x, edge_attr, W_e, att, bias_gat, weight1);
    bn_finalize<<<1, 128>>>(p_stats, bn1_gamma, bn1_beta, p_sc1, p_sh1);
    conv_kernel<<<(N_NODES + 63) / 64, 128>>>(conv_b, weight2);
    bn_finalize<<<1, 128>>>(p_stats + 256, bn2_gamma, bn2_beta, p_sc2, p_sh2);
    final_apply<<<(N_NODES * 32 + 255) / 256, 256>>>(out);
}

// round 7
// speedup vs baseline: 1.5831x; 1.5831x over previous
#include <cuda_runtime.h>

#define N_NODES 50000
#define E_EDGES 800000
#define DCH     128
#define EDIM    16

// ---------------- device scratch (no allocs allowed) ----------------
__device__ float g_xl[N_NODES * DCH];
__device__ float g_xr[N_NODES * DCH];
__device__ float g_zpre[N_NODES * DCH];
__device__ float g_z2[N_NODES * DCH];
__device__ float g_wext[384 * DCH];
__device__ int   g_deg[N_NODES];
__device__ int   g_cur[N_NODES];
__device__ int   g_off[N_NODES];
__device__ int   g_srcl[E_EDGES];
__device__ int   g_eidl[E_EDGES];
__device__ int   g_cnt;
__device__ float g_stats[512];              // [0..255] bn1 (sum,sumsq), [256..511] bn2
__device__ float g_scale1[DCH], g_shift1[DCH];
__device__ float g_scale2[DCH], g_shift2[DCH];

// ---------------- zero scratch ----------------
__global__ void zero_kernel() {
    int idx = blockIdx.x * blockDim.x + threadIdx.x;
    if (idx < N_NODES) { g_deg[idx] = 0; g_cur[idx] = 0; }
    if (idx < 512) g_stats[idx] = 0.f;
    if (idx == 0) g_cnt = 0;
}

// ---------------- generic 128x128 GEMM: C = A@W + b (R5 proven version) ----------------
__global__ __launch_bounds__(256) void gemm128(
    const float* __restrict__ A, const float* __restrict__ W,
    const float* __restrict__ bias, float* __restrict__ C, int nrows)
{
    __shared__ float as[16][64];
    __shared__ float ws[16][128];
    int tid = threadIdx.x;
    int row0 = blockIdx.x * 64;
    int tcol = tid & 31, trow = tid >> 5;
    int c0 = tcol * 4, r0 = trow * 8;
    float4 acc[8];
#pragma unroll
    for (int r = 0; r < 8; r++) acc[r] = make_float4(0.f, 0.f, 0.f, 0.f);

    int lr = tid & 63, lkg = tid >> 6;
    for (int kb = 0; kb < 128; kb += 16) {
        float4 v = make_float4(0.f, 0.f, 0.f, 0.f);
        int grow = row0 + lr;
        if (grow < nrows) v = *(const float4*)(A + (size_t)grow * 128 + kb + lkg * 4);
        as[lkg * 4 + 0][lr] = v.x; as[lkg * 4 + 1][lr] = v.y;
        as[lkg * 4 + 2][lr] = v.z; as[lkg * 4 + 3][lr] = v.w;
#pragma unroll
        for (int it = 0; it < 2; it++) {
            int idx = tid + it * 256;
            int k = idx >> 5, cg = idx & 31;
            *(float4*)&ws[k][cg * 4] = *(const float4*)(W + (size_t)(kb + k) * 128 + cg * 4);
        }
        __syncthreads();
#pragma unroll
        for (int k = 0; k < 16; k++) {
            float4 w4  = *(float4*)&ws[k][c0];
            float4 alo = *(float4*)&as[k][r0];
            float4 ahi = *(float4*)&as[k][r0 + 4];
            float a[8] = {alo.x, alo.y, alo.z, alo.w, ahi.x, ahi.y, ahi.z, ahi.w};
#pragma unroll
            for (int r = 0; r < 8; r++) {
                acc[r].x += a[r] * w4.x; acc[r].y += a[r] * w4.y;
                acc[r].z += a[r] * w4.z; acc[r].w += a[r] * w4.w;
            }
        }
        __syncthreads();
    }
    float4 b4 = *(const float4*)(bias + c0);
#pragma unroll
    for (int r = 0; r < 8; r++) {
        int grow = row0 + r0 + r;
        if (grow < nrows) {
            float4 o;
            o.x = acc[r].x + b4.x; o.y = acc[r].y + b4.y;
            o.z = acc[r].z + b4.z; o.w = acc[r].w + b4.w;
            *(float4*)(C + (size_t)grow * 128 + c0) = o;
        }
    }
}

// ---------------- CSR build (no self loops; atomic segment bases) ----------------
__global__ void hist_kernel(const int* __restrict__ ei) {
    int t = blockIdx.x * blockDim.x + threadIdx.x;
    if (t >= E_EDGES) return;
    atomicAdd(&g_deg[ei[E_EDGES + t]], 1);
}

__global__ void base_kernel() {
    int idx = blockIdx.x * blockDim.x + threadIdx.x;
    if (idx < N_NODES) g_off[idx] = atomicAdd(&g_cnt, g_deg[idx]);
}

__global__ void scatter_kernel(const int* __restrict__ ei) {
    int t = blockIdx.x * blockDim.x + threadIdx.x;
    if (t >= E_EDGES) return;
    int dst = ei[E_EDGES + t];
    int pos = atomicAdd(&g_cur[dst], 1);
    int o = g_off[dst] + pos;
    g_srcl[o] = ei[t];
    g_eidl[o] = t;
}

// ---------------- conv weight transpose: wext[(t*128+cin)*128 + cout] ----------------
__global__ void prep_wext(const float* __restrict__ conv_w) {
    int idx = blockIdx.x * blockDim.x + threadIdx.x;
    if (idx >= 384 * 128) return;
    int kext = idx >> 7, cout = idx & 127;
    int t = kext >> 7, cin = kext & 127;
    g_wext[idx] = conv_w[cout * 384 + cin * 3 + t];
}

// ---------------- fused attention: warp per dst node, online softmax ----------------
__global__ __launch_bounds__(256) void attn_kernel(
    const float* __restrict__ x,
    const float* __restrict__ edge_attr, const float* __restrict__ W_e,
    const float* __restrict__ att, const float* __restrict__ bias_gat,
    const float* __restrict__ weight1)
{
    __shared__ float We_s[2048];
    __shared__ float att_s[128];
    __shared__ float bias_s[128];
    __shared__ float red_s[256];
    int tid = threadIdx.x;
    for (int idx = tid; idx < 2048; idx += 256) We_s[idx] = W_e[idx];
    if (tid < 128) { att_s[tid] = att[tid]; bias_s[tid] = bias_gat[tid]; }
    red_s[tid] = 0.f;
    __syncthreads();

    int i = blockIdx.x * 8 + (tid >> 5);   // grid = 6250 -> exactly 50000 nodes
    int lane = tid & 31;
    int c0 = lane * 4;
    int base = g_off[i];
    int deg = g_deg[i];

    const float4 xr4 = *(const float4*)(g_xr + (size_t)i * 128 + c0);
    const float4 xli = *(const float4*)(g_xl + (size_t)i * 128 + c0);
    float ax = att_s[c0], ay = att_s[c0 + 1], az = att_s[c0 + 2], aw = att_s[c0 + 3];

    // self loop handled analytically: message = leaky(xl_i + xr_i), no edge term
    float sx = xli.x + xr4.x, sy = xli.y + xr4.y;
    float sz = xli.z + xr4.z, sw = xli.w + xr4.w;
    sx = (sx > 0.f) ? sx : 0.2f * sx; sy = (sy > 0.f) ? sy : 0.2f * sy;
    sz = (sz > 0.f) ? sz : 0.2f * sz; sw = (sw > 0.f) ? sw : 0.2f * sw;
    float part = sx * ax + sy * ay + sz * az + sw * aw;
#pragma unroll
    for (int o = 16; o; o >>= 1) part += __shfl_xor_sync(0xffffffffu, part, o);
    float m = part, den = 1.f;
    float4 acc = xli;

    for (int jj = 0; jj < deg; ++jj) {
        int src = g_srcl[base + jj];
        int e   = g_eidl[base + jj];
        const float4 xl4 = *(const float4*)(g_xl + (size_t)src * 128 + c0);
        const float4* eap = (const float4*)(edge_attr + (size_t)e * EDIM);
        float4 eA = __ldg(eap), eB = __ldg(eap + 1), eC = __ldg(eap + 2), eD = __ldg(eap + 3);
        float ev[16] = {eA.x, eA.y, eA.z, eA.w, eB.x, eB.y, eB.z, eB.w,
                        eC.x, eC.y, eC.z, eC.w, eD.x, eD.y, eD.z, eD.w};
        float mx = xl4.x + xr4.x, my = xl4.y + xr4.y;
        float mz = xl4.z + xr4.z, mw = xl4.w + xr4.w;
#pragma unroll
        for (int k = 0; k < EDIM; k++) {
            const float4 w = *(const float4*)&We_s[k * 128 + c0];
            mx += ev[k] * w.x; my += ev[k] * w.y; mz += ev[k] * w.z; mw += ev[k] * w.w;
        }
        mx = (mx > 0.f) ? mx : 0.2f * mx;
        my = (my > 0.f) ? my : 0.2f * my;
        mz = (mz > 0.f) ? mz : 0.2f * mz;
        mw = (mw > 0.f) ? mw : 0.2f * mw;
        float p = mx * ax + my * ay + mz * az + mw * aw;
#pragma unroll
        for (int o = 16; o; o >>= 1) p += __shfl_xor_sync(0xffffffffu, p, o);
        float l = p;
        if (l > m) {
            float scl = __expf(m - l);
            den *= scl;
            acc.x *= scl; acc.y *= scl; acc.z *= scl; acc.w *= scl;
            m = l;
        }
        float pr = __expf(l - m);
        den += pr;
        acc.x += pr * xl4.x; acc.y += pr * xl4.y;
        acc.z += pr * xl4.z; acc.w += pr * xl4.w;
    }
    float inv = 1.f / den;
    // softmax(weight1)
    float a0 = weight1[0], a1 = weight1[1];
    float wm = fmaxf(a0, a1);
    float e0 = __expf(a0 - wm), e1 = __expf(a1 - wm);
    float is = 1.f / (e0 + e1);
    float w10 = e0 * is, w11 = e1 * is;

    const float4 xv = *(const float4*)(x + (size_t)i * 128 + c0);
    float4 o;
    o.x = w10 * xv.x + w11 * (acc.x * inv + bias_s[c0]);
    o.y = w10 * xv.y + w11 * (acc.y * inv + bias_s[c0 + 1]);
    o.z = w10 * xv.z + w11 * (acc.z * inv + bias_s[c0 + 2]);
    o.w = w10 * xv.w + w11 * (acc.w * inv + bias_s[c0 + 3]);
    *(float4*)(g_zpre + (size_t)i * 128 + c0) = o;

    // fused BN1 stats: block-level partials then one global flush
    atomicAdd(&red_s[c0 + 0], o.x); atomicAdd(&red_s[128 + c0 + 0], o.x * o.x);
    atomicAdd(&red_s[c0 + 1], o.y); atomicAdd(&red_s[128 + c0 + 1], o.y * o.y);
    atomicAdd(&red_s[c0 + 2], o.z); atomicAdd(&red_s[128 + c0 + 2], o.z * o.z);
    atomicAdd(&red_s[c0 + 3], o.w); atomicAdd(&red_s[128 + c0 + 3], o.w * o.w);
    __syncthreads();
    atomicAdd(&g_stats[tid], red_s[tid]);
}

__global__ void bn_finalize(const float* __restrict__ stats,
                            const float* __restrict__ gamma, const float* __restrict__ beta,
                            float* __restrict__ scale, float* __restrict__ shift)
{
    int c = threadIdx.x;
    float mu = stats[c] * (1.f / N_NODES);
    float var = stats[128 + c] * (1.f / N_NODES) - mu * mu;
    float rstd = rsqrtf(var + 1e-5f);
    float s = rstd * gamma[c];
    scale[c] = s;
    shift[c] = beta[c] - mu * s;
}

// ---------------- conv1d(k=3) as K=384 GEMM + mix + fused BN2 stats ----------------
__global__ __launch_bounds__(256) void conv_kernel(const float* __restrict__ conv_b,
                                                   const float* __restrict__ weight2)
{
    __shared__ float zs[66][128];
    __shared__ float wt[16][128];
    __shared__ float sc_s[128], sh_s[128];
    __shared__ float red2[256];
    int tid = threadIdx.x;
    int row0 = blockIdx.x * 64;
    if (tid < 128) { sc_s[tid] = g_scale1[tid]; sh_s[tid] = g_shift1[tid]; }
    red2[tid] = 0.f;
    __syncthreads();

    // load + normalize input tile rows [row0-1, row0+64]; zero pad outside [0,N)
    for (int idx = tid; idx < 66 * 32; idx += 256) {
        int rr = idx >> 5, cg = idx & 31;
        int grow = row0 - 1 + rr;
        float4 v = make_float4(0.f, 0.f, 0.f, 0.f);
        if (grow >= 0 && grow < N_NODES) {
            float4 z = *(const float4*)(g_zpre + (size_t)grow * 128 + cg * 4);
            int c = cg * 4;
            v.x = z.x * sc_s[c] + sh_s[c];
            v.y = z.y * sc_s[c + 1] + sh_s[c + 1];
            v.z = z.z * sc_s[c + 2] + sh_s[c + 2];
            v.w = z.w * sc_s[c + 3] + sh_s[c + 3];
        }
        *(float4*)&zs[rr][cg * 4] = v;
    }

    int tcol = tid & 31, trow = tid >> 5;
    int c0 = tcol * 4, r0 = trow * 8;
    float4 acc[8];
#pragma unroll
    for (int r = 0; r < 8; r++) acc[r] = make_float4(0.f, 0.f, 0.f, 0.f);

    for (int t = 0; t < 3; t++) {
        for (int kc = 0; kc < 8; kc++) {
            __syncthreads();
#pragma unroll
            for (int it = 0; it < 2; it++) {
                int idx = tid + it * 256;
                int k = idx >> 5, cg = idx & 31;
                *(float4*)&wt[k][cg * 4] =
                    *(const float4*)(g_wext + (size_t)(t * 128 + kc * 16 + k) * 128 + cg * 4);
            }
            __syncthreads();
#pragma unroll
            for (int kk = 0; kk < 16; kk += 4) {
                float4 a4[8];
#pragma unroll
                for (int r = 0; r < 8; r++)
                    a4[r] = *(float4*)&zs[r0 + r + t][kc * 16 + kk];
#pragma unroll
                for (int q = 0; q < 4; q++) {
                    float4 w4 = *(float4*)&wt[kk + q][c0];
#pragma unroll
                    for (int r = 0; r < 8; r++) {
                        float av = (q == 0) ? a4[r].x : (q == 1) ? a4[r].y
                                 : (q == 2) ? a4[r].z : a4[r].w;
                        acc[r].x += av * w4.x; acc[r].y += av * w4.y;
                        acc[r].z += av * w4.z; acc[r].w += av * w4.w;
                    }
                }
            }
        }
    }

    // softmax(weight2)
    float a0 = weight2[0], a1 = weight2[1];
    float wm = fmaxf(a0, a1);
    float e0 = __expf(a0 - wm), e1 = __expf(a1 - wm);
    float is = 1.f / (e0 + e1);
    float w20 = e0 * is, w21 = e1 * is;

    float4 b4 = *(const float4*)(conv_b + c0);
    float sst[4] = {0.f, 0.f, 0.f, 0.f};
    float qst[4] = {0.f, 0.f, 0.f, 0.f};
#pragma unroll
    for (int r = 0; r < 8; r++) {
        int grow = row0 + r0 + r;
        if (grow < N_NODES) {
            float4 z1;
            z1.x = acc[r].x + b4.x; z1.y = acc[r].y + b4.y;
            z1.z = acc[r].z + b4.z; z1.w = acc[r].w + b4.w;
            z1.x = (z1.x > 0.f) ? z1.x : 0.01f * z1.x;
            z1.y = (z1.y > 0.f) ? z1.y : 0.01f * z1.y;
            z1.z = (z1.z > 0.f) ? z1.z : 0.01f * z1.z;
            z1.w = (z1.w > 0.f) ? z1.w : 0.01f * z1.w;
            float4 zn = *(float4*)&zs[r0 + r + 1][c0];
            float4 o;
            o.x = w20 * zn.x + w21 * z1.x;
            o.y = w20 * zn.y + w21 * z1.y;
            o.z = w20 * zn.z + w21 * z1.z;
            o.w = w20 * zn.w + w21 * z1.w;
            *(float4*)(g_z2 + (size_t)grow * 128 + c0) = o;
            sst[0] += o.x; qst[0] += o.x * o.x;
            sst[1] += o.y; qst[1] += o.y * o.y;
            sst[2] += o.z; qst[2] += o.z * o.z;
            sst[3] += o.w; qst[3] += o.w * o.w;
        }
    }
#pragma unroll
    for (int j = 0; j < 4; j++) {
        atomicAdd(&red2[c0 + j], sst[j]);
        atomicAdd(&red2[128 + c0 + j], qst[j]);
    }
    __syncthreads();
    atomicAdd(&g_stats[256 + tid], red2[tid]);
}

// ---------------- final BN2 apply ----------------
__global__ void final_apply(float* __restrict__ out) {
    int idx = blockIdx.x * blockDim.x + threadIdx.x;   // over N*32 float4 groups
    if (idx >= N_NODES * 32) return;
    int cg = idx & 31;
    int c = cg * 4;
    float4 z = *(const float4*)(g_z2 + (size_t)idx * 4);
    float4 o;
    o.x = z.x * g_scale2[c]     + g_shift2[c];
    o.y = z.y * g_scale2[c + 1] + g_shift2[c + 1];
    o.z = z.z * g_scale2[c + 2] + g_shift2[c + 2];
    o.w = z.w * g_scale2[c + 3] + g_shift2[c + 3];
    *(float4*)(out + (size_t)idx * 4) = o;
}

// ---------------- launch ----------------
extern "C" void kernel_launch(void* const* d_in, const int* in_sizes, int n_in,
                              void* d_out, int out_size)
{
    const float* x         = (const float*)d_in[0];
    const int*   ei        = (const int*)d_in[1];
    const float* edge_attr = (const float*)d_in[2];
    const float* W_l       = (const float*)d_in[3];
    const float* b_l       = (const float*)d_in[4];
    const float* W_r       = (const float*)d_in[5];
    const float* b_r       = (const float*)d_in[6];
    const float* W_e       = (const float*)d_in[7];
    const float* att       = (const float*)d_in[8];
    const float* bias_gat  = (const float*)d_in[9];
    const float* weight1   = (const float*)d_in[10];
    const float* bn1_gamma = (const float*)d_in[11];
    const float* bn1_beta  = (const float*)d_in[12];
    const float* conv_w    = (const float*)d_in[13];
    const float* conv_b    = (const float*)d_in[14];
    const float* weight2   = (const float*)d_in[15];
    const float* bn2_gamma = (const float*)d_in[16];
    const float* bn2_beta  = (const float*)d_in[17];
    float* out = (float*)d_out;

    float *p_xl, *p_xr, *p_stats, *p_sc1, *p_sh1, *p_sc2, *p_sh2;
    cudaGetSymbolAddress((void**)&p_xl, g_xl);
    cudaGetSymbolAddress((void**)&p_xr, g_xr);
    cudaGetSymbolAddress((void**)&p_stats, g_stats);
    cudaGetSymbolAddress((void**)&p_sc1, g_scale1);
    cudaGetSymbolAddress((void**)&p_sh1, g_shift1);
    cudaGetSymbolAddress((void**)&p_sc2, g_scale2);
    cudaGetSymbolAddress((void**)&p_sh2, g_shift2);

    zero_kernel<<<(N_NODES + 255) / 256, 256>>>();
    gemm128<<<(N_NODES + 63) / 64, 256>>>(x, W_l, b_l, p_xl, N_NODES);
    gemm128<<<(N_NODES + 63) / 64, 256>>>(x, W_r, b_r, p_xr, N_NODES);
    hist_kernel<<<(E_EDGES + 255) / 256, 256>>>(ei);
    base_kernel<<<(N_NODES + 255) / 256, 256>>>();
    scatter_kernel<<<(E_EDGES + 255) / 256, 256>>>(ei);
    prep_wext<<<(384 * 128 + 255) / 256, 256>>>(conv_w);
    attn_kernel<<<N_NODES / 8, 256>>>(x, edge_attr, W_e, att, bias_gat, weight1);
    bn_finalize<<<1, 128>>>(p_stats, bn1_gamma, bn1_beta, p_sc1, p_sh1);
    conv_kernel<<<(N_NODES + 63) / 64, 256>>>(conv_b, weight2);
    bn_finalize<<<1, 128>>>(p_stats + 256, bn2_gamma, bn2_beta, p_sc2, p_sh2);
    final_apply<<<(N_NODES * 32 + 255) / 256, 256>>>(out);
}

// round 8
// speedup vs baseline: 1.7124x; 1.0817x over previous
#include <cuda_runtime.h>

#define N_NODES 50000
#define E_EDGES 800000
#define DCH     128
#define EDIM    16

typedef unsigned long long ull;

// ---------------- packed f32x2 helpers (sm_103a FFMA2) ----------------
__device__ __forceinline__ void fma2(ull &d, ull a, ull b) {
    asm("fma.rn.f32x2 %0, %1, %2, %0;" : "+l"(d) : "l"(a), "l"(b));
}
__device__ __forceinline__ ull dup2(float a) {
    ull r; asm("mov.b64 %0, {%1, %1};" : "=l"(r) : "f"(a)); return r;
}
__device__ __forceinline__ ull pack2(float a, float b) {
    ull r; asm("mov.b64 %0, {%1, %2};" : "=l"(r) : "f"(a), "f"(b)); return r;
}
__device__ __forceinline__ float2 u2f(ull v) {
    float2 f; asm("mov.b64 {%0, %1}, %2;" : "=f"(f.x), "=f"(f.y) : "l"(v)); return f;
}

// ---------------- device scratch (no allocs allowed) ----------------
__device__ float g_xl[N_NODES * DCH];
__device__ float g_xr[N_NODES * DCH];
__device__ float g_zpre[N_NODES * DCH];
__device__ float g_z2[N_NODES * DCH];
__device__ float g_wext[384 * DCH];
__device__ int   g_deg[N_NODES];
__device__ int   g_cur[N_NODES];
__device__ int   g_off[N_NODES];
__device__ int   g_srcl[E_EDGES];
__device__ int   g_eidl[E_EDGES];
__device__ int   g_cnt;
__device__ float g_stats[512];              // [0..255] bn1 (sum,sumsq), [256..511] bn2
__device__ float g_scale1[DCH], g_shift1[DCH];
__device__ float g_scale2[DCH], g_shift2[DCH];

// ---------------- zero scratch ----------------
__global__ void zero_kernel() {
    int idx = blockIdx.x * blockDim.x + threadIdx.x;
    if (idx < N_NODES) { g_deg[idx] = 0; g_cur[idx] = 0; }
    if (idx < 512) g_stats[idx] = 0.f;
    if (idx == 0) g_cnt = 0;
}

// ---------------- generic 128x128 GEMM: C = A@W + b (R5 proven version) ----------------
__global__ __launch_bounds__(256) void gemm128(
    const float* __restrict__ A, const float* __restrict__ W,
    const float* __restrict__ bias, float* __restrict__ C, int nrows)
{
    __shared__ float as[16][64];
    __shared__ float ws[16][128];
    int tid = threadIdx.x;
    int row0 = blockIdx.x * 64;
    int tcol = tid & 31, trow = tid >> 5;
    int c0 = tcol * 4, r0 = trow * 8;
    float4 acc[8];
#pragma unroll
    for (int r = 0; r < 8; r++) acc[r] = make_float4(0.f, 0.f, 0.f, 0.f);

    int lr = tid & 63, lkg = tid >> 6;
    for (int kb = 0; kb < 128; kb += 16) {
        float4 v = make_float4(0.f, 0.f, 0.f, 0.f);
        int grow = row0 + lr;
        if (grow < nrows) v = *(const float4*)(A + (size_t)grow * 128 + kb + lkg * 4);
        as[lkg * 4 + 0][lr] = v.x; as[lkg * 4 + 1][lr] = v.y;
        as[lkg * 4 + 2][lr] = v.z; as[lkg * 4 + 3][lr] = v.w;
#pragma unroll
        for (int it = 0; it < 2; it++) {
            int idx = tid + it * 256;
            int k = idx >> 5, cg = idx & 31;
            *(float4*)&ws[k][cg * 4] = *(const float4*)(W + (size_t)(kb + k) * 128 + cg * 4);
        }
        __syncthreads();
#pragma unroll
        for (int k = 0; k < 16; k++) {
            float4 w4  = *(float4*)&ws[k][c0];
            float4 alo = *(float4*)&as[k][r0];
            float4 ahi = *(float4*)&as[k][r0 + 4];
            float a[8] = {alo.x, alo.y, alo.z, alo.w, ahi.x, ahi.y, ahi.z, ahi.w};
#pragma unroll
            for (int r = 0; r < 8; r++) {
                acc[r].x += a[r] * w4.x; acc[r].y += a[r] * w4.y;
                acc[r].z += a[r] * w4.z; acc[r].w += a[r] * w4.w;
            }
        }
        __syncthreads();
    }
    float4 b4 = *(const float4*)(bias + c0);
#pragma unroll
    for (int r = 0; r < 8; r++) {
        int grow = row0 + r0 + r;
        if (grow < nrows) {
            float4 o;
            o.x = acc[r].x + b4.x; o.y = acc[r].y + b4.y;
            o.z = acc[r].z + b4.z; o.w = acc[r].w + b4.w;
            *(float4*)(C + (size_t)grow * 128 + c0) = o;
        }
    }
}

// ---------------- CSR build (no self loops; atomic segment bases) ----------------
__global__ void hist_kernel(const int* __restrict__ ei) {
    int t = blockIdx.x * blockDim.x + threadIdx.x;
    if (t >= E_EDGES) return;
    atomicAdd(&g_deg[ei[E_EDGES + t]], 1);
}

__global__ void base_kernel() {
    int idx = blockIdx.x * blockDim.x + threadIdx.x;
    if (idx < N_NODES) g_off[idx] = atomicAdd(&g_cnt, g_deg[idx]);
}

__global__ void scatter_kernel(const int* __restrict__ ei) {
    int t = blockIdx.x * blockDim.x + threadIdx.x;
    if (t >= E_EDGES) return;
    int dst = ei[E_EDGES + t];
    int pos = atomicAdd(&g_cur[dst], 1);
    int o = g_off[dst] + pos;
    g_srcl[o] = ei[t];
    g_eidl[o] = t;
}

// ---------------- conv weight transpose: wext[(t*128+cin)*128 + cout] ----------------
__global__ void prep_wext(const float* __restrict__ conv_w) {
    int idx = blockIdx.x * blockDim.x + threadIdx.x;
    if (idx >= 384 * 128) return;
    int kext = idx >> 7, cout = idx & 127;
    int t = kext >> 7, cin = kext & 127;
    g_wext[idx] = conv_w[cout * 384 + cin * 3 + t];
}

// ---------------- fused attention: warp/node, online softmax, 2-edge batch + FFMA2 ----------------
__global__ __launch_bounds__(256) void attn_kernel(
    const float* __restrict__ x,
    const float* __restrict__ edge_attr, const float* __restrict__ W_e,
    const float* __restrict__ att, const float* __restrict__ bias_gat,
    const float* __restrict__ weight1)
{
    __shared__ __align__(16) float We_s[2048];
    __shared__ float att_s[128];
    __shared__ float bias_s[128];
    __shared__ float red_s[256];
    int tid = threadIdx.x;
    for (int idx = tid; idx < 2048; idx += 256) We_s[idx] = W_e[idx];
    if (tid < 128) { att_s[tid] = att[tid]; bias_s[tid] = bias_gat[tid]; }
    red_s[tid] = 0.f;
    __syncthreads();

    int i = blockIdx.x * 8 + (tid >> 5);   // grid = 6250 -> exactly 50000 nodes
    int lane = tid & 31;
    int c0 = lane * 4;
    int base = g_off[i];
    int deg = g_deg[i];

    const float4 xr4 = *(const float4*)(g_xr + (size_t)i * 128 + c0);
    const float4 xli = *(const float4*)(g_xl + (size_t)i * 128 + c0);
    float ax = att_s[c0], ay = att_s[c0 + 1], az = att_s[c0 + 2], aw = att_s[c0 + 3];

    // self loop handled analytically: message = leaky(xl_i + xr_i), no edge term
    float sx = xli.x + xr4.x, sy = xli.y + xr4.y;
    float sz = xli.z + xr4.z, sw = xli.w + xr4.w;
    sx = (sx > 0.f) ? sx : 0.2f * sx; sy = (sy > 0.f) ? sy : 0.2f * sy;
    sz = (sz > 0.f) ? sz : 0.2f * sz; sw = (sw > 0.f) ? sw : 0.2f * sw;
    float part = sx * ax + sy * ay + sz * az + sw * aw;
#pragma unroll
    for (int o = 16; o; o >>= 1) part += __shfl_xor_sync(0xffffffffu, part, o);
    float m = part, den = 1.f;
    float4 acc = xli;

    int jj = 0;
    // ---- 2-edge batched mainloop: one We_s read serves both edges ----
    for (; jj + 2 <= deg; jj += 2) {
        int s0 = g_srcl[base + jj],     s1 = g_srcl[base + jj + 1];
        int e0 = g_eidl[base + jj],     e1 = g_eidl[base + jj + 1];
        const float4 xlA = *(const float4*)(g_xl + (size_t)s0 * 128 + c0);
        const float4 xlB = *(const float4*)(g_xl + (size_t)s1 * 128 + c0);
        const float4* epA = (const float4*)(edge_attr + (size_t)e0 * EDIM);
        const float4* epB = (const float4*)(edge_attr + (size_t)e1 * EDIM);
        float4 aA = __ldg(epA), aB = __ldg(epA + 1), aC = __ldg(epA + 2), aD = __ldg(epA + 3);
        float4 bA = __ldg(epB), bB = __ldg(epB + 1), bC = __ldg(epB + 2), bD = __ldg(epB + 3);
        float evA[16] = {aA.x, aA.y, aA.z, aA.w, aB.x, aB.y, aB.z, aB.w,
                         aC.x, aC.y, aC.z, aC.w, aD.x, aD.y, aD.z, aD.w};
        float evB[16] = {bA.x, bA.y, bA.z, bA.w, bB.x, bB.y, bB.z, bB.w,
                         bC.x, bC.y, bC.z, bC.w, bD.x, bD.y, bD.z, bD.w};

        ull a01 = pack2(xlA.x + xr4.x, xlA.y + xr4.y);
        ull a23 = pack2(xlA.z + xr4.z, xlA.w + xr4.w);
        ull b01 = pack2(xlB.x + xr4.x, xlB.y + xr4.y);
        ull b23 = pack2(xlB.z + xr4.z, xlB.w + xr4.w);
#pragma unroll
        for (int k = 0; k < EDIM; k++) {
            ulonglong2 w = *(const ulonglong2*)&We_s[k * 128 + c0];
            ull dA = dup2(evA[k]);
            ull dB = dup2(evB[k]);
            fma2(a01, dA, w.x); fma2(a23, dA, w.y);
            fma2(b01, dB, w.x); fma2(b23, dB, w.y);
        }
        float2 pA01 = u2f(a01), pA23 = u2f(a23);
        float2 pB01 = u2f(b01), pB23 = u2f(b23);
        float mxA = pA01.x, myA = pA01.y, mzA = pA23.x, mwA = pA23.y;
        float mxB = pB01.x, myB = pB01.y, mzB = pB23.x, mwB = pB23.y;
        mxA = (mxA > 0.f) ? mxA : 0.2f * mxA;  myA = (myA > 0.f) ? myA : 0.2f * myA;
        mzA = (mzA > 0.f) ? mzA : 0.2f * mzA;  mwA = (mwA > 0.f) ? mwA : 0.2f * mwA;
        mxB = (mxB > 0.f) ? mxB : 0.2f * mxB;  myB = (myB > 0.f) ? myB : 0.2f * myB;
        mzB = (mzB > 0.f) ? mzB : 0.2f * mzB;  mwB = (mwB > 0.f) ? mwB : 0.2f * mwB;
        float pA = mxA * ax + myA * ay + mzA * az + mwA * aw;
        float pB = mxB * ax + myB * ay + mzB * az + mwB * aw;
#pragma unroll
        for (int o = 16; o; o >>= 1) {
            pA += __shfl_xor_sync(0xffffffffu, pA, o);
            pB += __shfl_xor_sync(0xffffffffu, pB, o);
        }
        // sequential online-softmax updates (warp-uniform branches)
        if (pA > m) {
            float scl = __expf(m - pA);
            den *= scl;
            acc.x *= scl; acc.y *= scl; acc.z *= scl; acc.w *= scl;
            m = pA;
        }
        {
            float pr = __expf(pA - m);
            den += pr;
            acc.x += pr * xlA.x; acc.y += pr * xlA.y;
            acc.z += pr * xlA.z; acc.w += pr * xlA.w;
        }
        if (pB > m) {
            float scl = __expf(m - pB);
            den *= scl;
            acc.x *= scl; acc.y *= scl; acc.z *= scl; acc.w *= scl;
            m = pB;
        }
        {
            float pr = __expf(pB - m);
            den += pr;
            acc.x += pr * xlB.x; acc.y += pr * xlB.y;
            acc.z += pr * xlB.z; acc.w += pr * xlB.w;
        }
    }
    // ---- tail (deg odd): single-edge body ----
    for (; jj < deg; ++jj) {
        int src = g_srcl[base + jj];
        int e   = g_eidl[base + jj];
        const float4 xl4 = *(const float4*)(g_xl + (size_t)src * 128 + c0);
        const float4* eap = (const float4*)(edge_attr + (size_t)e * EDIM);
        float4 eA = __ldg(eap), eB = __ldg(eap + 1), eC = __ldg(eap + 2), eD = __ldg(eap + 3);
        float ev[16] = {eA.x, eA.y, eA.z, eA.w, eB.x, eB.y, eB.z, eB.w,
                        eC.x, eC.y, eC.z, eC.w, eD.x, eD.y, eD.z, eD.w};
        float mx = xl4.x + xr4.x, my = xl4.y + xr4.y;
        float mz = xl4.z + xr4.z, mw = xl4.w + xr4.w;
#pragma unroll
        for (int k = 0; k < EDIM; k++) {
            const float4 w = *(const float4*)&We_s[k * 128 + c0];
            mx += ev[k] * w.x; my += ev[k] * w.y; mz += ev[k] * w.z; mw += ev[k] * w.w;
        }
        mx = (mx > 0.f) ? mx : 0.2f * mx;
        my = (my > 0.f) ? my : 0.2f * my;
        mz = (mz > 0.f) ? mz : 0.2f * mz;
        mw = (mw > 0.f) ? mw : 0.2f * mw;
        float p = mx * ax + my * ay + mz * az + mw * aw;
#pragma unroll
        for (int o = 16; o; o >>= 1) p += __shfl_xor_sync(0xffffffffu, p, o);
        if (p > m) {
            float scl = __expf(m - p);
            den *= scl;
            acc.x *= scl; acc.y *= scl; acc.z *= scl; acc.w *= scl;
            m = p;
        }
        float pr = __expf(p - m);
        den += pr;
        acc.x += pr * xl4.x; acc.y += pr * xl4.y;
        acc.z += pr * xl4.z; acc.w += pr * xl4.w;
    }

    float inv = 1.f / den;
    // softmax(weight1)
    float a0 = weight1[0], a1 = weight1[1];
    float wm = fmaxf(a0, a1);
    float e0 = __expf(a0 - wm), e1 = __expf(a1 - wm);
    float is = 1.f / (e0 + e1);
    float w10 = e0 * is, w11 = e1 * is;

    const float4 xv = *(const float4*)(x + (size_t)i * 128 + c0);
    float4 o;
    o.x = w10 * xv.x + w11 * (acc.x * inv + bias_s[c0]);
    o.y = w10 * xv.y + w11 * (acc.y * inv + bias_s[c0 + 1]);
    o.z = w10 * xv.z + w11 * (acc.z * inv + bias_s[c0 + 2]);
    o.w = w10 * xv.w + w11 * (acc.w * inv + bias_s[c0 + 3]);
    *(float4*)(g_zpre + (size_t)i * 128 + c0) = o;

    // fused BN1 stats: block-level partials then one global flush
    atomicAdd(&red_s[c0 + 0], o.x); atomicAdd(&red_s[128 + c0 + 0], o.x * o.x);
    atomicAdd(&red_s[c0 + 1], o.y); atomicAdd(&red_s[128 + c0 + 1], o.y * o.y);
    atomicAdd(&red_s[c0 + 2], o.z); atomicAdd(&red_s[128 + c0 + 2], o.z * o.z);
    atomicAdd(&red_s[c0 + 3], o.w); atomicAdd(&red_s[128 + c0 + 3], o.w * o.w);
    __syncthreads();
    atomicAdd(&g_stats[tid], red_s[tid]);
}

__global__ void bn_finalize(const float* __restrict__ stats,
                            const float* __restrict__ gamma, const float* __restrict__ beta,
                            float* __restrict__ scale, float* __restrict__ shift)
{
    int c = threadIdx.x;
    float mu = stats[c] * (1.f / N_NODES);
    float var = stats[128 + c] * (1.f / N_NODES) - mu * mu;
    float rstd = rsqrtf(var + 1e-5f);
    float s = rstd * gamma[c];
    scale[c] = s;
    shift[c] = beta[c] - mu * s;
}

// ---------------- conv1d(k=3) as K=384 GEMM + mix + fused BN2 stats ----------------
__global__ __launch_bounds__(256) void conv_kernel(const float* __restrict__ conv_b,
                                                   const float* __restrict__ weight2)
{
    __shared__ float zs[66][128];
    __shared__ float wt[16][128];
    __shared__ float sc_s[128], sh_s[128];
    __shared__ float red2[256];
    int tid = threadIdx.x;
    int row0 = blockIdx.x * 64;
    if (tid < 128) { sc_s[tid] = g_scale1[tid]; sh_s[tid] = g_shift1[tid]; }
    red2[tid] = 0.f;
    __syncthreads();

    // load + normalize input tile rows [row0-1, row0+64]; zero pad outside [0,N)
    for (int idx = tid; idx < 66 * 32; idx += 256) {
        int rr = idx >> 5, cg = idx & 31;
        int grow = row0 - 1 + rr;
        float4 v = make_float4(0.f, 0.f, 0.f, 0.f);
        if (grow >= 0 && grow < N_NODES) {
            float4 z = *(const float4*)(g_zpre + (size_t)grow * 128 + cg * 4);
            int c = cg * 4;
            v.x = z.x * sc_s[c] + sh_s[c];
            v.y = z.y * sc_s[c + 1] + sh_s[c + 1];
            v.z = z.z * sc_s[c + 2] + sh_s[c + 2];
            v.w = z.w * sc_s[c + 3] + sh_s[c + 3];
        }
        *(float4*)&zs[rr][cg * 4] = v;
    }

    int tcol = tid & 31, trow = tid >> 5;
    int c0 = tcol * 4, r0 = trow * 8;
    float4 acc[8];
#pragma unroll
    for (int r = 0; r < 8; r++) acc[r] = make_float4(0.f, 0.f, 0.f, 0.f);

    for (int t = 0; t < 3; t++) {
        for (int kc = 0; kc < 8; kc++) {
            __syncthreads();
#pragma unroll
            for (int it = 0; it < 2; it++) {
                int idx = tid + it * 256;
                int k = idx >> 5, cg = idx & 31;
                *(float4*)&wt[k][cg * 4] =
                    *(const float4*)(g_wext + (size_t)(t * 128 + kc * 16 + k) * 128 + cg * 4);
            }
            __syncthreads();
#pragma unroll
            for (int kk = 0; kk < 16; kk += 4) {
                float4 a4[8];
#pragma unroll
                for (int r = 0; r < 8; r++)
                    a4[r] = *(float4*)&zs[r0 + r + t][kc * 16 + kk];
#pragma unroll
                for (int q = 0; q < 4; q++) {
                    float4 w4 = *(float4*)&wt[kk + q][c0];
#pragma unroll
                    for (int r = 0; r < 8; r++) {
                        float av = (q == 0) ? a4[r].x : (q == 1) ? a4[r].y
                                 : (q == 2) ? a4[r].z : a4[r].w;
                        acc[r].x += av * w4.x; acc[r].y += av * w4.y;
                        acc[r].z += av * w4.z; acc[r].w += av * w4.w;
                    }
                }
            }
        }
    }

    // softmax(weight2)
    float a0 = weight2[0], a1 = weight2[1];
    float wm = fmaxf(a0, a1);
    float e0 = __expf(a0 - wm), e1 = __expf(a1 - wm);
    float is = 1.f / (e0 + e1);
    float w20 = e0 * is, w21 = e1 * is;

    float4 b4 = *(const float4*)(conv_b + c0);
    float sst[4] = {0.f, 0.f, 0.f, 0.f};
    float qst[4] = {0.f, 0.f, 0.f, 0.f};
#pragma unroll
    for (int r = 0; r < 8; r++) {
        int grow = row0 + r0 + r;
        if (grow < N_NODES) {
            float4 z1;
            z1.x = acc[r].x + b4.x; z1.y = acc[r].y + b4.y;
            z1.z = acc[r].z + b4.z; z1.w = acc[r].w + b4.w;
            z1.x = (z1.x > 0.f) ? z1.x : 0.01f * z1.x;
            z1.y = (z1.y > 0.f) ? z1.y : 0.01f * z1.y;
            z1.z = (z1.z > 0.f) ? z1.z : 0.01f * z1.z;
            z1.w = (z1.w > 0.f) ? z1.w : 0.01f * z1.w;
            float4 zn = *(float4*)&zs[r0 + r + 1][c0];
            float4 o;
            o.x = w20 * zn.x + w21 * z1.x;
            o.y = w20 * zn.y + w21 * z1.y;
            o.z = w20 * zn.z + w21 * z1.z;
            o.w = w20 * zn.w + w21 * z1.w;
            *(float4*)(g_z2 + (size_t)grow * 128 + c0) = o;
            sst[0] += o.x; qst[0] += o.x * o.x;
            sst[1] += o.y; qst[1] += o.y * o.y;
            sst[2] += o.z; qst[2] += o.z * o.z;
            sst[3] += o.w; qst[3] += o.w * o.w;
        }
    }
#pragma unroll
    for (int j = 0; j < 4; j++) {
        atomicAdd(&red2[c0 + j], sst[j]);
        atomicAdd(&red2[128 + c0 + j], qst[j]);
    }
    __syncthreads();
    atomicAdd(&g_stats[256 + tid], red2[tid]);
}

// ---------------- final BN2 apply ----------------
__global__ void final_apply(float* __restrict__ out) {
    int idx = blockIdx.x * blockDim.x + threadIdx.x;   // over N*32 float4 groups
    if (idx >= N_NODES * 32) return;
    int cg = idx & 31;
    int c = cg * 4;
    float4 z = *(const float4*)(g_z2 + (size_t)idx * 4);
    float4 o;
    o.x = z.x * g_scale2[c]     + g_shift2[c];
    o.y = z.y * g_scale2[c + 1] + g_shift2[c + 1];
    o.z = z.z * g_scale2[c + 2] + g_shift2[c + 2];
    o.w = z.w * g_scale2[c + 3] + g_shift2[c + 3];
    *(float4*)(out + (size_t)idx * 4) = o;
}

// ---------------- launch ----------------
extern "C" void kernel_launch(void* const* d_in, const int* in_sizes, int n_in,
                              void* d_out, int out_size)
{
    const float* x         = (const float*)d_in[0];
    const int*   ei        = (const int*)d_in[1];
    const float* edge_attr = (const float*)d_in[2];
    const float* W_l       = (const float*)d_in[3];
    const float* b_l       = (const float*)d_in[4];
    const float* W_r       = (const float*)d_in[5];
    const float* b_r       = (const float*)d_in[6];
    const float* W_e       = (const float*)d_in[7];
    const float* att       = (const float*)d_in[8];
    const float* bias_gat  = (const float*)d_in[9];
    const float* weight1   = (const float*)d_in[10];
    const float* bn1_gamma = (const float*)d_in[11];
    const float* bn1_beta  = (const float*)d_in[12];
    const float* conv_w    = (const float*)d_in[13];
    const float* conv_b    = (const float*)d_in[14];
    const float* weight2   = (const float*)d_in[15];
    const float* bn2_gamma = (const float*)d_in[16];
    const float* bn2_beta  = (const float*)d_in[17];
    float* out = (float*)d_out;

    float *p_xl, *p_xr, *p_stats, *p_sc1, *p_sh1, *p_sc2, *p_sh2;
    cudaGetSymbolAddress((void**)&p_xl, g_xl);
    cudaGetSymbolAddress((void**)&p_xr, g_xr);
    cudaGetSymbolAddress((void**)&p_stats, g_stats);
    cudaGetSymbolAddress((void**)&p_sc1, g_scale1);
    cudaGetSymbolAddress((void**)&p_sh1, g_shift1);
    cudaGetSymbolAddress((void**)&p_sc2, g_scale2);
    cudaGetSymbolAddress((void**)&p_sh2, g_shift2);

    zero_kernel<<<(N_NODES + 255) / 256, 256>>>();
    gemm128<<<(N_NODES + 63) / 64, 256>>>(x, W_l, b_l, p_xl, N_NODES);
    gemm128<<<(N_NODES + 63) / 64, 256>>>(x, W_r, b_r, p_xr, N_NODES);
    hist_kernel<<<(E_EDGES + 255) / 256, 256>>>(ei);
    base_kernel<<<(N_NODES + 255) / 256, 256>>>();
    scatter_kernel<<<(E_EDGES + 255) / 256, 256>>>(ei);
    prep_wext<<<(384 * 128 + 255) / 256, 256>>>(conv_w);
    attn_kernel<<<N_NODES / 8, 256>>>(x, edge_attr, W_e, att, bias_gat, weight1);
    bn_finalize<<<1, 128>>>(p_stats, bn1_gamma, bn1_beta, p_sc1, p_sh1);
    conv_kernel<<<(N_NODES + 63) / 64, 256>>>(conv_b, weight2);
    bn_finalize<<<1, 128>>>(p_stats + 256, bn2_gamma, bn2_beta, p_sc2, p_sh2);
    final_apply<<<(N_NODES * 32 + 255) / 256, 256>>>(out);
}

// round 9
// speedup vs baseline: 1.7319x; 1.0114x over previous
#include <cuda_runtime.h>

#define N_NODES 50000
#define E_EDGES 800000
#define DCH     128
#define EDIM    16

typedef unsigned long long ull;

// ---------------- packed f32x2 helpers (sm_103a FFMA2) ----------------
__device__ __forceinline__ void fma2(ull &d, ull a, ull b) {
    asm("fma.rn.f32x2 %0, %1, %2, %0;" : "+l"(d) : "l"(a), "l"(b));
}
__device__ __forceinline__ ull dup2(float a) {
    ull r; asm("mov.b64 %0, {%1, %1};" : "=l"(r) : "f"(a)); return r;
}
__device__ __forceinline__ ull pack2(float a, float b) {
    ull r; asm("mov.b64 %0, {%1, %2};" : "=l"(r) : "f"(a), "f"(b)); return r;
}
__device__ __forceinline__ float2 u2f(ull v) {
    float2 f; asm("mov.b64 {%0, %1}, %2;" : "=f"(f.x), "=f"(f.y) : "l"(v)); return f;
}

// ---------------- device scratch (no allocs allowed) ----------------
__device__ float g_xl[N_NODES * DCH];
__device__ float g_xr[N_NODES * DCH];
__device__ float g_zpre[N_NODES * DCH];
__device__ float g_z2[N_NODES * DCH];
__device__ float g_wext[384 * DCH];
__device__ int   g_deg[N_NODES];
__device__ int   g_cur[N_NODES];
__device__ int   g_off[N_NODES];
__device__ int   g_srcl[E_EDGES];
__device__ int   g_eidl[E_EDGES];
__device__ int   g_cnt;
__device__ float g_stats[512];              // [0..255] bn1 (sum,sumsq), [256..511] bn2
__device__ float g_scale1[DCH], g_shift1[DCH];
__device__ float g_scale2[DCH], g_shift2[DCH];

// ---------------- zero scratch ----------------
__global__ void zero_kernel() {
    int idx = blockIdx.x * blockDim.x + threadIdx.x;
    if (idx < N_NODES) { g_deg[idx] = 0; g_cur[idx] = 0; }
    if (idx < 512) g_stats[idx] = 0.f;
    if (idx == 0) g_cnt = 0;
}

// ---------------- 128x128 GEMM: C = A@W + b (R5 geometry, FFMA2 inner) ----------------
__global__ __launch_bounds__(256) void gemm128(
    const float* __restrict__ A, const float* __restrict__ W,
    const float* __restrict__ bias, float* __restrict__ C, int nrows)
{
    __shared__ __align__(16) float as[16][64];
    __shared__ __align__(16) float ws[16][128];
    int tid = threadIdx.x;
    int row0 = blockIdx.x * 64;
    int tcol = tid & 31, trow = tid >> 5;
    int c0 = tcol * 4, r0 = trow * 8;
    ull acc2[8][2];
#pragma unroll
    for (int r = 0; r < 8; r++) { acc2[r][0] = 0ull; acc2[r][1] = 0ull; }

    int lr = tid & 63, lkg = tid >> 6;
    for (int kb = 0; kb < 128; kb += 16) {
        float4 v = make_float4(0.f, 0.f, 0.f, 0.f);
        int grow = row0 + lr;
        if (grow < nrows) v = *(const float4*)(A + (size_t)grow * 128 + kb + lkg * 4);
        as[lkg * 4 + 0][lr] = v.x; as[lkg * 4 + 1][lr] = v.y;
        as[lkg * 4 + 2][lr] = v.z; as[lkg * 4 + 3][lr] = v.w;
#pragma unroll
        for (int it = 0; it < 2; it++) {
            int idx = tid + it * 256;
            int k = idx >> 5, cg = idx & 31;
            *(float4*)&ws[k][cg * 4] = *(const float4*)(W + (size_t)(kb + k) * 128 + cg * 4);
        }
        __syncthreads();
#pragma unroll
        for (int k = 0; k < 16; k++) {
            ulonglong2 w2 = *(const ulonglong2*)&ws[k][c0];
            float4 alo = *(const float4*)&as[k][r0];
            float4 ahi = *(const float4*)&as[k][r0 + 4];
            float a[8] = {alo.x, alo.y, alo.z, alo.w, ahi.x, ahi.y, ahi.z, ahi.w};
#pragma unroll
            for (int r = 0; r < 8; r++) {
                ull ad = dup2(a[r]);
                fma2(acc2[r][0], ad, w2.x);
                fma2(acc2[r][1], ad, w2.y);
            }
        }
        __syncthreads();
    }
    float4 b4 = *(const float4*)(bias + c0);
#pragma unroll
    for (int r = 0; r < 8; r++) {
        int grow = row0 + r0 + r;
        if (grow < nrows) {
            float2 u0 = u2f(acc2[r][0]), u1 = u2f(acc2[r][1]);
            float4 o;
            o.x = u0.x + b4.x; o.y = u0.y + b4.y;
            o.z = u1.x + b4.z; o.w = u1.y + b4.w;
            *(float4*)(C + (size_t)grow * 128 + c0) = o;
        }
    }
}

// ---------------- CSR build (no self loops; atomic segment bases) ----------------
__global__ void hist_kernel(const int* __restrict__ ei) {
    int t = blockIdx.x * blockDim.x + threadIdx.x;
    if (t >= E_EDGES) return;
    atomicAdd(&g_deg[ei[E_EDGES + t]], 1);
}

__global__ void base_kernel() {
    int idx = blockIdx.x * blockDim.x + threadIdx.x;
    if (idx < N_NODES) g_off[idx] = atomicAdd(&g_cnt, g_deg[idx]);
}

__global__ void scatter_kernel(const int* __restrict__ ei) {
    int t = blockIdx.x * blockDim.x + threadIdx.x;
    if (t >= E_EDGES) return;
    int dst = ei[E_EDGES + t];
    int pos = atomicAdd(&g_cur[dst], 1);
    int o = g_off[dst] + pos;
    g_srcl[o] = ei[t];
    g_eidl[o] = t;
}

// ---------------- conv weight transpose: wext[(t*128+cin)*128 + cout] ----------------
__global__ void prep_wext(const float* __restrict__ conv_w) {
    int idx = blockIdx.x * blockDim.x + threadIdx.x;
    if (idx >= 384 * 128) return;
    int kext = idx >> 7, cout = idx & 127;
    int t = kext >> 7, cin = kext & 127;
    g_wext[idx] = conv_w[cout * 384 + cin * 3 + t];
}

// ---------------- fused attention: warp/node, online softmax, 2-edge batch + FFMA2 ----------------
__global__ __launch_bounds__(256) void attn_kernel(
    const float* __restrict__ x,
    const float* __restrict__ edge_attr, const float* __restrict__ W_e,
    const float* __restrict__ att, const float* __restrict__ bias_gat,
    const float* __restrict__ weight1)
{
    __shared__ __align__(16) float We_s[2048];
    __shared__ float att_s[128];
    __shared__ float bias_s[128];
    __shared__ float red_s[256];
    int tid = threadIdx.x;
    for (int idx = tid; idx < 2048; idx += 256) We_s[idx] = W_e[idx];
    if (tid < 128) { att_s[tid] = att[tid]; bias_s[tid] = bias_gat[tid]; }
    red_s[tid] = 0.f;
    __syncthreads();

    int i = blockIdx.x * 8 + (tid >> 5);   // grid = 6250 -> exactly 50000 nodes
    int lane = tid & 31;
    int c0 = lane * 4;
    int base = g_off[i];
    int deg = g_deg[i];

    const float4 xr4 = *(const float4*)(g_xr + (size_t)i * 128 + c0);
    const float4 xli = *(const float4*)(g_xl + (size_t)i * 128 + c0);
    float ax = att_s[c0], ay = att_s[c0 + 1], az = att_s[c0 + 2], aw = att_s[c0 + 3];

    // self loop handled analytically: message = leaky(xl_i + xr_i), no edge term
    float sx = xli.x + xr4.x, sy = xli.y + xr4.y;
    float sz = xli.z + xr4.z, sw = xli.w + xr4.w;
    sx = (sx > 0.f) ? sx : 0.2f * sx; sy = (sy > 0.f) ? sy : 0.2f * sy;
    sz = (sz > 0.f) ? sz : 0.2f * sz; sw = (sw > 0.f) ? sw : 0.2f * sw;
    float part = sx * ax + sy * ay + sz * az + sw * aw;
#pragma unroll
    for (int o = 16; o; o >>= 1) part += __shfl_xor_sync(0xffffffffu, part, o);
    float m = part, den = 1.f;
    float4 acc = xli;

    int jj = 0;
    // ---- 2-edge batched mainloop: one We_s read serves both edges ----
    for (; jj + 2 <= deg; jj += 2) {
        int s0 = g_srcl[base + jj],     s1 = g_srcl[base + jj + 1];
        int e0 = g_eidl[base + jj],     e1 = g_eidl[base + jj + 1];
        const float4 xlA = *(const float4*)(g_xl + (size_t)s0 * 128 + c0);
        const float4 xlB = *(const float4*)(g_xl + (size_t)s1 * 128 + c0);
        const float4* epA = (const float4*)(edge_attr + (size_t)e0 * EDIM);
        const float4* epB = (const float4*)(edge_attr + (size_t)e1 * EDIM);
        float4 aA = __ldg(epA), aB = __ldg(epA + 1), aC = __ldg(epA + 2), aD = __ldg(epA + 3);
        float4 bA = __ldg(epB), bB = __ldg(epB + 1), bC = __ldg(epB + 2), bD = __ldg(epB + 3);
        float evA[16] = {aA.x, aA.y, aA.z, aA.w, aB.x, aB.y, aB.z, aB.w,
                         aC.x, aC.y, aC.z, aC.w, aD.x, aD.y, aD.z, aD.w};
        float evB[16] = {bA.x, bA.y, bA.z, bA.w, bB.x, bB.y, bB.z, bB.w,
                         bC.x, bC.y, bC.z, bC.w, bD.x, bD.y, bD.z, bD.w};

        ull a01 = pack2(xlA.x + xr4.x, xlA.y + xr4.y);
        ull a23 = pack2(xlA.z + xr4.z, xlA.w + xr4.w);
        ull b01 = pack2(xlB.x + xr4.x, xlB.y + xr4.y);
        ull b23 = pack2(xlB.z + xr4.z, xlB.w + xr4.w);
#pragma unroll
        for (int k = 0; k < EDIM; k++) {
            ulonglong2 w = *(const ulonglong2*)&We_s[k * 128 + c0];
            ull dA = dup2(evA[k]);
            ull dB = dup2(evB[k]);
            fma2(a01, dA, w.x); fma2(a23, dA, w.y);
            fma2(b01, dB, w.x); fma2(b23, dB, w.y);
        }
        float2 pA01 = u2f(a01), pA23 = u2f(a23);
        float2 pB01 = u2f(b01), pB23 = u2f(b23);
        float mxA = pA01.x, myA = pA01.y, mzA = pA23.x, mwA = pA23.y;
        float mxB = pB01.x, myB = pB01.y, mzB = pB23.x, mwB = pB23.y;
        mxA = (mxA > 0.f) ? mxA : 0.2f * mxA;  myA = (myA > 0.f) ? myA : 0.2f * myA;
        mzA = (mzA > 0.f) ? mzA : 0.2f * mzA;  mwA = (mwA > 0.f) ? mwA : 0.2f * mwA;
        mxB = (mxB > 0.f) ? mxB : 0.2f * mxB;  myB = (myB > 0.f) ? myB : 0.2f * myB;
        mzB = (mzB > 0.f) ? mzB : 0.2f * mzB;  mwB = (mwB > 0.f) ? mwB : 0.2f * mwB;
        float pA = mxA * ax + myA * ay + mzA * az + mwA * aw;
        float pB = mxB * ax + myB * ay + mzB * az + mwB * aw;
#pragma unroll
        for (int o = 16; o; o >>= 1) {
            pA += __shfl_xor_sync(0xffffffffu, pA, o);
            pB += __shfl_xor_sync(0xffffffffu, pB, o);
        }
        // sequential online-softmax updates (warp-uniform branches)
        if (pA > m) {
            float scl = __expf(m - pA);
            den *= scl;
            acc.x *= scl; acc.y *= scl; acc.z *= scl; acc.w *= scl;
            m = pA;
        }
        {
            float pr = __expf(pA - m);
            den += pr;
            acc.x += pr * xlA.x; acc.y += pr * xlA.y;
            acc.z += pr * xlA.z; acc.w += pr * xlA.w;
        }
        if (pB > m) {
            float scl = __expf(m - pB);
            den *= scl;
            acc.x *= scl; acc.y *= scl; acc.z *= scl; acc.w *= scl;
            m = pB;
        }
        {
            float pr = __expf(pB - m);
            den += pr;
            acc.x += pr * xlB.x; acc.y += pr * xlB.y;
            acc.z += pr * xlB.z; acc.w += pr * xlB.w;
        }
    }
    // ---- tail (deg odd): single-edge body ----
    for (; jj < deg; ++jj) {
        int src = g_srcl[base + jj];
        int e   = g_eidl[base + jj];
        const float4 xl4 = *(const float4*)(g_xl + (size_t)src * 128 + c0);
        const float4* eap = (const float4*)(edge_attr + (size_t)e * EDIM);
        float4 eA = __ldg(eap), eB = __ldg(eap + 1), eC = __ldg(eap + 2), eD = __ldg(eap + 3);
        float ev[16] = {eA.x, eA.y, eA.z, eA.w, eB.x, eB.y, eB.z, eB.w,
                        eC.x, eC.y, eC.z, eC.w, eD.x, eD.y, eD.z, eD.w};
        float mx = xl4.x + xr4.x, my = xl4.y + xr4.y;
        float mz = xl4.z + xr4.z, mw = xl4.w + xr4.w;
#pragma unroll
        for (int k = 0; k < EDIM; k++) {
            const float4 w = *(const float4*)&We_s[k * 128 + c0];
            mx += ev[k] * w.x; my += ev[k] * w.y; mz += ev[k] * w.z; mw += ev[k] * w.w;
        }
        mx = (mx > 0.f) ? mx : 0.2f * mx;
        my = (my > 0.f) ? my : 0.2f * my;
        mz = (mz > 0.f) ? mz : 0.2f * mz;
        mw = (mw > 0.f) ? mw : 0.2f * mw;
        float p = mx * ax + my * ay + mz * az + mw * aw;
#pragma unroll
        for (int o = 16; o; o >>= 1) p += __shfl_xor_sync(0xffffffffu, p, o);
        if (p > m) {
            float scl = __expf(m - p);
            den *= scl;
            acc.x *= scl; acc.y *= scl; acc.z *= scl; acc.w *= scl;
            m = p;
        }
        float pr = __expf(p - m);
        den += pr;
        acc.x += pr * xl4.x; acc.y += pr * xl4.y;
        acc.z += pr * xl4.z; acc.w += pr * xl4.w;
    }

    float inv = 1.f / den;
    // softmax(weight1)
    float a0 = weight1[0], a1 = weight1[1];
    float wm = fmaxf(a0, a1);
    float e0 = __expf(a0 - wm), e1 = __expf(a1 - wm);
    float is = 1.f / (e0 + e1);
    float w10 = e0 * is, w11 = e1 * is;

    const float4 xv = *(const float4*)(x + (size_t)i * 128 + c0);
    float4 o;
    o.x = w10 * xv.x + w11 * (acc.x * inv + bias_s[c0]);
    o.y = w10 * xv.y + w11 * (acc.y * inv + bias_s[c0 + 1]);
    o.z = w10 * xv.z + w11 * (acc.z * inv + bias_s[c0 + 2]);
    o.w = w10 * xv.w + w11 * (acc.w * inv + bias_s[c0 + 3]);
    *(float4*)(g_zpre + (size_t)i * 128 + c0) = o;

    // fused BN1 stats: block-level partials then one global flush
    atomicAdd(&red_s[c0 + 0], o.x); atomicAdd(&red_s[128 + c0 + 0], o.x * o.x);
    atomicAdd(&red_s[c0 + 1], o.y); atomicAdd(&red_s[128 + c0 + 1], o.y * o.y);
    atomicAdd(&red_s[c0 + 2], o.z); atomicAdd(&red_s[128 + c0 + 2], o.z * o.z);
    atomicAdd(&red_s[c0 + 3], o.w); atomicAdd(&red_s[128 + c0 + 3], o.w * o.w);
    __syncthreads();
    atomicAdd(&g_stats[tid], red_s[tid]);
}

__global__ void bn_finalize(const float* __restrict__ stats,
                            const float* __restrict__ gamma, const float* __restrict__ beta,
                            float* __restrict__ scale, float* __restrict__ shift)
{
    int c = threadIdx.x;
    float mu = stats[c] * (1.f / N_NODES);
    float var = stats[128 + c] * (1.f / N_NODES) - mu * mu;
    float rstd = rsqrtf(var + 1e-5f);
    float s = rstd * gamma[c];
    scale[c] = s;
    shift[c] = beta[c] - mu * s;
}

// ---------------- conv1d(k=3) as K=384 GEMM (FFMA2) + mix + fused BN2 stats ----------------
__global__ __launch_bounds__(256) void conv_kernel(const float* __restrict__ conv_b,
                                                   const float* __restrict__ weight2)
{
    __shared__ __align__(16) float zs[66][128];
    __shared__ __align__(16) float wt[16][128];
    __shared__ float sc_s[128], sh_s[128];
    __shared__ float red2[256];
    int tid = threadIdx.x;
    int row0 = blockIdx.x * 64;
    if (tid < 128) { sc_s[tid] = g_scale1[tid]; sh_s[tid] = g_shift1[tid]; }
    red2[tid] = 0.f;
    __syncthreads();

    // load + normalize input tile rows [row0-1, row0+64]; zero pad outside [0,N)
    for (int idx = tid; idx < 66 * 32; idx += 256) {
        int rr = idx >> 5, cg = idx & 31;
        int grow = row0 - 1 + rr;
        float4 v = make_float4(0.f, 0.f, 0.f, 0.f);
        if (grow >= 0 && grow < N_NODES) {
            float4 z = *(const float4*)(g_zpre + (size_t)grow * 128 + cg * 4);
            int c = cg * 4;
            v.x = z.x * sc_s[c] + sh_s[c];
            v.y = z.y * sc_s[c + 1] + sh_s[c + 1];
            v.z = z.z * sc_s[c + 2] + sh_s[c + 2];
            v.w = z.w * sc_s[c + 3] + sh_s[c + 3];
        }
        *(float4*)&zs[rr][cg * 4] = v;
    }

    int tcol = tid & 31, trow = tid >> 5;
    int c0 = tcol * 4, r0 = trow * 8;
    ull acc2[8][2];
#pragma unroll
    for (int r = 0; r < 8; r++) { acc2[r][0] = 0ull; acc2[r][1] = 0ull; }

    for (int t = 0; t < 3; t++) {
        for (int kc = 0; kc < 8; kc++) {
            __syncthreads();
#pragma unroll
            for (int it = 0; it < 2; it++) {
                int idx = tid + it * 256;
                int k = idx >> 5, cg = idx & 31;
                *(float4*)&wt[k][cg * 4] =
                    *(const float4*)(g_wext + (size_t)(t * 128 + kc * 16 + k) * 128 + cg * 4);
            }
            __syncthreads();
#pragma unroll
            for (int kk = 0; kk < 16; kk += 4) {
                float4 a4[8];
#pragma unroll
                for (int r = 0; r < 8; r++)
                    a4[r] = *(float4*)&zs[r0 + r + t][kc * 16 + kk];
#pragma unroll
                for (int q = 0; q < 4; q++) {
                    ulonglong2 w2 = *(const ulonglong2*)&wt[kk + q][c0];
#pragma unroll
                    for (int r = 0; r < 8; r++) {
                        float av = (q == 0) ? a4[r].x : (q == 1) ? a4[r].y
                                 : (q == 2) ? a4[r].z : a4[r].w;
                        ull ad = dup2(av);
                        fma2(acc2[r][0], ad, w2.x);
                        fma2(acc2[r][1], ad, w2.y);
                    }
                }
            }
        }
    }

    // softmax(weight2)
    float a0 = weight2[0], a1 = weight2[1];
    float wm = fmaxf(a0, a1);
    float e0 = __expf(a0 - wm), e1 = __expf(a1 - wm);
    float is = 1.f / (e0 + e1);
    float w20 = e0 * is, w21 = e1 * is;

    float4 b4 = *(const float4*)(conv_b + c0);
    float sst[4] = {0.f, 0.f, 0.f, 0.f};
    float qst[4] = {0.f, 0.f, 0.f, 0.f};
#pragma unroll
    for (int r = 0; r < 8; r++) {
        int grow = row0 + r0 + r;
        if (grow < N_NODES) {
            float2 u0 = u2f(acc2[r][0]), u1 = u2f(acc2[r][1]);
            float4 z1;
            z1.x = u0.x + b4.x; z1.y = u0.y + b4.y;
            z1.z = u1.x + b4.z; z1.w = u1.y + b4.w;
            z1.x = (z1.x > 0.f) ? z1.x : 0.01f * z1.x;
            z1.y = (z1.y > 0.f) ? z1.y : 0.01f * z1.y;
            z1.z = (z1.z > 0.f) ? z1.z : 0.01f * z1.z;
            z1.w = (z1.w > 0.f) ? z1.w : 0.01f * z1.w;
            float4 zn = *(float4*)&zs[r0 + r + 1][c0];
            float4 o;
            o.x = w20 * zn.x + w21 * z1.x;
            o.y = w20 * zn.y + w21 * z1.y;
            o.z = w20 * zn.z + w21 * z1.z;
            o.w = w20 * zn.w + w21 * z1.w;
            *(float4*)(g_z2 + (size_t)grow * 128 + c0) = o;
            sst[0] += o.x; qst[0] += o.x * o.x;
            sst[1] += o.y; qst[1] += o.y * o.y;
            sst[2] += o.z; qst[2] += o.z * o.z;
            sst[3] += o.w; qst[3] += o.w * o.w;
        }
    }
#pragma unroll
    for (int j = 0; j < 4; j++) {
        atomicAdd(&red2[c0 + j], sst[j]);
        atomicAdd(&red2[128 + c0 + j], qst[j]);
    }
    __syncthreads();
    atomicAdd(&g_stats[256 + tid], red2[tid]);
}

// ---------------- final BN2 apply ----------------
__global__ void final_apply(float* __restrict__ out) {
    int idx = blockIdx.x * blockDim.x + threadIdx.x;   // over N*32 float4 groups
    if (idx >= N_NODES * 32) return;
    int cg = idx & 31;
    int c = cg * 4;
    float4 z = *(const float4*)(g_z2 + (size_t)idx * 4);
    float4 o;
    o.x = z.x * g_scale2[c]     + g_shift2[c];
    o.y = z.y * g_scale2[c + 1] + g_shift2[c + 1];
    o.z = z.z * g_scale2[c + 2] + g_shift2[c + 2];
    o.w = z.w * g_scale2[c + 3] + g_shift2[c + 3];
    *(float4*)(out + (size_t)idx * 4) = o;
}

// ---------------- launch ----------------
extern "C" void kernel_launch(void* const* d_in, const int* in_sizes, int n_in,
                              void* d_out, int out_size)
{
    const float* x         = (const float*)d_in[0];
    const int*   ei        = (const int*)d_in[1];
    const float* edge_attr = (const float*)d_in[2];
    const float* W_l       = (const float*)d_in[3];
    const float* b_l       = (const float*)d_in[4];
    const float* W_r       = (const float*)d_in[5];
    const float* b_r       = (const float*)d_in[6];
    const float* W_e       = (const float*)d_in[7];
    const float* att       = (const float*)d_in[8];
    const float* bias_gat  = (const float*)d_in[9];
    const float* weight1   = (const float*)d_in[10];
    const float* bn1_gamma = (const float*)d_in[11];
    const float* bn1_beta  = (const float*)d_in[12];
    const float* conv_w    = (const float*)d_in[13];
    const float* conv_b    = (const float*)d_in[14];
    const float* weight2   = (const float*)d_in[15];
    const float* bn2_gamma = (const float*)d_in[16];
    const float* bn2_beta  = (const float*)d_in[17];
    float* out = (float*)d_out;

    float *p_xl, *p_xr, *p_stats, *p_sc1, *p_sh1, *p_sc2, *p_sh2;
    cudaGetSymbolAddress((void**)&p_xl, g_xl);
    cudaGetSymbolAddress((void**)&p_xr, g_xr);
    cudaGetSymbolAddress((void**)&p_stats, g_stats);
    cudaGetSymbolAddress((void**)&p_sc1, g_scale1);
    cudaGetSymbolAddress((void**)&p_sh1, g_shift1);
    cudaGetSymbolAddress((void**)&p_sc2, g_scale2);
    cudaGetSymbolAddress((void**)&p_sh2, g_shift2);

    zero_kernel<<<(N_NODES + 255) / 256, 256>>>();
    gemm128<<<(N_NODES + 63) / 64, 256>>>(x, W_l, b_l, p_xl, N_NODES);
    gemm128<<<(N_NODES + 63) / 64, 256>>>(x, W_r, b_r, p_xr, N_NODES);
    hist_kernel<<<(E_EDGES + 255) / 256, 256>>>(ei);
    base_kernel<<<(N_NODES + 255) / 256, 256>>>();
    scatter_kernel<<<(E_EDGES + 255) / 256, 256>>>(ei);
    prep_wext<<<(384 * 128 + 255) / 256, 256>>>(conv_w);
    attn_kernel<<<N_NODES / 8, 256>>>(x, edge_attr, W_e, att, bias_gat, weight1);
    bn_finalize<<<1, 128>>>(p_stats, bn1_gamma, bn1_beta, p_sc1, p_sh1);
    conv_kernel<<<(N_NODES + 63) / 64, 256>>>(conv_b, weight2);
    bn_finalize<<<1, 128>>>(p_stats + 256, bn2_gamma, bn2_beta, p_sc2, p_sh2);
    final_apply<<<(N_NODES * 32 + 255) / 256, 256>>>(out);
}

// round 10
// speedup vs baseline: 1.7453x; 1.0078x over previous
#include <cuda_runtime.h>

#define N_NODES 50000
#define E_EDGES 800000
#define DCH     128
#define EDIM    16

typedef unsigned long long ull;

// ---------------- packed f32x2 helpers (sm_103a FFMA2) ----------------
__device__ __forceinline__ void fma2(ull &d, ull a, ull b) {
    asm("fma.rn.f32x2 %0, %1, %2, %0;" : "+l"(d) : "l"(a), "l"(b));
}
__device__ __forceinline__ ull dup2(float a) {
    ull r; asm("mov.b64 %0, {%1, %1};" : "=l"(r) : "f"(a)); return r;
}
__device__ __forceinline__ ull pack2(float a, float b) {
    ull r; asm("mov.b64 %0, {%1, %2};" : "=l"(r) : "f"(a), "f"(b)); return r;
}
__device__ __forceinline__ float2 u2f(ull v) {
    float2 f; asm("mov.b64 {%0, %1}, %2;" : "=f"(f.x), "=f"(f.y) : "l"(v)); return f;
}

// ---------------- device scratch (no allocs allowed) ----------------
__device__ float g_xl[N_NODES * DCH];
__device__ float g_xr[N_NODES * DCH];
__device__ float g_zpre[N_NODES * DCH];
__device__ float g_z2[N_NODES * DCH];
__device__ float g_wext[384 * DCH];
__device__ int   g_deg[N_NODES];
__device__ int   g_cur[N_NODES];
__device__ int   g_off[N_NODES];
__device__ int   g_srcl[E_EDGES];
__device__ int   g_eidl[E_EDGES];
__device__ int   g_cnt;
__device__ float g_stats[512];              // [0..255] bn1 (sum,sumsq), [256..511] bn2
__device__ float g_scale1[DCH], g_shift1[DCH];
__device__ float g_scale2[DCH], g_shift2[DCH];

// ---------------- zero scratch ----------------
__global__ void zero_kernel() {
    int idx = blockIdx.x * blockDim.x + threadIdx.x;
    if (idx < N_NODES) { g_deg[idx] = 0; g_cur[idx] = 0; }
    if (idx < 512) g_stats[idx] = 0.f;
    if (idx == 0) g_cnt = 0;
}

// ---------------- dual GEMM: xl = x@Wl + bl, xr = x@Wr + br in one pass ----------------
__global__ __launch_bounds__(256) void gemm_dual(
    const float* __restrict__ A,
    const float* __restrict__ Wl, const float* __restrict__ bl,
    const float* __restrict__ Wr, const float* __restrict__ br,
    float* __restrict__ Cl, float* __restrict__ Cr, int nrows)
{
    __shared__ __align__(16) float as[16][64];
    __shared__ __align__(16) float wsL[16][128];
    __shared__ __align__(16) float wsR[16][128];
    int tid = threadIdx.x;
    int row0 = blockIdx.x * 64;
    int tcol = tid & 31, trow = tid >> 5;
    int c0 = tcol * 4, r0 = trow * 8;
    ull accL[8][2], accR[8][2];
#pragma unroll
    for (int r = 0; r < 8; r++) {
        accL[r][0] = 0ull; accL[r][1] = 0ull;
        accR[r][0] = 0ull; accR[r][1] = 0ull;
    }

    int lr = tid & 63, lkg = tid >> 6;
    for (int kb = 0; kb < 128; kb += 16) {
        float4 v = make_float4(0.f, 0.f, 0.f, 0.f);
        int grow = row0 + lr;
        if (grow < nrows) v = *(const float4*)(A + (size_t)grow * 128 + kb + lkg * 4);
        as[lkg * 4 + 0][lr] = v.x; as[lkg * 4 + 1][lr] = v.y;
        as[lkg * 4 + 2][lr] = v.z; as[lkg * 4 + 3][lr] = v.w;
#pragma unroll
        for (int it = 0; it < 2; it++) {
            int idx = tid + it * 256;
            int k = idx >> 5, cg = idx & 31;
            *(float4*)&wsL[k][cg * 4] = *(const float4*)(Wl + (size_t)(kb + k) * 128 + cg * 4);
            *(float4*)&wsR[k][cg * 4] = *(const float4*)(Wr + (size_t)(kb + k) * 128 + cg * 4);
        }
        __syncthreads();
#pragma unroll
        for (int k = 0; k < 16; k++) {
            ulonglong2 wL = *(const ulonglong2*)&wsL[k][c0];
            ulonglong2 wR = *(const ulonglong2*)&wsR[k][c0];
            float4 alo = *(const float4*)&as[k][r0];
            float4 ahi = *(const float4*)&as[k][r0 + 4];
            float a[8] = {alo.x, alo.y, alo.z, alo.w, ahi.x, ahi.y, ahi.z, ahi.w};
#pragma unroll
            for (int r = 0; r < 8; r++) {
                ull ad = dup2(a[r]);
                fma2(accL[r][0], ad, wL.x);
                fma2(accL[r][1], ad, wL.y);
                fma2(accR[r][0], ad, wR.x);
                fma2(accR[r][1], ad, wR.y);
            }
        }
        __syncthreads();
    }
    float4 bl4 = *(const float4*)(bl + c0);
    float4 br4 = *(const float4*)(br + c0);
#pragma unroll
    for (int r = 0; r < 8; r++) {
        int grow = row0 + r0 + r;
        if (grow < nrows) {
            float2 l0 = u2f(accL[r][0]), l1 = u2f(accL[r][1]);
            float2 r0v = u2f(accR[r][0]), r1v = u2f(accR[r][1]);
            float4 ol, orr;
            ol.x = l0.x + bl4.x;  ol.y = l0.y + bl4.y;
            ol.z = l1.x + bl4.z;  ol.w = l1.y + bl4.w;
            orr.x = r0v.x + br4.x; orr.y = r0v.y + br4.y;
            orr.z = r1v.x + br4.z; orr.w = r1v.y + br4.w;
            *(float4*)(Cl + (size_t)grow * 128 + c0) = ol;
            *(float4*)(Cr + (size_t)grow * 128 + c0) = orr;
        }
    }
}

// ---------------- CSR build (no self loops; atomic segment bases) ----------------
__global__ void hist_kernel(const int* __restrict__ ei) {
    int t = blockIdx.x * blockDim.x + threadIdx.x;
    if (t >= E_EDGES) return;
    atomicAdd(&g_deg[ei[E_EDGES + t]], 1);
}

__global__ void base_kernel() {
    int idx = blockIdx.x * blockDim.x + threadIdx.x;
    if (idx < N_NODES) g_off[idx] = atomicAdd(&g_cnt, g_deg[idx]);
}

__global__ void scatter_kernel(const int* __restrict__ ei) {
    int t = blockIdx.x * blockDim.x + threadIdx.x;
    if (t >= E_EDGES) return;
    int dst = ei[E_EDGES + t];
    int pos = atomicAdd(&g_cur[dst], 1);
    int o = g_off[dst] + pos;
    g_srcl[o] = ei[t];
    g_eidl[o] = t;
}

// ---------------- conv weight transpose: wext[(t*128+cin)*128 + cout] ----------------
__global__ void prep_wext(const float* __restrict__ conv_w) {
    int idx = blockIdx.x * blockDim.x + threadIdx.x;
    if (idx >= 384 * 128) return;
    int kext = idx >> 7, cout = idx & 127;
    int t = kext >> 7, cin = kext & 127;
    g_wext[idx] = conv_w[cout * 384 + cin * 3 + t];
}

// ---------------- fused attention: warp/node, online softmax, 2-edge batch + FFMA2 ----------------
__global__ __launch_bounds__(256) void attn_kernel(
    const float* __restrict__ x,
    const float* __restrict__ edge_attr, const float* __restrict__ W_e,
    const float* __restrict__ att, const float* __restrict__ bias_gat,
    const float* __restrict__ weight1)
{
    __shared__ __align__(16) float We_s[2048];
    __shared__ float att_s[128];
    __shared__ float bias_s[128];
    __shared__ float red_s[256];
    int tid = threadIdx.x;
    for (int idx = tid; idx < 2048; idx += 256) We_s[idx] = W_e[idx];
    if (tid < 128) { att_s[tid] = att[tid]; bias_s[tid] = bias_gat[tid]; }
    red_s[tid] = 0.f;
    __syncthreads();

    int i = blockIdx.x * 8 + (tid >> 5);   // grid = 6250 -> exactly 50000 nodes
    int lane = tid & 31;
    int c0 = lane * 4;
    int base = g_off[i];
    int deg = g_deg[i];

    const float4 xr4 = *(const float4*)(g_xr + (size_t)i * 128 + c0);
    const float4 xli = *(const float4*)(g_xl + (size_t)i * 128 + c0);
    float ax = att_s[c0], ay = att_s[c0 + 1], az = att_s[c0 + 2], aw = att_s[c0 + 3];

    // self loop handled analytically: message = leaky(xl_i + xr_i), no edge term
    float sx = xli.x + xr4.x, sy = xli.y + xr4.y;
    float sz = xli.z + xr4.z, sw = xli.w + xr4.w;
    sx = (sx > 0.f) ? sx : 0.2f * sx; sy = (sy > 0.f) ? sy : 0.2f * sy;
    sz = (sz > 0.f) ? sz : 0.2f * sz; sw = (sw > 0.f) ? sw : 0.2f * sw;
    float part = sx * ax + sy * ay + sz * az + sw * aw;
#pragma unroll
    for (int o = 16; o; o >>= 1) part += __shfl_xor_sync(0xffffffffu, part, o);
    float m = part, den = 1.f;
    float4 acc = xli;

    int jj = 0;
    // ---- 2-edge batched mainloop: one We_s read serves both edges ----
    for (; jj + 2 <= deg; jj += 2) {
        int s0 = g_srcl[base + jj],     s1 = g_srcl[base + jj + 1];
        int e0 = g_eidl[base + jj],     e1 = g_eidl[base + jj + 1];
        const float4 xlA = *(const float4*)(g_xl + (size_t)s0 * 128 + c0);
        const float4 xlB = *(const float4*)(g_xl + (size_t)s1 * 128 + c0);
        const float4* epA = (const float4*)(edge_attr + (size_t)e0 * EDIM);
        const float4* epB = (const float4*)(edge_attr + (size_t)e1 * EDIM);
        float4 aA = __ldg(epA), aB = __ldg(epA + 1), aC = __ldg(epA + 2), aD = __ldg(epA + 3);
        float4 bA = __ldg(epB), bB = __ldg(epB + 1), bC = __ldg(epB + 2), bD = __ldg(epB + 3);
        float evA[16] = {aA.x, aA.y, aA.z, aA.w, aB.x, aB.y, aB.z, aB.w,
                         aC.x, aC.y, aC.z, aC.w, aD.x, aD.y, aD.z, aD.w};
        float evB[16] = {bA.x, bA.y, bA.z, bA.w, bB.x, bB.y, bB.z, bB.w,
                         bC.x, bC.y, bC.z, bC.w, bD.x, bD.y, bD.z, bD.w};

        ull a01 = pack2(xlA.x + xr4.x, xlA.y + xr4.y);
        ull a23 = pack2(xlA.z + xr4.z, xlA.w + xr4.w);
        ull b01 = pack2(xlB.x + xr4.x, xlB.y + xr4.y);
        ull b23 = pack2(xlB.z + xr4.z, xlB.w + xr4.w);
#pragma unroll
        for (int k = 0; k < EDIM; k++) {
            ulonglong2 w = *(const ulonglong2*)&We_s[k * 128 + c0];
            ull dA = dup2(evA[k]);
            ull dB = dup2(evB[k]);
            fma2(a01, dA, w.x); fma2(a23, dA, w.y);
            fma2(b01, dB, w.x); fma2(b23, dB, w.y);
        }
        float2 pA01 = u2f(a01), pA23 = u2f(a23);
        float2 pB01 = u2f(b01), pB23 = u2f(b23);
        float mxA = pA01.x, myA = pA01.y, mzA = pA23.x, mwA = pA23.y;
        float mxB = pB01.x, myB = pB01.y, mzB = pB23.x, mwB = pB23.y;
        mxA = (mxA > 0.f) ? mxA : 0.2f * mxA;  myA = (myA > 0.f) ? myA : 0.2f * myA;
        mzA = (mzA > 0.f) ? mzA : 0.2f * mzA;  mwA = (mwA > 0.f) ? mwA : 0.2f * mwA;
        mxB = (mxB > 0.f) ? mxB : 0.2f * mxB;  myB = (myB > 0.f) ? myB : 0.2f * myB;
        mzB = (mzB > 0.f) ? mzB : 0.2f * mzB;  mwB = (mwB > 0.f) ? mwB : 0.2f * mwB;
        float pA = mxA * ax + myA * ay + mzA * az + mwA * aw;
        float pB = mxB * ax + myB * ay + mzB * az + mwB * aw;
#pragma unroll
        for (int o = 16; o; o >>= 1) {
            pA += __shfl_xor_sync(0xffffffffu, pA, o);
            pB += __shfl_xor_sync(0xffffffffu, pB, o);
        }
        // sequential online-softmax updates (warp-uniform branches)
        if (pA > m) {
            float scl = __expf(m - pA);
            den *= scl;
            acc.x *= scl; acc.y *= scl; acc.z *= scl; acc.w *= scl;
            m = pA;
        }
        {
            float pr = __expf(pA - m);
            den += pr;
            acc.x += pr * xlA.x; acc.y += pr * xlA.y;
            acc.z += pr * xlA.z; acc.w += pr * xlA.w;
        }
        if (pB > m) {
            float scl = __expf(m - pB);
            den *= scl;
            acc.x *= scl; acc.y *= scl; acc.z *= scl; acc.w *= scl;
            m = pB;
        }
        {
            float pr = __expf(pB - m);
            den += pr;
            acc.x += pr * xlB.x; acc.y += pr * xlB.y;
            acc.z += pr * xlB.z; acc.w += pr * xlB.w;
        }
    }
    // ---- tail (deg odd): single-edge body ----
    for (; jj < deg; ++jj) {
        int src = g_srcl[base + jj];
        int e   = g_eidl[base + jj];
        const float4 xl4 = *(const float4*)(g_xl + (size_t)src * 128 + c0);
        const float4* eap = (const float4*)(edge_attr + (size_t)e * EDIM);
        float4 eA = __ldg(eap), eB = __ldg(eap + 1), eC = __ldg(eap + 2), eD = __ldg(eap + 3);
        float ev[16] = {eA.x, eA.y, eA.z, eA.w, eB.x, eB.y, eB.z, eB.w,
                        eC.x, eC.y, eC.z, eC.w, eD.x, eD.y, eD.z, eD.w};
        float mx = xl4.x + xr4.x, my = xl4.y + xr4.y;
        float mz = xl4.z + xr4.z, mw = xl4.w + xr4.w;
#pragma unroll
        for (int k = 0; k < EDIM; k++) {
            const float4 w = *(const float4*)&We_s[k * 128 + c0];
            mx += ev[k] * w.x; my += ev[k] * w.y; mz += ev[k] * w.z; mw += ev[k] * w.w;
        }
        mx = (mx > 0.f) ? mx : 0.2f * mx;
        my = (my > 0.f) ? my : 0.2f * my;
        mz = (mz > 0.f) ? mz : 0.2f * mz;
        mw = (mw > 0.f) ? mw : 0.2f * mw;
        float p = mx * ax + my * ay + mz * az + mw * aw;
#pragma unroll
        for (int o = 16; o; o >>= 1) p += __shfl_xor_sync(0xffffffffu, p, o);
        if (p > m) {
            float scl = __expf(m - p);
            den *= scl;
            acc.x *= scl; acc.y *= scl; acc.z *= scl; acc.w *= scl;
            m = p;
        }
        float pr = __expf(p - m);
        den += pr;
        acc.x += pr * xl4.x; acc.y += pr * xl4.y;
        acc.z += pr * xl4.z; acc.w += pr * xl4.w;
    }

    float inv = 1.f / den;
    // softmax(weight1)
    float a0 = weight1[0], a1 = weight1[1];
    float wm = fmaxf(a0, a1);
    float e0 = __expf(a0 - wm), e1 = __expf(a1 - wm);
    float is = 1.f / (e0 + e1);
    float w10 = e0 * is, w11 = e1 * is;

    const float4 xv = *(const float4*)(x + (size_t)i * 128 + c0);
    float4 o;
    o.x = w10 * xv.x + w11 * (acc.x * inv + bias_s[c0]);
    o.y = w10 * xv.y + w11 * (acc.y * inv + bias_s[c0 + 1]);
    o.z = w10 * xv.z + w11 * (acc.z * inv + bias_s[c0 + 2]);
    o.w = w10 * xv.w + w11 * (acc.w * inv + bias_s[c0 + 3]);
    *(float4*)(g_zpre + (size_t)i * 128 + c0) = o;

    // fused BN1 stats: block-level partials then one global flush
    atomicAdd(&red_s[c0 + 0], o.x); atomicAdd(&red_s[128 + c0 + 0], o.x * o.x);
    atomicAdd(&red_s[c0 + 1], o.y); atomicAdd(&red_s[128 + c0 + 1], o.y * o.y);
    atomicAdd(&red_s[c0 + 2], o.z); atomicAdd(&red_s[128 + c0 + 2], o.z * o.z);
    atomicAdd(&red_s[c0 + 3], o.w); atomicAdd(&red_s[128 + c0 + 3], o.w * o.w);
    __syncthreads();
    atomicAdd(&g_stats[tid], red_s[tid]);
}

__global__ void bn_finalize(const float* __restrict__ stats,
                            const float* __restrict__ gamma, const float* __restrict__ beta,
                            float* __restrict__ scale, float* __restrict__ shift)
{
    int c = threadIdx.x;
    float mu = stats[c] * (1.f / N_NODES);
    float var = stats[128 + c] * (1.f / N_NODES) - mu * mu;
    float rstd = rsqrtf(var + 1e-5f);
    float s = rstd * gamma[c];
    scale[c] = s;
    shift[c] = beta[c] - mu * s;
}

// ---------------- conv1d(k=3) as K=384 GEMM (FFMA2) + mix + fused BN2 stats ----------------
__global__ __launch_bounds__(256) void conv_kernel(const float* __restrict__ conv_b,
                                                   const float* __restrict__ weight2)
{
    __shared__ __align__(16) float zs[66][128];
    __shared__ __align__(16) float wt[16][128];
    __shared__ float sc_s[128], sh_s[128];
    __shared__ float red2[256];
    int tid = threadIdx.x;
    int row0 = blockIdx.x * 64;
    if (tid < 128) { sc_s[tid] = g_scale1[tid]; sh_s[tid] = g_shift1[tid]; }
    red2[tid] = 0.f;
    __syncthreads();

    // load + normalize input tile rows [row0-1, row0+64]; zero pad outside [0,N)
    for (int idx = tid; idx < 66 * 32; idx += 256) {
        int rr = idx >> 5, cg = idx & 31;
        int grow = row0 - 1 + rr;
        float4 v = make_float4(0.f, 0.f, 0.f, 0.f);
        if (grow >= 0 && grow < N_NODES) {
            float4 z = *(const float4*)(g_zpre + (size_t)grow * 128 + cg * 4);
            int c = cg * 4;
            v.x = z.x * sc_s[c] + sh_s[c];
            v.y = z.y * sc_s[c + 1] + sh_s[c + 1];
            v.z = z.z * sc_s[c + 2] + sh_s[c + 2];
            v.w = z.w * sc_s[c + 3] + sh_s[c + 3];
        }
        *(float4*)&zs[rr][cg * 4] = v;
    }

    int tcol = tid & 31, trow = tid >> 5;
    int c0 = tcol * 4, r0 = trow * 8;
    ull acc2[8][2];
#pragma unroll
    for (int r = 0; r < 8; r++) { acc2[r][0] = 0ull; acc2[r][1] = 0ull; }

    for (int t = 0; t < 3; t++) {
        for (int kc = 0; kc < 8; kc++) {
            __syncthreads();
#pragma unroll
            for (int it = 0; it < 2; it++) {
                int idx = tid + it * 256;
                int k = idx >> 5, cg = idx & 31;
                *(float4*)&wt[k][cg * 4] =
                    *(const float4*)(g_wext + (size_t)(t * 128 + kc * 16 + k) * 128 + cg * 4);
            }
            __syncthreads();
#pragma unroll
            for (int kk = 0; kk < 16; kk += 4) {
                float4 a4[8];
#pragma unroll
                for (int r = 0; r < 8; r++)
                    a4[r] = *(float4*)&zs[r0 + r + t][kc * 16 + kk];
#pragma unroll
                for (int q = 0; q < 4; q++) {
                    ulonglong2 w2 = *(const ulonglong2*)&wt[kk + q][c0];
#pragma unroll
                    for (int r = 0; r < 8; r++) {
                        float av = (q == 0) ? a4[r].x : (q == 1) ? a4[r].y
                                 : (q == 2) ? a4[r].z : a4[r].w;
                        ull ad = dup2(av);
                        fma2(acc2[r][0], ad, w2.x);
                        fma2(acc2[r][1], ad, w2.y);
                    }
                }
            }
        }
    }

    // softmax(weight2)
    float a0 = weight2[0], a1 = weight2[1];
    float wm = fmaxf(a0, a1);
    float e0 = __expf(a0 - wm), e1 = __expf(a1 - wm);
    float is = 1.f / (e0 + e1);
    float w20 = e0 * is, w21 = e1 * is;

    float4 b4 = *(const float4*)(conv_b + c0);
    float sst[4] = {0.f, 0.f, 0.f, 0.f};
    float qst[4] = {0.f, 0.f, 0.f, 0.f};
#pragma unroll
    for (int r = 0; r < 8; r++) {
        int grow = row0 + r0 + r;
        if (grow < N_NODES) {
            float2 u0 = u2f(acc2[r][0]), u1 = u2f(acc2[r][1]);
            float4 z1;
            z1.x = u0.x + b4.x; z1.y = u0.y + b4.y;
            z1.z = u1.x + b4.z; z1.w = u1.y + b4.w;
            z1.x = (z1.x > 0.f) ? z1.x : 0.01f * z1.x;
            z1.y = (z1.y > 0.f) ? z1.y : 0.01f * z1.y;
            z1.z = (z1.z > 0.f) ? z1.z : 0.01f * z1.z;
            z1.w = (z1.w > 0.f) ? z1.w : 0.01f * z1.w;
            float4 zn = *(float4*)&zs[r0 + r + 1][c0];
            float4 o;
            o.x = w20 * zn.x + w21 * z1.x;
            o.y = w20 * zn.y + w21 * z1.y;
            o.z = w20 * zn.z + w21 * z1.z;
            o.w = w20 * zn.w + w21 * z1.w;
            *(float4*)(g_z2 + (size_t)grow * 128 + c0) = o;
            sst[0] += o.x; qst[0] += o.x * o.x;
            sst[1] += o.y; qst[1] += o.y * o.y;
            sst[2] += o.z; qst[2] += o.z * o.z;
            sst[3] += o.w; qst[3] += o.w * o.w;
        }
    }
#pragma unroll
    for (int j = 0; j < 4; j++) {
        atomicAdd(&red2[c0 + j], sst[j]);
        atomicAdd(&red2[128 + c0 + j], qst[j]);
    }
    __syncthreads();
    atomicAdd(&g_stats[256 + tid], red2[tid]);
}

// ---------------- final BN2 apply ----------------
__global__ void final_apply(float* __restrict__ out) {
    int idx = blockIdx.x * blockDim.x + threadIdx.x;   // over N*32 float4 groups
    if (idx >= N_NODES * 32) return;
    int cg = idx & 31;
    int c = cg * 4;
    float4 z = *(const float4*)(g_z2 + (size_t)idx * 4);
    float4 o;
    o.x = z.x * g_scale2[c]     + g_shift2[c];
    o.y = z.y * g_scale2[c + 1] + g_shift2[c + 1];
    o.z = z.z * g_scale2[c + 2] + g_shift2[c + 2];
    o.w = z.w * g_scale2[c + 3] + g_shift2[c + 3];
    *(float4*)(out + (size_t)idx * 4) = o;
}

// ---------------- launch ----------------
extern "C" void kernel_launch(void* const* d_in, const int* in_sizes, int n_in,
                              void* d_out, int out_size)
{
    const float* x         = (const float*)d_in[0];
    const int*   ei        = (const int*)d_in[1];
    const float* edge_attr = (const float*)d_in[2];
    const float* W_l       = (const float*)d_in[3];
    const float* b_l       = (const float*)d_in[4];
    const float* W_r       = (const float*)d_in[5];
    const float* b_r       = (const float*)d_in[6];
    const float* W_e       = (const float*)d_in[7];
    const float* att       = (const float*)d_in[8];
    const float* bias_gat  = (const float*)d_in[9];
    const float* weight1   = (const float*)d_in[10];
    const float* bn1_gamma = (const float*)d_in[11];
    const float* bn1_beta  = (const float*)d_in[12];
    const float* conv_w    = (const float*)d_in[13];
    const float* conv_b    = (const float*)d_in[14];
    const float* weight2   = (const float*)d_in[15];
    const float* bn2_gamma = (const float*)d_in[16];
    const float* bn2_beta  = (const float*)d_in[17];
    float* out = (float*)d_out;

    float *p_xl, *p_xr, *p_stats, *p_sc1, *p_sh1, *p_sc2, *p_sh2;
    cudaGetSymbolAddress((void**)&p_xl, g_xl);
    cudaGetSymbolAddress((void**)&p_xr, g_xr);
    cudaGetSymbolAddress((void**)&p_stats, g_stats);
    cudaGetSymbolAddress((void**)&p_sc1, g_scale1);
    cudaGetSymbolAddress((void**)&p_sh1, g_shift1);
    cudaGetSymbolAddress((void**)&p_sc2, g_scale2);
    cudaGetSymbolAddress((void**)&p_sh2, g_shift2);

    // order chosen so the ncu-profiled 4th launch is gemm_dual (the hot GEMM)
    zero_kernel<<<(N_NODES + 255) / 256, 256>>>();
    hist_kernel<<<(E_EDGES + 255) / 256, 256>>>(ei);
    base_kernel<<<(N_NODES + 255) / 256, 256>>>();
    gemm_dual<<<(N_NODES + 63) / 64, 256>>>(x, W_l, b_l, W_r, b_r, p_xl, p_xr, N_NODES);
    scatter_kernel<<<(E_EDGES + 255) / 256, 256>>>(ei);
    prep_wext<<<(384 * 128 + 255) / 256, 256>>>(conv_w);
    attn_kernel<<<N_NODES / 8, 256>>>(x, edge_attr, W_e, att, bias_gat, weight1);
    bn_finalize<<<1, 128>>>(p_stats, bn1_gamma, bn1_beta, p_sc1, p_sh1);
    conv_kernel<<<(N_NODES + 63) / 64, 256>>>(conv_b, weight2);
    bn_finalize<<<1, 128>>>(p_stats + 256, bn2_gamma, bn2_beta, p_sc2, p_sh2);
    final_apply<<<(N_NODES * 32 + 255) / 256, 256>>>(out);
}

// round 11
// speedup vs baseline: 1.7510x; 1.0033x over previous
#include <cuda_runtime.h>

#define N_NODES 50000
#define E_EDGES 800000
#define DCH     128
#define EDIM    16

typedef unsigned long long ull;

// ---------------- packed f32x2 helpers (sm_103a FFMA2) ----------------
__device__ __forceinline__ void fma2(ull &d, ull a, ull b) {
    asm("fma.rn.f32x2 %0, %1, %2, %0;" : "+l"(d) : "l"(a), "l"(b));
}
__device__ __forceinline__ ull dup2(float a) {
    ull r; asm("mov.b64 %0, {%1, %1};" : "=l"(r) : "f"(a)); return r;
}
__device__ __forceinline__ ull pack2(float a, float b) {
    ull r; asm("mov.b64 %0, {%1, %2};" : "=l"(r) : "f"(a), "f"(b)); return r;
}
__device__ __forceinline__ float2 u2f(ull v) {
    float2 f; asm("mov.b64 {%0, %1}, %2;" : "=f"(f.x), "=f"(f.y) : "l"(v)); return f;
}

// ---------------- cp.async helpers ----------------
__device__ __forceinline__ unsigned s2u(const void* p) {
    unsigned a;
    asm("{ .reg .u64 t; cvta.to.shared.u64 t, %1; cvt.u32.u64 %0, t; }" : "=r"(a) : "l"(p));
    return a;
}
__device__ __forceinline__ void cpa16(unsigned d, const void* s) {
    asm volatile("cp.async.cg.shared.global [%0], [%1], 16;" :: "r"(d), "l"(s));
}
#define CP_COMMIT() asm volatile("cp.async.commit_group;" ::: "memory")
#define CP_WAIT0()  asm volatile("cp.async.wait_group 0;" ::: "memory")

// ---------------- device scratch (no allocs allowed) ----------------
__device__ float g_xl[N_NODES * DCH];
__device__ float g_xr[N_NODES * DCH];
__device__ float g_zpre[N_NODES * DCH];
__device__ float g_z2[N_NODES * DCH];
__device__ float g_wext[384 * DCH];
__device__ int   g_deg[N_NODES];
__device__ int   g_cur[N_NODES];
__device__ int   g_off[N_NODES];
__device__ int   g_srcl[E_EDGES];
__device__ int   g_eidl[E_EDGES];
__device__ int   g_cnt;
__device__ float g_stats[512];              // [0..255] bn1 (sum,sumsq), [256..511] bn2
__device__ float g_scale1[DCH], g_shift1[DCH];
__device__ float g_scale2[DCH], g_shift2[DCH];

// ---------------- zero scratch ----------------
__global__ void zero_kernel() {
    int idx = blockIdx.x * blockDim.x + threadIdx.x;
    if (idx < N_NODES) { g_deg[idx] = 0; g_cur[idx] = 0; }
    if (idx < 512) g_stats[idx] = 0.f;
    if (idx == 0) g_cnt = 0;
}

// ---------------- dual GEMM, cp.async double-buffered ----------------
__global__ __launch_bounds__(256, 2) void gemm_dual(
    const float* __restrict__ A,
    const float* __restrict__ Wl, const float* __restrict__ bl,
    const float* __restrict__ Wr, const float* __restrict__ br,
    float* __restrict__ Cl, float* __restrict__ Cr, int nrows)
{
    __shared__ __align__(16) float as[2][16][64];
    __shared__ __align__(16) float wsL[2][16][128];
    __shared__ __align__(16) float wsR[2][16][128];
    int tid = threadIdx.x;
    int row0 = blockIdx.x * 64;
    int tcol = tid & 31, trow = tid >> 5;
    int c0 = tcol * 4, r0 = trow * 8;
    ull accL[8][2], accR[8][2];
#pragma unroll
    for (int r = 0; r < 8; r++) {
        accL[r][0] = 0ull; accL[r][1] = 0ull;
        accR[r][0] = 0ull; accR[r][1] = 0ull;
    }

    // loader indices
    int lr = tid & 63, lkg = tid >> 6;           // A tile: row lr, k-group lkg
    int wk0 = tid >> 5,        wcg = tid & 31;   // W tile chunk 1 (k 0..7)
    int wk1 = (tid + 256) >> 5;                  // W tile chunk 2 (k 8..15)
    int grow = row0 + lr;
    bool rowok = (grow < nrows);

    // prolog: stage kb=0 weights via cp.async; x tile via register
    cpa16(s2u(&wsL[0][wk0][wcg * 4]), Wl + (size_t)wk0 * 128 + wcg * 4);
    cpa16(s2u(&wsL[0][wk1][wcg * 4]), Wl + (size_t)wk1 * 128 + wcg * 4);
    cpa16(s2u(&wsR[0][wk0][wcg * 4]), Wr + (size_t)wk0 * 128 + wcg * 4);
    cpa16(s2u(&wsR[0][wk1][wcg * 4]), Wr + (size_t)wk1 * 128 + wcg * 4);
    CP_COMMIT();
    float4 vx = make_float4(0.f, 0.f, 0.f, 0.f);
    if (rowok) vx = *(const float4*)(A + (size_t)grow * 128 + lkg * 4);

#pragma unroll 1
    for (int kbi = 0; kbi < 8; kbi++) {
        int buf = kbi & 1;
        CP_WAIT0();
        as[buf][lkg * 4 + 0][lr] = vx.x; as[buf][lkg * 4 + 1][lr] = vx.y;
        as[buf][lkg * 4 + 2][lr] = vx.z; as[buf][lkg * 4 + 3][lr] = vx.w;
        __syncthreads();
        if (kbi < 7) {
            int kb = (kbi + 1) * 16;
            cpa16(s2u(&wsL[buf ^ 1][wk0][wcg * 4]), Wl + (size_t)(kb + wk0) * 128 + wcg * 4);
            cpa16(s2u(&wsL[buf ^ 1][wk1][wcg * 4]), Wl + (size_t)(kb + wk1) * 128 + wcg * 4);
            cpa16(s2u(&wsR[buf ^ 1][wk0][wcg * 4]), Wr + (size_t)(kb + wk0) * 128 + wcg * 4);
            cpa16(s2u(&wsR[buf ^ 1][wk1][wcg * 4]), Wr + (size_t)(kb + wk1) * 128 + wcg * 4);
            CP_COMMIT();
            if (rowok) vx = *(const float4*)(A + (size_t)grow * 128 + kb + lkg * 4);
        }
#pragma unroll
        for (int k = 0; k < 16; k++) {
            ulonglong2 wL = *(const ulonglong2*)&wsL[buf][k][c0];
            ulonglong2 wR = *(const ulonglong2*)&wsR[buf][k][c0];
            float4 alo = *(const float4*)&as[buf][k][r0];
            float4 ahi = *(const float4*)&as[buf][k][r0 + 4];
            float a[8] = {alo.x, alo.y, alo.z, alo.w, ahi.x, ahi.y, ahi.z, ahi.w};
#pragma unroll
            for (int r = 0; r < 8; r++) {
                ull ad = dup2(a[r]);
                fma2(accL[r][0], ad, wL.x);
                fma2(accL[r][1], ad, wL.y);
                fma2(accR[r][0], ad, wR.x);
                fma2(accR[r][1], ad, wR.y);
            }
        }
    }
    float4 bl4 = *(const float4*)(bl + c0);
    float4 br4 = *(const float4*)(br + c0);
#pragma unroll
    for (int r = 0; r < 8; r++) {
        int gw = row0 + r0 + r;
        if (gw < nrows) {
            float2 l0 = u2f(accL[r][0]), l1 = u2f(accL[r][1]);
            float2 r0v = u2f(accR[r][0]), r1v = u2f(accR[r][1]);
            float4 ol, orr;
            ol.x = l0.x + bl4.x;  ol.y = l0.y + bl4.y;
            ol.z = l1.x + bl4.z;  ol.w = l1.y + bl4.w;
            orr.x = r0v.x + br4.x; orr.y = r0v.y + br4.y;
            orr.z = r1v.x + br4.z; orr.w = r1v.y + br4.w;
            *(float4*)(Cl + (size_t)gw * 128 + c0) = ol;
            *(float4*)(Cr + (size_t)gw * 128 + c0) = orr;
        }
    }
}

// ---------------- CSR build (no self loops; atomic segment bases) ----------------
__global__ void hist_kernel(const int* __restrict__ ei) {
    int t = blockIdx.x * blockDim.x + threadIdx.x;
    if (t >= E_EDGES) return;
    atomicAdd(&g_deg[ei[E_EDGES + t]], 1);
}

__global__ void base_kernel() {
    int idx = blockIdx.x * blockDim.x + threadIdx.x;
    if (idx < N_NODES) g_off[idx] = atomicAdd(&g_cnt, g_deg[idx]);
}

__global__ void scatter_kernel(const int* __restrict__ ei) {
    int t = blockIdx.x * blockDim.x + threadIdx.x;
    if (t >= E_EDGES) return;
    int dst = ei[E_EDGES + t];
    int pos = atomicAdd(&g_cur[dst], 1);
    int o = g_off[dst] + pos;
    g_srcl[o] = ei[t];
    g_eidl[o] = t;
}

// ---------------- conv weight transpose: wext[(t*128+cin)*128 + cout] ----------------
__global__ void prep_wext(const float* __restrict__ conv_w) {
    int idx = blockIdx.x * blockDim.x + threadIdx.x;
    if (idx >= 384 * 128) return;
    int kext = idx >> 7, cout = idx & 127;
    int t = kext >> 7, cin = kext & 127;
    g_wext[idx] = conv_w[cout * 384 + cin * 3 + t];
}

// ---------------- fused attention: warp/node, online softmax, 2-edge batch + FFMA2 ----------------
__global__ __launch_bounds__(256) void attn_kernel(
    const float* __restrict__ x,
    const float* __restrict__ edge_attr, const float* __restrict__ W_e,
    const float* __restrict__ att, const float* __restrict__ bias_gat,
    const float* __restrict__ weight1)
{
    __shared__ __align__(16) float We_s[2048];
    __shared__ float att_s[128];
    __shared__ float bias_s[128];
    __shared__ float red_s[256];
    int tid = threadIdx.x;
    for (int idx = tid; idx < 2048; idx += 256) We_s[idx] = W_e[idx];
    if (tid < 128) { att_s[tid] = att[tid]; bias_s[tid] = bias_gat[tid]; }
    red_s[tid] = 0.f;
    __syncthreads();

    int i = blockIdx.x * 8 + (tid >> 5);   // grid = 6250 -> exactly 50000 nodes
    int lane = tid & 31;
    int c0 = lane * 4;
    int base = g_off[i];
    int deg = g_deg[i];

    const float4 xr4 = *(const float4*)(g_xr + (size_t)i * 128 + c0);
    const float4 xli = *(const float4*)(g_xl + (size_t)i * 128 + c0);
    float ax = att_s[c0], ay = att_s[c0 + 1], az = att_s[c0 + 2], aw = att_s[c0 + 3];

    // self loop handled analytically: message = leaky(xl_i + xr_i), no edge term
    float sx = xli.x + xr4.x, sy = xli.y + xr4.y;
    float sz = xli.z + xr4.z, sw = xli.w + xr4.w;
    sx = (sx > 0.f) ? sx : 0.2f * sx; sy = (sy > 0.f) ? sy : 0.2f * sy;
    sz = (sz > 0.f) ? sz : 0.2f * sz; sw = (sw > 0.f) ? sw : 0.2f * sw;
    float part = sx * ax + sy * ay + sz * az + sw * aw;
#pragma unroll
    for (int o = 16; o; o >>= 1) part += __shfl_xor_sync(0xffffffffu, part, o);
    float m = part, den = 1.f;
    float4 acc = xli;

    int jj = 0;
    // ---- 2-edge batched mainloop: one We_s read serves both edges ----
    for (; jj + 2 <= deg; jj += 2) {
        int s0 = g_srcl[base + jj],     s1 = g_srcl[base + jj + 1];
        int e0 = g_eidl[base + jj],     e1 = g_eidl[base + jj + 1];
        const float4 xlA = *(const float4*)(g_xl + (size_t)s0 * 128 + c0);
        const float4 xlB = *(const float4*)(g_xl + (size_t)s1 * 128 + c0);
        const float4* epA = (const float4*)(edge_attr + (size_t)e0 * EDIM);
        const float4* epB = (const float4*)(edge_attr + (size_t)e1 * EDIM);
        float4 aA = __ldg(epA), aB = __ldg(epA + 1), aC = __ldg(epA + 2), aD = __ldg(epA + 3);
        float4 bA = __ldg(epB), bB = __ldg(epB + 1), bC = __ldg(epB + 2), bD = __ldg(epB + 3);
        float evA[16] = {aA.x, aA.y, aA.z, aA.w, aB.x, aB.y, aB.z, aB.w,
                         aC.x, aC.y, aC.z, aC.w, aD.x, aD.y, aD.z, aD.w};
        float evB[16] = {bA.x, bA.y, bA.z, bA.w, bB.x, bB.y, bB.z, bB.w,
                         bC.x, bC.y, bC.z, bC.w, bD.x, bD.y, bD.z, bD.w};

        ull a01 = pack2(xlA.x + xr4.x, xlA.y + xr4.y);
        ull a23 = pack2(xlA.z + xr4.z, xlA.w + xr4.w);
        ull b01 = pack2(xlB.x + xr4.x, xlB.y + xr4.y);
        ull b23 = pack2(xlB.z + xr4.z, xlB.w + xr4.w);
#pragma unroll
        for (int k = 0; k < EDIM; k++) {
            ulonglong2 w = *(const ulonglong2*)&We_s[k * 128 + c0];
            ull dA = dup2(evA[k]);
            ull dB = dup2(evB[k]);
            fma2(a01, dA, w.x); fma2(a23, dA, w.y);
            fma2(b01, dB, w.x); fma2(b23, dB, w.y);
        }
        float2 pA01 = u2f(a01), pA23 = u2f(a23);
        float2 pB01 = u2f(b01), pB23 = u2f(b23);
        float mxA = pA01.x, myA = pA01.y, mzA = pA23.x, mwA = pA23.y;
        float mxB = pB01.x, myB = pB01.y, mzB = pB23.x, mwB = pB23.y;
        mxA = (mxA > 0.f) ? mxA : 0.2f * mxA;  myA = (myA > 0.f) ? myA : 0.2f * myA;
        mzA = (mzA > 0.f) ? mzA : 0.2f * mzA;  mwA = (mwA > 0.f) ? mwA : 0.2f * mwA;
        mxB = (mxB > 0.f) ? mxB : 0.2f * mxB;  myB = (myB > 0.f) ? myB : 0.2f * myB;
        mzB = (mzB > 0.f) ? mzB : 0.2f * mzB;  mwB = (mwB > 0.f) ? mwB : 0.2f * mwB;
        float pA = mxA * ax + myA * ay + mzA * az + mwA * aw;
        float pB = mxB * ax + myB * ay + mzB * az + mwB * aw;
#pragma unroll
        for (int o = 16; o; o >>= 1) {
            pA += __shfl_xor_sync(0xffffffffu, pA, o);
            pB += __shfl_xor_sync(0xffffffffu, pB, o);
        }
        // sequential online-softmax updates (warp-uniform branches)
        if (pA > m) {
            float scl = __expf(m - pA);
            den *= scl;
            acc.x *= scl; acc.y *= scl; acc.z *= scl; acc.w *= scl;
            m = pA;
        }
        {
            float pr = __expf(pA - m);
            den += pr;
            acc.x += pr * xlA.x; acc.y += pr * xlA.y;
            acc.z += pr * xlA.z; acc.w += pr * xlA.w;
        }
        if (pB > m) {
            float scl = __expf(m - pB);
            den *= scl;
            acc.x *= scl; acc.y *= scl; acc.z *= scl; acc.w *= scl;
            m = pB;
        }
        {
            float pr = __expf(pB - m);
            den += pr;
            acc.x += pr * xlB.x; acc.y += pr * xlB.y;
            acc.z += pr * xlB.z; acc.w += pr * xlB.w;
        }
    }
    // ---- tail (deg odd): single-edge body ----
    for (; jj < deg; ++jj) {
        int src = g_srcl[base + jj];
        int e   = g_eidl[base + jj];
        const float4 xl4 = *(const float4*)(g_xl + (size_t)src * 128 + c0);
        const float4* eap = (const float4*)(edge_attr + (size_t)e * EDIM);
        float4 eA = __ldg(eap), eB = __ldg(eap + 1), eC = __ldg(eap + 2), eD = __ldg(eap + 3);
        float ev[16] = {eA.x, eA.y, eA.z, eA.w, eB.x, eB.y, eB.z, eB.w,
                        eC.x, eC.y, eC.z, eC.w, eD.x, eD.y, eD.z, eD.w};
        float mx = xl4.x + xr4.x, my = xl4.y + xr4.y;
        float mz = xl4.z + xr4.z, mw = xl4.w + xr4.w;
#pragma unroll
        for (int k = 0; k < EDIM; k++) {
            const float4 w = *(const float4*)&We_s[k * 128 + c0];
            mx += ev[k] * w.x; my += ev[k] * w.y; mz += ev[k] * w.z; mw += ev[k] * w.w;
        }
        mx = (mx > 0.f) ? mx : 0.2f * mx;
        my = (my > 0.f) ? my : 0.2f * my;
        mz = (mz > 0.f) ? mz : 0.2f * mz;
        mw = (mw > 0.f) ? mw : 0.2f * mw;
        float p = mx * ax + my * ay + mz * az + mw * aw;
#pragma unroll
        for (int o = 16; o; o >>= 1) p += __shfl_xor_sync(0xffffffffu, p, o);
        if (p > m) {
            float scl = __expf(m - p);
            den *= scl;
            acc.x *= scl; acc.y *= scl; acc.z *= scl; acc.w *= scl;
            m = p;
        }
        float pr = __expf(p - m);
        den += pr;
        acc.x += pr * xl4.x; acc.y += pr * xl4.y;
        acc.z += pr * xl4.z; acc.w += pr * xl4.w;
    }

    float inv = 1.f / den;
    // softmax(weight1)
    float a0 = weight1[0], a1 = weight1[1];
    float wm = fmaxf(a0, a1);
    float e0 = __expf(a0 - wm), e1 = __expf(a1 - wm);
    float is = 1.f / (e0 + e1);
    float w10 = e0 * is, w11 = e1 * is;

    const float4 xv = *(const float4*)(x + (size_t)i * 128 + c0);
    float4 o;
    o.x = w10 * xv.x + w11 * (acc.x * inv + bias_s[c0]);
    o.y = w10 * xv.y + w11 * (acc.y * inv + bias_s[c0 + 1]);
    o.z = w10 * xv.z + w11 * (acc.z * inv + bias_s[c0 + 2]);
    o.w = w10 * xv.w + w11 * (acc.w * inv + bias_s[c0 + 3]);
    *(float4*)(g_zpre + (size_t)i * 128 + c0) = o;

    // fused BN1 stats: block-level partials then one global flush
    atomicAdd(&red_s[c0 + 0], o.x); atomicAdd(&red_s[128 + c0 + 0], o.x * o.x);
    atomicAdd(&red_s[c0 + 1], o.y); atomicAdd(&red_s[128 + c0 + 1], o.y * o.y);
    atomicAdd(&red_s[c0 + 2], o.z); atomicAdd(&red_s[128 + c0 + 2], o.z * o.z);
    atomicAdd(&red_s[c0 + 3], o.w); atomicAdd(&red_s[128 + c0 + 3], o.w * o.w);
    __syncthreads();
    atomicAdd(&g_stats[tid], red_s[tid]);
}

__global__ void bn_finalize(const float* __restrict__ stats,
                            const float* __restrict__ gamma, const float* __restrict__ beta,
                            float* __restrict__ scale, float* __restrict__ shift)
{
    int c = threadIdx.x;
    float mu = stats[c] * (1.f / N_NODES);
    float var = stats[128 + c] * (1.f / N_NODES) - mu * mu;
    float rstd = rsqrtf(var + 1e-5f);
    float s = rstd * gamma[c];
    scale[c] = s;
    shift[c] = beta[c] - mu * s;
}

// ---------------- conv1d(k=3) GEMM, cp.async double-buffered weights ----------------
__global__ __launch_bounds__(256) void conv_kernel(const float* __restrict__ conv_b,
                                                   const float* __restrict__ weight2)
{
    __shared__ __align__(16) float zs[66][128];
    __shared__ __align__(16) float wt[2][16][128];
    __shared__ float sc_s[128], sh_s[128];
    __shared__ float red2[256];
    int tid = threadIdx.x;
    int row0 = blockIdx.x * 64;
    if (tid < 128) { sc_s[tid] = g_scale1[tid]; sh_s[tid] = g_shift1[tid]; }
    red2[tid] = 0.f;
    __syncthreads();

    // weight loader indices
    int wk0 = tid >> 5, wcg = tid & 31;
    int wk1 = (tid + 256) >> 5;

    // prolog: stage step 0 weights
    cpa16(s2u(&wt[0][wk0][wcg * 4]), g_wext + (size_t)wk0 * 128 + wcg * 4);
    cpa16(s2u(&wt[0][wk1][wcg * 4]), g_wext + (size_t)wk1 * 128 + wcg * 4);
    CP_COMMIT();

    // load + normalize input tile rows [row0-1, row0+64]; zero pad outside [0,N)
    for (int idx = tid; idx < 66 * 32; idx += 256) {
        int rr = idx >> 5, cg = idx & 31;
        int grow = row0 - 1 + rr;
        float4 v = make_float4(0.f, 0.f, 0.f, 0.f);
        if (grow >= 0 && grow < N_NODES) {
            float4 z = *(const float4*)(g_zpre + (size_t)grow * 128 + cg * 4);
            int c = cg * 4;
            v.x = z.x * sc_s[c] + sh_s[c];
            v.y = z.y * sc_s[c + 1] + sh_s[c + 1];
            v.z = z.z * sc_s[c + 2] + sh_s[c + 2];
            v.w = z.w * sc_s[c + 3] + sh_s[c + 3];
        }
        *(float4*)&zs[rr][cg * 4] = v;
    }

    int tcol = tid & 31, trow = tid >> 5;
    int c0 = tcol * 4, r0 = trow * 8;
    ull acc2[8][2];
#pragma unroll
    for (int r = 0; r < 8; r++) { acc2[r][0] = 0ull; acc2[r][1] = 0ull; }

#pragma unroll 1
    for (int step = 0; step < 24; step++) {
        int buf = step & 1;
        int t = step >> 3, kc = step & 7;
        CP_WAIT0();
        __syncthreads();   // wt[buf] visible to all; all finished reading wt[buf^1]
        if (step < 23) {
            size_t kbase = (size_t)(step + 1) * 16;
            cpa16(s2u(&wt[buf ^ 1][wk0][wcg * 4]), g_wext + (kbase + wk0) * 128 + wcg * 4);
            cpa16(s2u(&wt[buf ^ 1][wk1][wcg * 4]), g_wext + (kbase + wk1) * 128 + wcg * 4);
            CP_COMMIT();
        }
#pragma unroll
        for (int kk = 0; kk < 16; kk += 4) {
            float4 a4[8];
#pragma unroll
            for (int r = 0; r < 8; r++)
                a4[r] = *(float4*)&zs[r0 + r + t][kc * 16 + kk];
#pragma unroll
            for (int q = 0; q < 4; q++) {
                ulonglong2 w2 = *(const ulonglong2*)&wt[buf][kk + q][c0];
#pragma unroll
                for (int r = 0; r < 8; r++) {
                    float av = (q == 0) ? a4[r].x : (q == 1) ? a4[r].y
                             : (q == 2) ? a4[r].z : a4[r].w;
                    ull ad = dup2(av);
                    fma2(acc2[r][0], ad, w2.x);
                    fma2(acc2[r][1], ad, w2.y);
                }
            }
        }
    }

    // softmax(weight2)
    float a0 = weight2[0], a1 = weight2[1];
    float wm = fmaxf(a0, a1);
    float e0 = __expf(a0 - wm), e1 = __expf(a1 - wm);
    float is = 1.f / (e0 + e1);
    float w20 = e0 * is, w21 = e1 * is;

    float4 b4 = *(const float4*)(conv_b + c0);
    float sst[4] = {0.f, 0.f, 0.f, 0.f};
    float qst[4] = {0.f, 0.f, 0.f, 0.f};
#pragma unroll
    for (int r = 0; r < 8; r++) {
        int grow = row0 + r0 + r;
        if (grow < N_NODES) {
            float2 u0 = u2f(acc2[r][0]), u1 = u2f(acc2[r][1]);
            float4 z1;
            z1.x = u0.x + b4.x; z1.y = u0.y + b4.y;
            z1.z = u1.x + b4.z; z1.w = u1.y + b4.w;
            z1.x = (z1.x > 0.f) ? z1.x : 0.01f * z1.x;
            z1.y = (z1.y > 0.f) ? z1.y : 0.01f * z1.y;
            z1.z = (z1.z > 0.f) ? z1.z : 0.01f * z1.z;
            z1.w = (z1.w > 0.f) ? z1.w : 0.01f * z1.w;
            float4 zn = *(float4*)&zs[r0 + r + 1][c0];
            float4 o;
            o.x = w20 * zn.x + w21 * z1.x;
            o.y = w20 * zn.y + w21 * z1.y;
            o.z = w20 * zn.z + w21 * z1.z;
            o.w = w20 * zn.w + w21 * z1.w;
            *(float4*)(g_z2 + (size_t)grow * 128 + c0) = o;
            sst[0] += o.x; qst[0] += o.x * o.x;
            sst[1] += o.y; qst[1] += o.y * o.y;
            sst[2] += o.z; qst[2] += o.z * o.z;
            sst[3] += o.w; qst[3] += o.w * o.w;
        }
    }
#pragma unroll
    for (int j = 0; j < 4; j++) {
        atomicAdd(&red2[c0 + j], sst[j]);
        atomicAdd(&red2[128 + c0 + j], qst[j]);
    }
    __syncthreads();
    atomicAdd(&g_stats[256 + tid], red2[tid]);
}

// ---------------- final BN2 apply ----------------
__global__ void final_apply(float* __restrict__ out) {
    int idx = blockIdx.x * blockDim.x + threadIdx.x;   // over N*32 float4 groups
    if (idx >= N_NODES * 32) return;
    int cg = idx & 31;
    int c = cg * 4;
    float4 z = *(const float4*)(g_z2 + (size_t)idx * 4);
    float4 o;
    o.x = z.x * g_scale2[c]     + g_shift2[c];
    o.y = z.y * g_scale2[c + 1] + g_shift2[c + 1];
    o.z = z.z * g_scale2[c + 2] + g_shift2[c + 2];
    o.w = z.w * g_scale2[c + 3] + g_shift2[c + 3];
    *(float4*)(out + (size_t)idx * 4) = o;
}

// ---------------- launch ----------------
extern "C" void kernel_launch(void* const* d_in, const int* in_sizes, int n_in,
                              void* d_out, int out_size)
{
    const float* x         = (const float*)d_in[0];
    const int*   ei        = (const int*)d_in[1];
    const float* edge_attr = (const float*)d_in[2];
    const float* W_l       = (const float*)d_in[3];
    const float* b_l       = (const float*)d_in[4];
    const float* W_r       = (const float*)d_in[5];
    const float* b_r       = (const float*)d_in[6];
    const float* W_e       = (const float*)d_in[7];
    const float* att       = (const float*)d_in[8];
    const float* bias_gat  = (const float*)d_in[9];
    const float* weight1   = (const float*)d_in[10];
    const float* bn1_gamma = (const float*)d_in[11];
    const float* bn1_beta  = (const float*)d_in[12];
    const float* conv_w    = (const float*)d_in[13];
    const float* conv_b    = (const float*)d_in[14];
    const float* weight2   = (const float*)d_in[15];
    const float* bn2_gamma = (const float*)d_in[16];
    const float* bn2_beta  = (const float*)d_in[17];
    float* out = (float*)d_out;

    float *p_xl, *p_xr, *p_stats, *p_sc1, *p_sh1, *p_sc2, *p_sh2;
    cudaGetSymbolAddress((void**)&p_xl, g_xl);
    cudaGetSymbolAddress((void**)&p_xr, g_xr);
    cudaGetSymbolAddress((void**)&p_stats, g_stats);
    cudaGetSymbolAddress((void**)&p_sc1, g_scale1);
    cudaGetSymbolAddress((void**)&p_sh1, g_shift1);
    cudaGetSymbolAddress((void**)&p_sc2, g_scale2);
    cudaGetSymbolAddress((void**)&p_sh2, g_shift2);

    // order chosen so the ncu-profiled 4th launch is gemm_dual (the hot GEMM)
    zero_kernel<<<(N_NODES + 255) / 256, 256>>>();
    hist_kernel<<<(E_EDGES + 255) / 256, 256>>>(ei);
    base_kernel<<<(N_NODES + 255) / 256, 256>>>();
    gemm_dual<<<(N_NODES + 63) / 64, 256>>>(x, W_l, b_l, W_r, b_r, p_xl, p_xr, N_NODES);
    scatter_kernel<<<(E_EDGES + 255) / 256, 256>>>(ei);
    prep_wext<<<(384 * 128 + 255) / 256, 256>>>(conv_w);
    attn_kernel<<<N_NODES / 8, 256>>>(x, edge_attr, W_e, att, bias_gat, weight1);
    bn_finalize<<<1, 128>>>(p_stats, bn1_gamma, bn1_beta, p_sc1, p_sh1);
    conv_kernel<<<(N_NODES + 63) / 64, 256>>>(conv_b, weight2);
    bn_finalize<<<1, 128>>>(p_stats + 256, bn2_gamma, bn2_beta, p_sc2, p_sh2);
    final_apply<<<(N_NODES * 32 + 255) / 256, 256>>>(out);
}

// round 13
// speedup vs baseline: 1.7949x; 1.0251x over previous
#include <cuda_runtime.h>

#define N_NODES 50000
#define E_EDGES 800000
#define DCH     128
#define EDIM    16

typedef unsigned long long ull;

// ---------------- packed f32x2 helpers (sm_103a FFMA2) ----------------
__device__ __forceinline__ void fma2(ull &d, ull a, ull b) {
    asm("fma.rn.f32x2 %0, %1, %2, %0;" : "+l"(d) : "l"(a), "l"(b));
}
__device__ __forceinline__ ull dup2(float a) {
    ull r; asm("mov.b64 %0, {%1, %1};" : "=l"(r) : "f"(a)); return r;
}
__device__ __forceinline__ ull pack2(float a, float b) {
    ull r; asm("mov.b64 %0, {%1, %2};" : "=l"(r) : "f"(a), "f"(b)); return r;
}
__device__ __forceinline__ float2 u2f(ull v) {
    float2 f; asm("mov.b64 {%0, %1}, %2;" : "=f"(f.x), "=f"(f.y) : "l"(v)); return f;
}

// ---------------- cp.async helpers ----------------
__device__ __forceinline__ unsigned s2u(const void* p) {
    unsigned a;
    asm("{ .reg .u64 t; cvta.to.shared.u64 t, %1; cvt.u32.u64 %0, t; }" : "=r"(a) : "l"(p));
    return a;
}
__device__ __forceinline__ void cpa16(unsigned d, const void* s) {
    asm volatile("cp.async.cg.shared.global [%0], [%1], 16;" :: "r"(d), "l"(s));
}
#define CP_COMMIT() asm volatile("cp.async.commit_group;" ::: "memory")
#define CP_WAIT0()  asm volatile("cp.async.wait_group 0;" ::: "memory")

// ---------------- device scratch (no allocs allowed) ----------------
__device__ float g_xl[N_NODES * DCH];
__device__ float g_xr[N_NODES * DCH];
__device__ float g_zpre[N_NODES * DCH];
__device__ float g_z2[N_NODES * DCH];
__device__ float g_wext[384 * DCH];
__device__ int   g_deg[N_NODES];
__device__ int   g_cur[N_NODES];
__device__ int   g_off[N_NODES];
__device__ int   g_srcl[E_EDGES];
__device__ int   g_eidl[E_EDGES];
__device__ int   g_cnt;
__device__ float g_stats[512];              // [0..255] bn1 (sum,sumsq), [256..511] bn2
__device__ float g_scale1[DCH], g_shift1[DCH];
__device__ float g_scale2[DCH], g_shift2[DCH];

// ---------------- zero scratch ----------------
__global__ void zero_kernel() {
    int idx = blockIdx.x * blockDim.x + threadIdx.x;
    if (idx < N_NODES) { g_deg[idx] = 0; g_cur[idx] = 0; }
    if (idx < 512) g_stats[idx] = 0.f;
    if (idx == 0) g_cnt = 0;
}

// ---------------- dual GEMM, cp.async double-buffered (R11 measured win) ----------------
__global__ __launch_bounds__(256, 2) void gemm_dual(
    const float* __restrict__ A,
    const float* __restrict__ Wl, const float* __restrict__ bl,
    const float* __restrict__ Wr, const float* __restrict__ br,
    float* __restrict__ Cl, float* __restrict__ Cr, int nrows)
{
    __shared__ __align__(16) float as[2][16][64];
    __shared__ __align__(16) float wsL[2][16][128];
    __shared__ __align__(16) float wsR[2][16][128];
    int tid = threadIdx.x;
    int row0 = blockIdx.x * 64;
    int tcol = tid & 31, trow = tid >> 5;
    int c0 = tcol * 4, r0 = trow * 8;
    ull accL[8][2], accR[8][2];
#pragma unroll
    for (int r = 0; r < 8; r++) {
        accL[r][0] = 0ull; accL[r][1] = 0ull;
        accR[r][0] = 0ull; accR[r][1] = 0ull;
    }

    int lr = tid & 63, lkg = tid >> 6;
    int wk0 = tid >> 5,        wcg = tid & 31;
    int wk1 = (tid + 256) >> 5;
    int grow = row0 + lr;
    bool rowok = (grow < nrows);

    cpa16(s2u(&wsL[0][wk0][wcg * 4]), Wl + (size_t)wk0 * 128 + wcg * 4);
    cpa16(s2u(&wsL[0][wk1][wcg * 4]), Wl + (size_t)wk1 * 128 + wcg * 4);
    cpa16(s2u(&wsR[0][wk0][wcg * 4]), Wr + (size_t)wk0 * 128 + wcg * 4);
    cpa16(s2u(&wsR[0][wk1][wcg * 4]), Wr + (size_t)wk1 * 128 + wcg * 4);
    CP_COMMIT();
    float4 vx = make_float4(0.f, 0.f, 0.f, 0.f);
    if (rowok) vx = *(const float4*)(A + (size_t)grow * 128 + lkg * 4);

#pragma unroll 1
    for (int kbi = 0; kbi < 8; kbi++) {
        int buf = kbi & 1;
        CP_WAIT0();
        as[buf][lkg * 4 + 0][lr] = vx.x; as[buf][lkg * 4 + 1][lr] = vx.y;
        as[buf][lkg * 4 + 2][lr] = vx.z; as[buf][lkg * 4 + 3][lr] = vx.w;
        __syncthreads();
        if (kbi < 7) {
            int kb = (kbi + 1) * 16;
            cpa16(s2u(&wsL[buf ^ 1][wk0][wcg * 4]), Wl + (size_t)(kb + wk0) * 128 + wcg * 4);
            cpa16(s2u(&wsL[buf ^ 1][wk1][wcg * 4]), Wl + (size_t)(kb + wk1) * 128 + wcg * 4);
            cpa16(s2u(&wsR[buf ^ 1][wk0][wcg * 4]), Wr + (size_t)(kb + wk0) * 128 + wcg * 4);
            cpa16(s2u(&wsR[buf ^ 1][wk1][wcg * 4]), Wr + (size_t)(kb + wk1) * 128 + wcg * 4);
            CP_COMMIT();
            if (rowok) vx = *(const float4*)(A + (size_t)grow * 128 + kb + lkg * 4);
        }
#pragma unroll
        for (int k = 0; k < 16; k++) {
            ulonglong2 wL = *(const ulonglong2*)&wsL[buf][k][c0];
            ulonglong2 wR = *(const ulonglong2*)&wsR[buf][k][c0];
            float4 alo = *(const float4*)&as[buf][k][r0];
            float4 ahi = *(const float4*)&as[buf][k][r0 + 4];
            float a[8] = {alo.x, alo.y, alo.z, alo.w, ahi.x, ahi.y, ahi.z, ahi.w};
#pragma unroll
            for (int r = 0; r < 8; r++) {
                ull ad = dup2(a[r]);
                fma2(accL[r][0], ad, wL.x);
                fma2(accL[r][1], ad, wL.y);
                fma2(accR[r][0], ad, wR.x);
                fma2(accR[r][1], ad, wR.y);
            }
        }
    }
    float4 bl4 = *(const float4*)(bl + c0);
    float4 br4 = *(const float4*)(br + c0);
#pragma unroll
    for (int r = 0; r < 8; r++) {
        int gw = row0 + r0 + r;
        if (gw < nrows) {
            float2 l0 = u2f(accL[r][0]), l1 = u2f(accL[r][1]);
            float2 r0v = u2f(accR[r][0]), r1v = u2f(accR[r][1]);
            float4 ol, orr;
            ol.x = l0.x + bl4.x;  ol.y = l0.y + bl4.y;
            ol.z = l1.x + bl4.z;  ol.w = l1.y + bl4.w;
            orr.x = r0v.x + br4.x; orr.y = r0v.y + br4.y;
            orr.z = r1v.x + br4.z; orr.w = r1v.y + br4.w;
            *(float4*)(Cl + (size_t)gw * 128 + c0) = ol;
            *(float4*)(Cr + (size_t)gw * 128 + c0) = orr;
        }
    }
}

// ---------------- CSR build (no self loops; atomic segment bases) ----------------
__global__ void hist_kernel(const int* __restrict__ ei) {
    int t = blockIdx.x * blockDim.x + threadIdx.x;
    if (t >= E_EDGES) return;
    atomicAdd(&g_deg[ei[E_EDGES + t]], 1);
}

__global__ void base_kernel() {
    int idx = blockIdx.x * blockDim.x + threadIdx.x;
    if (idx < N_NODES) g_off[idx] = atomicAdd(&g_cnt, g_deg[idx]);
}

__global__ void scatter_kernel(const int* __restrict__ ei) {
    int t = blockIdx.x * blockDim.x + threadIdx.x;
    if (t >= E_EDGES) return;
    int dst = ei[E_EDGES + t];
    int pos = atomicAdd(&g_cur[dst], 1);
    int o = g_off[dst] + pos;
    g_srcl[o] = ei[t];
    g_eidl[o] = t;
}

// ---------------- conv weight transpose: wext[(t*128+cin)*128 + cout] ----------------
__global__ void prep_wext(const float* __restrict__ conv_w) {
    int idx = blockIdx.x * blockDim.x + threadIdx.x;
    if (idx >= 384 * 128) return;
    int kext = idx >> 7, cout = idx & 127;
    int t = kext >> 7, cin = kext & 127;
    g_wext[idx] = conv_w[cout * 384 + cin * 3 + t];
}

// ---------------- fused attention: warp/node, dual-stream online softmax ----------------
__global__ __launch_bounds__(256) void attn_kernel(
    const float* __restrict__ x,
    const float* __restrict__ edge_attr, const float* __restrict__ W_e,
    const float* __restrict__ att, const float* __restrict__ bias_gat,
    const float* __restrict__ weight1)
{
    __shared__ __align__(16) float We_s[2048];
    __shared__ float att_s[128];
    __shared__ float bias_s[128];
    __shared__ float red_s[256];
    int tid = threadIdx.x;
    for (int idx = tid; idx < 2048; idx += 256) We_s[idx] = W_e[idx];
    if (tid < 128) { att_s[tid] = att[tid]; bias_s[tid] = bias_gat[tid]; }
    red_s[tid] = 0.f;
    __syncthreads();

    int i = blockIdx.x * 8 + (tid >> 5);   // grid = 6250 -> exactly 50000 nodes
    int lane = tid & 31;
    int c0 = lane * 4;
    int base = g_off[i];
    int deg = g_deg[i];

    const float4 xr4 = *(const float4*)(g_xr + (size_t)i * 128 + c0);
    const float4 xli = *(const float4*)(g_xl + (size_t)i * 128 + c0);
    float ax = att_s[c0], ay = att_s[c0 + 1], az = att_s[c0 + 2], aw = att_s[c0 + 3];

    // self loop -> stream A init: message = leaky(xl_i + xr_i), no edge term
    float sx = xli.x + xr4.x, sy = xli.y + xr4.y;
    float sz = xli.z + xr4.z, sw = xli.w + xr4.w;
    sx = (sx > 0.f) ? sx : 0.2f * sx; sy = (sy > 0.f) ? sy : 0.2f * sy;
    sz = (sz > 0.f) ? sz : 0.2f * sz; sw = (sw > 0.f) ? sw : 0.2f * sw;
    float part = sx * ax + sy * ay + sz * az + sw * aw;
#pragma unroll
    for (int o = 16; o; o >>= 1) part += __shfl_xor_sync(0xffffffffu, part, o);
    // stream A state (holds self loop)
    float mA = part, denA = 1.f;
    float4 accA = xli;
    // stream B state (empty)
    float mB = -3.0e38f, denB = 0.f;
    float4 accB = make_float4(0.f, 0.f, 0.f, 0.f);

    int jj = 0;
    // ---- 2-edge batched mainloop: one We_s read serves both edges;
    //      streams A/B update independently (no cross dependency) ----
    for (; jj + 2 <= deg; jj += 2) {
        int s0 = g_srcl[base + jj],     s1 = g_srcl[base + jj + 1];
        int e0 = g_eidl[base + jj],     e1 = g_eidl[base + jj + 1];
        const float4 xlA = *(const float4*)(g_xl + (size_t)s0 * 128 + c0);
        const float4 xlB = *(const float4*)(g_xl + (size_t)s1 * 128 + c0);
        const float4* epA = (const float4*)(edge_attr + (size_t)e0 * EDIM);
        const float4* epB = (const float4*)(edge_attr + (size_t)e1 * EDIM);
        float4 aA = __ldg(epA), aB = __ldg(epA + 1), aC = __ldg(epA + 2), aD = __ldg(epA + 3);
        float4 bA = __ldg(epB), bB = __ldg(epB + 1), bC = __ldg(epB + 2), bD = __ldg(epB + 3);
        float evA[16] = {aA.x, aA.y, aA.z, aA.w, aB.x, aB.y, aB.z, aB.w,
                         aC.x, aC.y, aC.z, aC.w, aD.x, aD.y, aD.z, aD.w};
        float evB[16] = {bA.x, bA.y, bA.z, bA.w, bB.x, bB.y, bB.z, bB.w,
                         bC.x, bC.y, bC.z, bC.w, bD.x, bD.y, bD.z, bD.w};

        ull a01 = pack2(xlA.x + xr4.x, xlA.y + xr4.y);
        ull a23 = pack2(xlA.z + xr4.z, xlA.w + xr4.w);
        ull b01 = pack2(xlB.x + xr4.x, xlB.y + xr4.y);
        ull b23 = pack2(xlB.z + xr4.z, xlB.w + xr4.w);
#pragma unroll
        for (int k = 0; k < EDIM; k++) {
            ulonglong2 w = *(const ulonglong2*)&We_s[k * 128 + c0];
            ull dA = dup2(evA[k]);
            ull dB = dup2(evB[k]);
            fma2(a01, dA, w.x); fma2(a23, dA, w.y);
            fma2(b01, dB, w.x); fma2(b23, dB, w.y);
        }
        float2 pA01 = u2f(a01), pA23 = u2f(a23);
        float2 pB01 = u2f(b01), pB23 = u2f(b23);
        float mxA = pA01.x, myA = pA01.y, mzA = pA23.x, mwA = pA23.y;
        float mxB = pB01.x, myB = pB01.y, mzB = pB23.x, mwB = pB23.y;
        mxA = (mxA > 0.f) ? mxA : 0.2f * mxA;  myA = (myA > 0.f) ? myA : 0.2f * myA;
        mzA = (mzA > 0.f) ? mzA : 0.2f * mzA;  mwA = (mwA > 0.f) ? mwA : 0.2f * mwA;
        mxB = (mxB > 0.f) ? mxB : 0.2f * mxB;  myB = (myB > 0.f) ? myB : 0.2f * myB;
        mzB = (mzB > 0.f) ? mzB : 0.2f * mzB;  mwB = (mwB > 0.f) ? mwB : 0.2f * mwB;
        float pA = mxA * ax + myA * ay + mzA * az + mwA * aw;
        float pB = mxB * ax + myB * ay + mzB * az + mwB * aw;
#pragma unroll
        for (int o = 16; o; o >>= 1) {
            pA += __shfl_xor_sync(0xffffffffu, pA, o);
            pB += __shfl_xor_sync(0xffffffffu, pB, o);
        }
        // independent stream updates (warp-uniform branches)
        if (pA > mA) {
            float scl = __expf(mA - pA);
            denA *= scl;
            accA.x *= scl; accA.y *= scl; accA.z *= scl; accA.w *= scl;
            mA = pA;
        }
        if (pB > mB) {
            float scl = (denB == 0.f) ? 0.f : __expf(mB - pB);
            denB *= scl;
            accB.x *= scl; accB.y *= scl; accB.z *= scl; accB.w *= scl;
            mB = pB;
        }
        float prA = __expf(pA - mA);
        float prB = __expf(pB - mB);
        denA += prA;
        denB += prB;
        accA.x += prA * xlA.x; accA.y += prA * xlA.y;
        accA.z += prA * xlA.z; accA.w += prA * xlA.w;
        accB.x += prB * xlB.x; accB.y += prB * xlB.y;
        accB.z += prB * xlB.z; accB.w += prB * xlB.w;
    }
    // ---- tail (deg odd): single-edge body, stream A ----
    for (; jj < deg; ++jj) {
        int src = g_srcl[base + jj];
        int e   = g_eidl[base + jj];
        const float4 xl4 = *(const float4*)(g_xl + (size_t)src * 128 + c0);
        const float4* eap = (const float4*)(edge_attr + (size_t)e * EDIM);
        float4 eA = __ldg(eap), eB = __ldg(eap + 1), eC = __ldg(eap + 2), eD = __ldg(eap + 3);
        float ev[16] = {eA.x, eA.y, eA.z, eA.w, eB.x, eB.y, eB.z, eB.w,
                        eC.x, eC.y, eC.z, eC.w, eD.x, eD.y, eD.z, eD.w};
        float mx = xl4.x + xr4.x, my = xl4.y + xr4.y;
        float mz = xl4.z + xr4.z, mw = xl4.w + xr4.w;
#pragma unroll
        for (int k = 0; k < EDIM; k++) {
            const float4 w = *(const float4*)&We_s[k * 128 + c0];
            mx += ev[k] * w.x; my += ev[k] * w.y; mz += ev[k] * w.z; mw += ev[k] * w.w;
        }
        mx = (mx > 0.f) ? mx : 0.2f * mx;
        my = (my > 0.f) ? my : 0.2f * my;
        mz = (mz > 0.f) ? mz : 0.2f * mz;
        mw = (mw > 0.f) ? mw : 0.2f * mw;
        float p = mx * ax + my * ay + mz * az + mw * aw;
#pragma unroll
        for (int o = 16; o; o >>= 1) p += __shfl_xor_sync(0xffffffffu, p, o);
        if (p > mA) {
            float scl = __expf(mA - p);
            denA *= scl;
            accA.x *= scl; accA.y *= scl; accA.z *= scl; accA.w *= scl;
            mA = p;
        }
        float pr = __expf(p - mA);
        denA += pr;
        accA.x += pr * xl4.x; accA.y += pr * xl4.y;
        accA.z += pr * xl4.z; accA.w += pr * xl4.w;
    }

    // ---- merge streams: m = max(mA, mB) ----
    float m = fmaxf(mA, mB);
    float sA = __expf(mA - m);
    float sB = (denB == 0.f) ? 0.f : __expf(mB - m);
    float den = denA * sA + denB * sB;
    float4 acc;
    acc.x = accA.x * sA + accB.x * sB;
    acc.y = accA.y * sA + accB.y * sB;
    acc.z = accA.z * sA + accB.z * sB;
    acc.w = accA.w * sA + accB.w * sB;

    float inv = 1.f / den;
    // softmax(weight1)
    float a0 = weight1[0], a1 = weight1[1];
    float wm = fmaxf(a0, a1);
    float e0 = __expf(a0 - wm), e1 = __expf(a1 - wm);
    float is = 1.f / (e0 + e1);
    float w10 = e0 * is, w11 = e1 * is;

    const float4 xv = *(const float4*)(x + (size_t)i * 128 + c0);
    float4 o;
    o.x = w10 * xv.x + w11 * (acc.x * inv + bias_s[c0]);
    o.y = w10 * xv.y + w11 * (acc.y * inv + bias_s[c0 + 1]);
    o.z = w10 * xv.z + w11 * (acc.z * inv + bias_s[c0 + 2]);
    o.w = w10 * xv.w + w11 * (acc.w * inv + bias_s[c0 + 3]);
    *(float4*)(g_zpre + (size_t)i * 128 + c0) = o;

    // fused BN1 stats: block-level partials then one global flush
    atomicAdd(&red_s[c0 + 0], o.x); atomicAdd(&red_s[128 + c0 + 0], o.x * o.x);
    atomicAdd(&red_s[c0 + 1], o.y); atomicAdd(&red_s[128 + c0 + 1], o.y * o.y);
    atomicAdd(&red_s[c0 + 2], o.z); atomicAdd(&red_s[128 + c0 + 2], o.z * o.z);
    atomicAdd(&red_s[c0 + 3], o.w); atomicAdd(&red_s[128 + c0 + 3], o.w * o.w);
    __syncthreads();
    atomicAdd(&g_stats[tid], red_s[tid]);
}

__global__ void bn_finalize(const float* __restrict__ stats,
                            const float* __restrict__ gamma, const float* __restrict__ beta,
                            float* __restrict__ scale, float* __restrict__ shift)
{
    int c = threadIdx.x;
    float mu = stats[c] * (1.f / N_NODES);
    float var = stats[128 + c] * (1.f / N_NODES) - mu * mu;
    float rstd = rsqrtf(var + 1e-5f);
    float s = rstd * gamma[c];
    scale[c] = s;
    shift[c] = beta[c] - mu * s;
}

// ---------------- conv1d(k=3) as K=384 GEMM (FFMA2) + mix + fused BN2 stats (R10 proven) ----------------
__global__ __launch_bounds__(256) void conv_kernel(const float* __restrict__ conv_b,
                                                   const float* __restrict__ weight2)
{
    __shared__ __align__(16) float zs[66][128];
    __shared__ __align__(16) float wt[16][128];
    __shared__ float sc_s[128], sh_s[128];
    __shared__ float red2[256];
    int tid = threadIdx.x;
    int row0 = blockIdx.x * 64;
    if (tid < 128) { sc_s[tid] = g_scale1[tid]; sh_s[tid] = g_shift1[tid]; }
    red2[tid] = 0.f;
    __syncthreads();

    // load + normalize input tile rows [row0-1, row0+64]; zero pad outside [0,N)
    for (int idx = tid; idx < 66 * 32; idx += 256) {
        int rr = idx >> 5, cg = idx & 31;
        int grow = row0 - 1 + rr;
        float4 v = make_float4(0.f, 0.f, 0.f, 0.f);
        if (grow >= 0 && grow < N_NODES) {
            float4 z = *(const float4*)(g_zpre + (size_t)grow * 128 + cg * 4);
            int c = cg * 4;
            v.x = z.x * sc_s[c] + sh_s[c];
            v.y = z.y * sc_s[c + 1] + sh_s[c + 1];
            v.z = z.z * sc_s[c + 2] + sh_s[c + 2];
            v.w = z.w * sc_s[c + 3] + sh_s[c + 3];
        }
        *(float4*)&zs[rr][cg * 4] = v;
    }

    int tcol = tid & 31, trow = tid >> 5;
    int c0 = tcol * 4, r0 = trow * 8;
    ull acc2[8][2];
#pragma unroll
    for (int r = 0; r < 8; r++) { acc2[r][0] = 0ull; acc2[r][1] = 0ull; }

    for (int t = 0; t < 3; t++) {
        for (int kc = 0; kc < 8; kc++) {
            __syncthreads();
#pragma unroll
            for (int it = 0; it < 2; it++) {
                int idx = tid + it * 256;
                int k = idx >> 5, cg = idx & 31;
                *(float4*)&wt[k][cg * 4] =
                    *(const float4*)(g_wext + (size_t)(t * 128 + kc * 16 + k) * 128 + cg * 4);
            }
            __syncthreads();
#pragma unroll
            for (int kk = 0; kk < 16; kk += 4) {
                float4 a4[8];
#pragma unroll
                for (int r = 0; r < 8; r++)
                    a4[r] = *(float4*)&zs[r0 + r + t][kc * 16 + kk];
#pragma unroll
                for (int q = 0; q < 4; q++) {
                    ulonglong2 w2 = *(const ulonglong2*)&wt[kk + q][c0];
#pragma unroll
                    for (int r = 0; r < 8; r++) {
                        float av = (q == 0) ? a4[r].x : (q == 1) ? a4[r].y
                                 : (q == 2) ? a4[r].z : a4[r].w;
                        ull ad = dup2(av);
                        fma2(acc2[r][0], ad, w2.x);
                        fma2(acc2[r][1], ad, w2.y);
                    }
                }
            }
        }
    }

    // softmax(weight2)
    float a0 = weight2[0], a1 = weight2[1];
    float wm = fmaxf(a0, a1);
    float e0 = __expf(a0 - wm), e1 = __expf(a1 - wm);
    float is = 1.f / (e0 + e1);
    float w20 = e0 * is, w21 = e1 * is;

    float4 b4 = *(const float4*)(conv_b + c0);
    float sst[4] = {0.f, 0.f, 0.f, 0.f};
    float qst[4] = {0.f, 0.f, 0.f, 0.f};
#pragma unroll
    for (int r = 0; r < 8; r++) {
        int grow = row0 + r0 + r;
        if (grow < N_NODES) {
            float2 u0 = u2f(acc2[r][0]), u1 = u2f(acc2[r][1]);
            float4 z1;
            z1.x = u0.x + b4.x; z1.y = u0.y + b4.y;
            z1.z = u1.x + b4.z; z1.w = u1.y + b4.w;
            z1.x = (z1.x > 0.f) ? z1.x : 0.01f * z1.x;
            z1.y = (z1.y > 0.f) ? z1.y : 0.01f * z1.y;
            z1.z = (z1.z > 0.f) ? z1.z : 0.01f * z1.z;
            z1.w = (z1.w > 0.f) ? z1.w : 0.01f * z1.w;
            float4 zn = *(float4*)&zs[r0 + r + 1][c0];
            float4 o;
            o.x = w20 * zn.x + w21 * z1.x;
            o.y = w20 * zn.y + w21 * z1.y;
            o.z = w20 * zn.z + w21 * z1.z;
            o.w = w20 * zn.w + w21 * z1.w;
            *(float4*)(g_z2 + (size_t)grow * 128 + c0) = o;
            sst[0] += o.x; qst[0] += o.x * o.x;
            sst[1] += o.y; qst[1] += o.y * o.y;
            sst[2] += o.z; qst[2] += o.z * o.z;
            sst[3] += o.w; qst[3] += o.w * o.w;
        }
    }
#pragma unroll
    for (int j = 0; j < 4; j++) {
        atomicAdd(&red2[c0 + j], sst[j]);
        atomicAdd(&red2[128 + c0 + j], qst[j]);
    }
    __syncthreads();
    atomicAdd(&g_stats[256 + tid], red2[tid]);
}

// ---------------- final BN2 apply ----------------
__global__ void final_apply(float* __restrict__ out) {
    int idx = blockIdx.x * blockDim.x + threadIdx.x;   // over N*32 float4 groups
    if (idx >= N_NODES * 32) return;
    int cg = idx & 31;
    int c = cg * 4;
    float4 z = *(const float4*)(g_z2 + (size_t)idx * 4);
    float4 o;
    o.x = z.x * g_scale2[c]     + g_shift2[c];
    o.y = z.y * g_scale2[c + 1] + g_shift2[c + 1];
    o.z = z.z * g_scale2[c + 2] + g_shift2[c + 2];
    o.w = z.w * g_scale2[c + 3] + g_shift2[c + 3];
    *(float4*)(out + (size_t)idx * 4) = o;
}

// ---------------- launch ----------------
extern "C" void kernel_launch(void* const* d_in, const int* in_sizes, int n_in,
                              void* d_out, int out_size)
{
    const float* x         = (const float*)d_in[0];
    const int*   ei        = (const int*)d_in[1];
    const float* edge_attr = (const float*)d_in[2];
    const float* W_l       = (const float*)d_in[3];
    const float* b_l       = (const float*)d_in[4];
    const float* W_r       = (const float*)d_in[5];
    const float* b_r       = (const float*)d_in[6];
    const float* W_e       = (const float*)d_in[7];
    const float* att       = (const float*)d_in[8];
    const float* bias_gat  = (const float*)d_in[9];
    const float* weight1   = (const float*)d_in[10];
    const float* bn1_gamma = (const float*)d_in[11];
    const float* bn1_beta  = (const float*)d_in[12];
    const float* conv_w    = (const float*)d_in[13];
    const float* conv_b    = (const float*)d_in[14];
    const float* weight2   = (const float*)d_in[15];
    const float* bn2_gamma = (const float*)d_in[16];
    const float* bn2_beta  = (const float*)d_in[17];
    float* out = (float*)d_out;

    float *p_xl, *p_xr, *p_stats, *p_sc1, *p_sh1, *p_sc2, *p_sh2;
    cudaGetSymbolAddress((void**)&p_xl, g_xl);
    cudaGetSymbolAddress((void**)&p_xr, g_xr);
    cudaGetSymbolAddress((void**)&p_stats, g_stats);
    cudaGetSymbolAddress((void**)&p_sc1, g_scale1);
    cudaGetSymbolAddress((void**)&p_sh1, g_shift1);
    cudaGetSymbolAddress((void**)&p_sc2, g_scale2);
    cudaGetSymbolAddress((void**)&p_sh2, g_shift2);

    // order chosen so the ncu-profiled 4th launch is gemm_dual (the hot GEMM)
    zero_kernel<<<(N_NODES + 255) / 256, 256>>>();
    hist_kernel<<<(E_EDGES + 255) / 256, 256>>>(ei);
    base_kernel<<<(N_NODES + 255) / 256, 256>>>();
    gemm_dual<<<(N_NODES + 63) / 64, 256>>>(x, W_l, b_l, W_r, b_r, p_xl, p_xr, N_NODES);
    scatter_kernel<<<(E_EDGES + 255) / 256, 256>>>(ei);
    prep_wext<<<(384 * 128 + 255) / 256, 256>>>(conv_w);
    attn_kernel<<<N_NODES / 8, 256>>>(x, edge_attr, W_e, att, bias_gat, weight1);
    bn_finalize<<<1, 128>>>(p_stats, bn1_gamma, bn1_beta, p_sc1, p_sh1);
    conv_kernel<<<(N_NODES + 63) / 64, 256>>>(conv_b, weight2);
    bn_finalize<<<1, 128>>>(p_stats + 256, bn2_gamma, bn2_beta, p_sc2, p_sh2);
    final_apply<<<(N_NODES * 32 + 255) / 256, 256>>>(out);
}

// round 14
// speedup vs baseline: 1.8305x; 1.0198x over previous
#include <cuda_runtime.h>

#define N_NODES 50000
#define E_EDGES 800000
#define DCH     128
#define EDIM    16

typedef unsigned long long ull;

// ---------------- packed f32x2 helpers (sm_103a FFMA2) ----------------
__device__ __forceinline__ void fma2(ull &d, ull a, ull b) {
    asm("fma.rn.f32x2 %0, %1, %2, %0;" : "+l"(d) : "l"(a), "l"(b));
}
__device__ __forceinline__ ull dup2(float a) {
    ull r; asm("mov.b64 %0, {%1, %1};" : "=l"(r) : "f"(a)); return r;
}
__device__ __forceinline__ ull pack2(float a, float b) {
    ull r; asm("mov.b64 %0, {%1, %2};" : "=l"(r) : "f"(a), "f"(b)); return r;
}
__device__ __forceinline__ float2 u2f(ull v) {
    float2 f; asm("mov.b64 {%0, %1}, %2;" : "=f"(f.x), "=f"(f.y) : "l"(v)); return f;
}

// ---------------- cp.async helpers ----------------
__device__ __forceinline__ unsigned s2u(const void* p) {
    unsigned a;
    asm("{ .reg .u64 t; cvta.to.shared.u64 t, %1; cvt.u32.u64 %0, t; }" : "=r"(a) : "l"(p));
    return a;
}
__device__ __forceinline__ void cpa16(unsigned d, const void* s) {
    asm volatile("cp.async.cg.shared.global [%0], [%1], 16;" :: "r"(d), "l"(s));
}
#define CP_COMMIT() asm volatile("cp.async.commit_group;" ::: "memory")
#define CP_WAIT0()  asm volatile("cp.async.wait_group 0;" ::: "memory")

// ---------------- device scratch (no allocs allowed) ----------------
__device__ float g_xl[N_NODES * DCH];
__device__ float g_xr[N_NODES * DCH];
__device__ float g_zpre[N_NODES * DCH];
__device__ float g_z2[N_NODES * DCH];
__device__ float g_wext[384 * DCH];
__device__ int   g_deg[N_NODES];
__device__ int   g_cur[N_NODES];
__device__ int   g_off[N_NODES];
__device__ int   g_srcl[E_EDGES];
__device__ int   g_eidl[E_EDGES];
__device__ int   g_cnt;
__device__ float g_stats[512];              // [0..255] bn1 (sum,sumsq), [256..511] bn2
__device__ float g_scale1[DCH], g_shift1[DCH];
__device__ float g_scale2[DCH], g_shift2[DCH];

// ---------------- zero scratch ----------------
__global__ void zero_kernel() {
    int idx = blockIdx.x * blockDim.x + threadIdx.x;
    if (idx < N_NODES) { g_deg[idx] = 0; g_cur[idx] = 0; }
    if (idx < 512) g_stats[idx] = 0.f;
    if (idx == 0) g_cnt = 0;
}

// ---------------- dual GEMM, cp.async double-buffered (R11 measured win) ----------------
__global__ __launch_bounds__(256, 2) void gemm_dual(
    const float* __restrict__ A,
    const float* __restrict__ Wl, const float* __restrict__ bl,
    const float* __restrict__ Wr, const float* __restrict__ br,
    float* __restrict__ Cl, float* __restrict__ Cr, int nrows)
{
    __shared__ __align__(16) float as[2][16][64];
    __shared__ __align__(16) float wsL[2][16][128];
    __shared__ __align__(16) float wsR[2][16][128];
    int tid = threadIdx.x;
    int row0 = blockIdx.x * 64;
    int tcol = tid & 31, trow = tid >> 5;
    int c0 = tcol * 4, r0 = trow * 8;
    ull accL[8][2], accR[8][2];
#pragma unroll
    for (int r = 0; r < 8; r++) {
        accL[r][0] = 0ull; accL[r][1] = 0ull;
        accR[r][0] = 0ull; accR[r][1] = 0ull;
    }

    int lr = tid & 63, lkg = tid >> 6;
    int wk0 = tid >> 5,        wcg = tid & 31;
    int wk1 = (tid + 256) >> 5;
    int grow = row0 + lr;
    bool rowok = (grow < nrows);

    cpa16(s2u(&wsL[0][wk0][wcg * 4]), Wl + (size_t)wk0 * 128 + wcg * 4);
    cpa16(s2u(&wsL[0][wk1][wcg * 4]), Wl + (size_t)wk1 * 128 + wcg * 4);
    cpa16(s2u(&wsR[0][wk0][wcg * 4]), Wr + (size_t)wk0 * 128 + wcg * 4);
    cpa16(s2u(&wsR[0][wk1][wcg * 4]), Wr + (size_t)wk1 * 128 + wcg * 4);
    CP_COMMIT();
    float4 vx = make_float4(0.f, 0.f, 0.f, 0.f);
    if (rowok) vx = *(const float4*)(A + (size_t)grow * 128 + lkg * 4);

#pragma unroll 1
    for (int kbi = 0; kbi < 8; kbi++) {
        int buf = kbi & 1;
        CP_WAIT0();
        as[buf][lkg * 4 + 0][lr] = vx.x; as[buf][lkg * 4 + 1][lr] = vx.y;
        as[buf][lkg * 4 + 2][lr] = vx.z; as[buf][lkg * 4 + 3][lr] = vx.w;
        __syncthreads();
        if (kbi < 7) {
            int kb = (kbi + 1) * 16;
            cpa16(s2u(&wsL[buf ^ 1][wk0][wcg * 4]), Wl + (size_t)(kb + wk0) * 128 + wcg * 4);
            cpa16(s2u(&wsL[buf ^ 1][wk1][wcg * 4]), Wl + (size_t)(kb + wk1) * 128 + wcg * 4);
            cpa16(s2u(&wsR[buf ^ 1][wk0][wcg * 4]), Wr + (size_t)(kb + wk0) * 128 + wcg * 4);
            cpa16(s2u(&wsR[buf ^ 1][wk1][wcg * 4]), Wr + (size_t)(kb + wk1) * 128 + wcg * 4);
            CP_COMMIT();
            if (rowok) vx = *(const float4*)(A + (size_t)grow * 128 + kb + lkg * 4);
        }
#pragma unroll
        for (int k = 0; k < 16; k++) {
            ulonglong2 wL = *(const ulonglong2*)&wsL[buf][k][c0];
            ulonglong2 wR = *(const ulonglong2*)&wsR[buf][k][c0];
            float4 alo = *(const float4*)&as[buf][k][r0];
            float4 ahi = *(const float4*)&as[buf][k][r0 + 4];
            float a[8] = {alo.x, alo.y, alo.z, alo.w, ahi.x, ahi.y, ahi.z, ahi.w};
#pragma unroll
            for (int r = 0; r < 8; r++) {
                ull ad = dup2(a[r]);
                fma2(accL[r][0], ad, wL.x);
                fma2(accL[r][1], ad, wL.y);
                fma2(accR[r][0], ad, wR.x);
                fma2(accR[r][1], ad, wR.y);
            }
        }
    }
    float4 bl4 = *(const float4*)(bl + c0);
    float4 br4 = *(const float4*)(br + c0);
#pragma unroll
    for (int r = 0; r < 8; r++) {
        int gw = row0 + r0 + r;
        if (gw < nrows) {
            float2 l0 = u2f(accL[r][0]), l1 = u2f(accL[r][1]);
            float2 r0v = u2f(accR[r][0]), r1v = u2f(accR[r][1]);
            float4 ol, orr;
            ol.x = l0.x + bl4.x;  ol.y = l0.y + bl4.y;
            ol.z = l1.x + bl4.z;  ol.w = l1.y + bl4.w;
            orr.x = r0v.x + br4.x; orr.y = r0v.y + br4.y;
            orr.z = r1v.x + br4.z; orr.w = r1v.y + br4.w;
            *(float4*)(Cl + (size_t)gw * 128 + c0) = ol;
            *(float4*)(Cr + (size_t)gw * 128 + c0) = orr;
        }
    }
}

// ---------------- CSR build (no self loops; atomic segment bases) ----------------
__global__ void hist_kernel(const int* __restrict__ ei) {
    int t = blockIdx.x * blockDim.x + threadIdx.x;
    if (t >= E_EDGES) return;
    atomicAdd(&g_deg[ei[E_EDGES + t]], 1);
}

__global__ void base_kernel() {
    int idx = blockIdx.x * blockDim.x + threadIdx.x;
    if (idx < N_NODES) g_off[idx] = atomicAdd(&g_cnt, g_deg[idx]);
}

__global__ void scatter_kernel(const int* __restrict__ ei) {
    int t = blockIdx.x * blockDim.x + threadIdx.x;
    if (t >= E_EDGES) return;
    int dst = ei[E_EDGES + t];
    int pos = atomicAdd(&g_cur[dst], 1);
    int o = g_off[dst] + pos;
    g_srcl[o] = ei[t];
    g_eidl[o] = t;
}

// ---------------- conv weight transpose: wext[(t*128+cin)*128 + cout] ----------------
__global__ void prep_wext(const float* __restrict__ conv_w) {
    int idx = blockIdx.x * blockDim.x + threadIdx.x;
    if (idx >= 384 * 128) return;
    int kext = idx >> 7, cout = idx & 127;
    int t = kext >> 7, cin = kext & 127;
    g_wext[idx] = conv_w[cout * 384 + cin * 3 + t];
}

// ---------------- fused attention: warp/node, dual-stream online softmax + idx prefetch ----------------
__global__ __launch_bounds__(256) void attn_kernel(
    const float* __restrict__ x,
    const float* __restrict__ edge_attr, const float* __restrict__ W_e,
    const float* __restrict__ att, const float* __restrict__ bias_gat,
    const float* __restrict__ weight1)
{
    __shared__ __align__(16) float We_s[2048];
    __shared__ float att_s[128];
    __shared__ float bias_s[128];
    __shared__ float red_s[256];
    int tid = threadIdx.x;
    for (int idx = tid; idx < 2048; idx += 256) We_s[idx] = W_e[idx];
    if (tid < 128) { att_s[tid] = att[tid]; bias_s[tid] = bias_gat[tid]; }
    red_s[tid] = 0.f;
    __syncthreads();

    int i = blockIdx.x * 8 + (tid >> 5);   // grid = 6250 -> exactly 50000 nodes
    int lane = tid & 31;
    int c0 = lane * 4;
    int base = g_off[i];
    int deg = g_deg[i];

    const float4 xr4 = *(const float4*)(g_xr + (size_t)i * 128 + c0);
    const float4 xli = *(const float4*)(g_xl + (size_t)i * 128 + c0);
    float ax = att_s[c0], ay = att_s[c0 + 1], az = att_s[c0 + 2], aw = att_s[c0 + 3];

    // self loop -> stream A init: message = leaky(xl_i + xr_i), no edge term
    float sx = xli.x + xr4.x, sy = xli.y + xr4.y;
    float sz = xli.z + xr4.z, sw = xli.w + xr4.w;
    sx = (sx > 0.f) ? sx : 0.2f * sx; sy = (sy > 0.f) ? sy : 0.2f * sy;
    sz = (sz > 0.f) ? sz : 0.2f * sz; sw = (sw > 0.f) ? sw : 0.2f * sw;
    float part = sx * ax + sy * ay + sz * az + sw * aw;
#pragma unroll
    for (int o = 16; o; o >>= 1) part += __shfl_xor_sync(0xffffffffu, part, o);
    // stream A state (holds self loop)
    float mA = part, denA = 1.f;
    float4 accA = xli;
    // stream B state (empty)
    float mB = -3.0e38f, denB = 0.f;
    float4 accB = make_float4(0.f, 0.f, 0.f, 0.f);

    // index prefetch registers (one batch ahead)
    int s0n = 0, s1n = 0, e0n = 0, e1n = 0;
    if (deg >= 2) {
        s0n = g_srcl[base];     s1n = g_srcl[base + 1];
        e0n = g_eidl[base];     e1n = g_eidl[base + 1];
    }

    int jj = 0;
    // ---- 2-edge batched mainloop ----
    for (; jj + 2 <= deg; jj += 2) {
        int s0 = s0n, s1 = s1n, e0 = e0n, e1 = e1n;
        if (jj + 4 <= deg) {     // prefetch next batch's indices under this batch's compute
            s0n = g_srcl[base + jj + 2];  s1n = g_srcl[base + jj + 3];
            e0n = g_eidl[base + jj + 2];  e1n = g_eidl[base + jj + 3];
        }
        const float4 xlA = *(const float4*)(g_xl + (size_t)s0 * 128 + c0);
        const float4 xlB = *(const float4*)(g_xl + (size_t)s1 * 128 + c0);
        const float4* epA = (const float4*)(edge_attr + (size_t)e0 * EDIM);
        const float4* epB = (const float4*)(edge_attr + (size_t)e1 * EDIM);
        float4 aA = __ldg(epA), aB = __ldg(epA + 1), aC = __ldg(epA + 2), aD = __ldg(epA + 3);
        float4 bA = __ldg(epB), bB = __ldg(epB + 1), bC = __ldg(epB + 2), bD = __ldg(epB + 3);
        float evA[16] = {aA.x, aA.y, aA.z, aA.w, aB.x, aB.y, aB.z, aB.w,
                         aC.x, aC.y, aC.z, aC.w, aD.x, aD.y, aD.z, aD.w};
        float evB[16] = {bA.x, bA.y, bA.z, bA.w, bB.x, bB.y, bB.z, bB.w,
                         bC.x, bC.y, bC.z, bC.w, bD.x, bD.y, bD.z, bD.w};

        ull a01 = pack2(xlA.x + xr4.x, xlA.y + xr4.y);
        ull a23 = pack2(xlA.z + xr4.z, xlA.w + xr4.w);
        ull b01 = pack2(xlB.x + xr4.x, xlB.y + xr4.y);
        ull b23 = pack2(xlB.z + xr4.z, xlB.w + xr4.w);
#pragma unroll
        for (int k = 0; k < EDIM; k++) {
            ulonglong2 w = *(const ulonglong2*)&We_s[k * 128 + c0];
            ull dA = dup2(evA[k]);
            ull dB = dup2(evB[k]);
            fma2(a01, dA, w.x); fma2(a23, dA, w.y);
            fma2(b01, dB, w.x); fma2(b23, dB, w.y);
        }
        float2 pA01 = u2f(a01), pA23 = u2f(a23);
        float2 pB01 = u2f(b01), pB23 = u2f(b23);
        float mxA = pA01.x, myA = pA01.y, mzA = pA23.x, mwA = pA23.y;
        float mxB = pB01.x, myB = pB01.y, mzB = pB23.x, mwB = pB23.y;
        mxA = (mxA > 0.f) ? mxA : 0.2f * mxA;  myA = (myA > 0.f) ? myA : 0.2f * myA;
        mzA = (mzA > 0.f) ? mzA : 0.2f * mzA;  mwA = (mwA > 0.f) ? mwA : 0.2f * mwA;
        mxB = (mxB > 0.f) ? mxB : 0.2f * mxB;  myB = (myB > 0.f) ? myB : 0.2f * myB;
        mzB = (mzB > 0.f) ? mzB : 0.2f * mzB;  mwB = (mwB > 0.f) ? mwB : 0.2f * mwB;
        float pA = mxA * ax + myA * ay + mzA * az + mwA * aw;
        float pB = mxB * ax + myB * ay + mzB * az + mwB * aw;
#pragma unroll
        for (int o = 16; o; o >>= 1) {
            pA += __shfl_xor_sync(0xffffffffu, pA, o);
            pB += __shfl_xor_sync(0xffffffffu, pB, o);
        }
        // independent stream updates (warp-uniform branches)
        if (pA > mA) {
            float scl = __expf(mA - pA);
            denA *= scl;
            accA.x *= scl; accA.y *= scl; accA.z *= scl; accA.w *= scl;
            mA = pA;
        }
        if (pB > mB) {
            float scl = (denB == 0.f) ? 0.f : __expf(mB - pB);
            denB *= scl;
            accB.x *= scl; accB.y *= scl; accB.z *= scl; accB.w *= scl;
            mB = pB;
        }
        float prA = __expf(pA - mA);
        float prB = __expf(pB - mB);
        denA += prA;
        denB += prB;
        accA.x += prA * xlA.x; accA.y += prA * xlA.y;
        accA.z += prA * xlA.z; accA.w += prA * xlA.w;
        accB.x += prB * xlB.x; accB.y += prB * xlB.y;
        accB.z += prB * xlB.z; accB.w += prB * xlB.w;
    }
    // ---- tail (deg odd): single-edge body, stream A ----
    for (; jj < deg; ++jj) {
        int src = g_srcl[base + jj];
        int e   = g_eidl[base + jj];
        const float4 xl4 = *(const float4*)(g_xl + (size_t)src * 128 + c0);
        const float4* eap = (const float4*)(edge_attr + (size_t)e * EDIM);
        float4 eA = __ldg(eap), eB = __ldg(eap + 1), eC = __ldg(eap + 2), eD = __ldg(eap + 3);
        float ev[16] = {eA.x, eA.y, eA.z, eA.w, eB.x, eB.y, eB.z, eB.w,
                        eC.x, eC.y, eC.z, eC.w, eD.x, eD.y, eD.z, eD.w};
        float mx = xl4.x + xr4.x, my = xl4.y + xr4.y;
        float mz = xl4.z + xr4.z, mw = xl4.w + xr4.w;
#pragma unroll
        for (int k = 0; k < EDIM; k++) {
            const float4 w = *(const float4*)&We_s[k * 128 + c0];
            mx += ev[k] * w.x; my += ev[k] * w.y; mz += ev[k] * w.z; mw += ev[k] * w.w;
        }
        mx = (mx > 0.f) ? mx : 0.2f * mx;
        my = (my > 0.f) ? my : 0.2f * my;
        mz = (mz > 0.f) ? mz : 0.2f * mz;
        mw = (mw > 0.f) ? mw : 0.2f * mw;
        float p = mx * ax + my * ay + mz * az + mw * aw;
#pragma unroll
        for (int o = 16; o; o >>= 1) p += __shfl_xor_sync(0xffffffffu, p, o);
        if (p > mA) {
            float scl = __expf(mA - p);
            denA *= scl;
            accA.x *= scl; accA.y *= scl; accA.z *= scl; accA.w *= scl;
            mA = p;
        }
        float pr = __expf(p - mA);
        denA += pr;
        accA.x += pr * xl4.x; accA.y += pr * xl4.y;
        accA.z += pr * xl4.z; accA.w += pr * xl4.w;
    }

    // ---- merge streams: m = max(mA, mB) ----
    float m = fmaxf(mA, mB);
    float sA = __expf(mA - m);
    float sB = (denB == 0.f) ? 0.f : __expf(mB - m);
    float den = denA * sA + denB * sB;
    float4 acc;
    acc.x = accA.x * sA + accB.x * sB;
    acc.y = accA.y * sA + accB.y * sB;
    acc.z = accA.z * sA + accB.z * sB;
    acc.w = accA.w * sA + accB.w * sB;

    float inv = 1.f / den;
    // softmax(weight1)
    float a0 = weight1[0], a1 = weight1[1];
    float wm = fmaxf(a0, a1);
    float e0 = __expf(a0 - wm), e1 = __expf(a1 - wm);
    float is = 1.f / (e0 + e1);
    float w10 = e0 * is, w11 = e1 * is;

    const float4 xv = *(const float4*)(x + (size_t)i * 128 + c0);
    float4 o;
    o.x = w10 * xv.x + w11 * (acc.x * inv + bias_s[c0]);
    o.y = w10 * xv.y + w11 * (acc.y * inv + bias_s[c0 + 1]);
    o.z = w10 * xv.z + w11 * (acc.z * inv + bias_s[c0 + 2]);
    o.w = w10 * xv.w + w11 * (acc.w * inv + bias_s[c0 + 3]);
    *(float4*)(g_zpre + (size_t)i * 128 + c0) = o;

    // fused BN1 stats: block-level partials then one global flush
    atomicAdd(&red_s[c0 + 0], o.x); atomicAdd(&red_s[128 + c0 + 0], o.x * o.x);
    atomicAdd(&red_s[c0 + 1], o.y); atomicAdd(&red_s[128 + c0 + 1], o.y * o.y);
    atomicAdd(&red_s[c0 + 2], o.z); atomicAdd(&red_s[128 + c0 + 2], o.z * o.z);
    atomicAdd(&red_s[c0 + 3], o.w); atomicAdd(&red_s[128 + c0 + 3], o.w * o.w);
    __syncthreads();
    atomicAdd(&g_stats[tid], red_s[tid]);
}

__global__ void bn_finalize(const float* __restrict__ stats,
                            const float* __restrict__ gamma, const float* __restrict__ beta,
                            float* __restrict__ scale, float* __restrict__ shift)
{
    int c = threadIdx.x;
    float mu = stats[c] * (1.f / N_NODES);
    float var = stats[128 + c] * (1.f / N_NODES) - mu * mu;
    float rstd = rsqrtf(var + 1e-5f);
    float s = rstd * gamma[c];
    scale[c] = s;
    shift[c] = beta[c] - mu * s;
}

// ---------------- conv1d(k=3) as K=384 GEMM (FFMA2) + mix + fused BN2 stats (R10 proven) ----------------
__global__ __launch_bounds__(256) void conv_kernel(const float* __restrict__ conv_b,
                                                   const float* __restrict__ weight2)
{
    __shared__ __align__(16) float zs[66][128];
    __shared__ __align__(16) float wt[16][128];
    __shared__ float sc_s[128], sh_s[128];
    __shared__ float red2[256];
    int tid = threadIdx.x;
    int row0 = blockIdx.x * 64;
    if (tid < 128) { sc_s[tid] = g_scale1[tid]; sh_s[tid] = g_shift1[tid]; }
    red2[tid] = 0.f;
    __syncthreads();

    // load + normalize input tile rows [row0-1, row0+64]; zero pad outside [0,N)
    for (int idx = tid; idx < 66 * 32; idx += 256) {
        int rr = idx >> 5, cg = idx & 31;
        int grow = row0 - 1 + rr;
        float4 v = make_float4(0.f, 0.f, 0.f, 0.f);
        if (grow >= 0 && grow < N_NODES) {
            float4 z = *(const float4*)(g_zpre + (size_t)grow * 128 + cg * 4);
            int c = cg * 4;
            v.x = z.x * sc_s[c] + sh_s[c];
            v.y = z.y * sc_s[c + 1] + sh_s[c + 1];
            v.z = z.z * sc_s[c + 2] + sh_s[c + 2];
            v.w = z.w * sc_s[c + 3] + sh_s[c + 3];
        }
        *(float4*)&zs[rr][cg * 4] = v;
    }

    int tcol = tid & 31, trow = tid >> 5;
    int c0 = tcol * 4, r0 = trow * 8;
    ull acc2[8][2];
#pragma unroll
    for (int r = 0; r < 8; r++) { acc2[r][0] = 0ull; acc2[r][1] = 0ull; }

    for (int t = 0; t < 3; t++) {
        for (int kc = 0; kc < 8; kc++) {
            __syncthreads();
#pragma unroll
            for (int it = 0; it < 2; it++) {
                int idx = tid + it * 256;
                int k = idx >> 5, cg = idx & 31;
                *(float4*)&wt[k][cg * 4] =
                    *(const float4*)(g_wext + (size_t)(t * 128 + kc * 16 + k) * 128 + cg * 4);
            }
            __syncthreads();
#pragma unroll
            for (int kk = 0; kk < 16; kk += 4) {
                float4 a4[8];
#pragma unroll
                for (int r = 0; r < 8; r++)
                    a4[r] = *(float4*)&zs[r0 + r + t][kc * 16 + kk];
#pragma unroll
                for (int q = 0; q < 4; q++) {
                    ulonglong2 w2 = *(const ulonglong2*)&wt[kk + q][c0];
#pragma unroll
                    for (int r = 0; r < 8; r++) {
                        float av = (q == 0) ? a4[r].x : (q == 1) ? a4[r].y
                                 : (q == 2) ? a4[r].z : a4[r].w;
                        ull ad = dup2(av);
                        fma2(acc2[r][0], ad, w2.x);
                        fma2(acc2[r][1], ad, w2.y);
                    }
                }
            }
        }
    }

    // softmax(weight2)
    float a0 = weight2[0], a1 = weight2[1];
    float wm = fmaxf(a0, a1);
    float e0 = __expf(a0 - wm), e1 = __expf(a1 - wm);
    float is = 1.f / (e0 + e1);
    float w20 = e0 * is, w21 = e1 * is;

    float4 b4 = *(const float4*)(conv_b + c0);
    float sst[4] = {0.f, 0.f, 0.f, 0.f};
    float qst[4] = {0.f, 0.f, 0.f, 0.f};
#pragma unroll
    for (int r = 0; r < 8; r++) {
        int grow = row0 + r0 + r;
        if (grow < N_NODES) {
            float2 u0 = u2f(acc2[r][0]), u1 = u2f(acc2[r][1]);
            float4 z1;
            z1.x = u0.x + b4.x; z1.y = u0.y + b4.y;
            z1.z = u1.x + b4.z; z1.w = u1.y + b4.w;
            z1.x = (z1.x > 0.f) ? z1.x : 0.01f * z1.x;
            z1.y = (z1.y > 0.f) ? z1.y : 0.01f * z1.y;
            z1.z = (z1.z > 0.f) ? z1.z : 0.01f * z1.z;
            z1.w = (z1.w > 0.f) ? z1.w : 0.01f * z1.w;
            float4 zn = *(float4*)&zs[r0 + r + 1][c0];
            float4 o;
            o.x = w20 * zn.x + w21 * z1.x;
            o.y = w20 * zn.y + w21 * z1.y;
            o.z = w20 * zn.z + w21 * z1.z;
            o.w = w20 * zn.w + w21 * z1.w;
            *(float4*)(g_z2 + (size_t)grow * 128 + c0) = o;
            sst[0] += o.x; qst[0] += o.x * o.x;
            sst[1] += o.y; qst[1] += o.y * o.y;
            sst[2] += o.z; qst[2] += o.z * o.z;
            sst[3] += o.w; qst[3] += o.w * o.w;
        }
    }
#pragma unroll
    for (int j = 0; j < 4; j++) {
        atomicAdd(&red2[c0 + j], sst[j]);
        atomicAdd(&red2[128 + c0 + j], qst[j]);
    }
    __syncthreads();
    atomicAdd(&g_stats[256 + tid], red2[tid]);
}

// ---------------- final BN2 apply ----------------
__global__ void final_apply(float* __restrict__ out) {
    int idx = blockIdx.x * blockDim.x + threadIdx.x;   // over N*32 float4 groups
    if (idx >= N_NODES * 32) return;
    int cg = idx & 31;
    int c = cg * 4;
    float4 z = *(const float4*)(g_z2 + (size_t)idx * 4);
    float4 o;
    o.x = z.x * g_scale2[c]     + g_shift2[c];
    o.y = z.y * g_scale2[c + 1] + g_shift2[c + 1];
    o.z = z.z * g_scale2[c + 2] + g_shift2[c + 2];
    o.w = z.w * g_scale2[c + 3] + g_shift2[c + 3];
    *(float4*)(out + (size_t)idx * 4) = o;
}

// ---------------- launch ----------------
extern "C" void kernel_launch(void* const* d_in, const int* in_sizes, int n_in,
                              void* d_out, int out_size)
{
    const float* x         = (const float*)d_in[0];
    const int*   ei        = (const int*)d_in[1];
    const float* edge_attr = (const float*)d_in[2];
    const float* W_l       = (const float*)d_in[3];
    const float* b_l       = (const float*)d_in[4];
    const float* W_r       = (const float*)d_in[5];
    const float* b_r       = (const float*)d_in[6];
    const float* W_e       = (const float*)d_in[7];
    const float* att       = (const float*)d_in[8];
    const float* bias_gat  = (const float*)d_in[9];
    const float* weight1   = (const float*)d_in[10];
    const float* bn1_gamma = (const float*)d_in[11];
    const float* bn1_beta  = (const float*)d_in[12];
    const float* conv_w    = (const float*)d_in[13];
    const float* conv_b    = (const float*)d_in[14];
    const float* weight2   = (const float*)d_in[15];
    const float* bn2_gamma = (const float*)d_in[16];
    const float* bn2_beta  = (const float*)d_in[17];
    float* out = (float*)d_out;

    float *p_xl, *p_xr, *p_stats, *p_sc1, *p_sh1, *p_sc2, *p_sh2;
    cudaGetSymbolAddress((void**)&p_xl, g_xl);
    cudaGetSymbolAddress((void**)&p_xr, g_xr);
    cudaGetSymbolAddress((void**)&p_stats, g_stats);
    cudaGetSymbolAddress((void**)&p_sc1, g_scale1);
    cudaGetSymbolAddress((void**)&p_sh1, g_shift1);
    cudaGetSymbolAddress((void**)&p_sc2, g_scale2);
    cudaGetSymbolAddress((void**)&p_sh2, g_shift2);

    // order chosen so the ncu-profiled 4th launch is gemm_dual (the hot GEMM)
    zero_kernel<<<(N_NODES + 255) / 256, 256>>>();
    hist_kernel<<<(E_EDGES + 255) / 256, 256>>>(ei);
    base_kernel<<<(N_NODES + 255) / 256, 256>>>();
    gemm_dual<<<(N_NODES + 63) / 64, 256>>>(x, W_l, b_l, W_r, b_r, p_xl, p_xr, N_NODES);
    scatter_kernel<<<(E_EDGES + 255) / 256, 256>>>(ei);
    prep_wext<<<(384 * 128 + 255) / 256, 256>>>(conv_w);
    attn_kernel<<<N_NODES / 8, 256>>>(x, edge_attr, W_e, att, bias_gat, weight1);
    bn_finalize<<<1, 128>>>(p_stats, bn1_gamma, bn1_beta, p_sc1, p_sh1);
    conv_kernel<<<(N_NODES + 63) / 64, 256>>>(conv_b, weight2);
    bn_finalize<<<1, 128>>>(p_stats + 256, bn2_gamma, bn2_beta, p_sc2, p_sh2);
    final_apply<<<(N_NODES * 32 + 255) / 256, 256>>>(out);
}